// round 1
// baseline (speedup 1.0000x reference)
#include <cuda_runtime.h>
#include <math.h>

#define B_ 32
#define J_ 1024
#define D_ 192
#define E_ 384
#define N_ 16
#define BJ_ (B_*J_)

// ---------------- device scratch (no allocs allowed) ----------------
__device__ float g_t[BJ_*D_];          // LayerNorm output
__device__ float g_x[BJ_*E_];          // x = t@Wx + bx
__device__ float g_gate[BJ_*E_];       // sigmoid(silu(z))
__device__ float g_Abar[2][B_*N_*J_];  // [dir][b][n][s]
__device__ float g_Bu  [2][B_*N_*J_];
__device__ float g_Ct  [2][B_*N_*J_];
__device__ float g_g   [2][BJ_*N_];    // hs*Ct at ORIGINAL j, [dir][row][n]

// ---------------- K0: LayerNorm ----------------
__global__ void ln_kernel(const float* __restrict__ tok,
                          const float* __restrict__ gamma,
                          const float* __restrict__ beta) {
    int row  = blockIdx.x * 8 + (threadIdx.x >> 5);
    int lane = threadIdx.x & 31;
    const float* tr = tok + (size_t)row * D_;
    float v[6];
    float s = 0.f;
    #pragma unroll
    for (int i = 0; i < 6; i++) { v[i] = tr[lane + 32*i]; s += v[i]; }
    #pragma unroll
    for (int o = 16; o > 0; o >>= 1) s += __shfl_xor_sync(0xffffffffu, s, o);
    float mu = s * (1.f / D_);
    float vs = 0.f;
    #pragma unroll
    for (int i = 0; i < 6; i++) { float d = v[i] - mu; vs += d * d; }
    #pragma unroll
    for (int o = 16; o > 0; o >>= 1) vs += __shfl_xor_sync(0xffffffffu, vs, o);
    float inv = rsqrtf(vs * (1.f / D_) + 1e-5f);
    #pragma unroll
    for (int i = 0; i < 6; i++) {
        int c = lane + 32*i;
        g_t[(size_t)row * D_ + c] = (v[i] - mu) * inv * gamma[c] + beta[c];
    }
}

// ---------------- K1: dual GEMM  x = t@Wx+bx ; gate = sigmoid(silu(t@Wz+bz)) ----------------
// tile 64 rows x 64 cols (per matrix), BK=32, 256 threads, 4x(4-vec) micro-tile
__global__ __launch_bounds__(256) void gemm1_kernel(
        const float* __restrict__ Wx, const float* __restrict__ bx,
        const float* __restrict__ Wz, const float* __restrict__ bz) {
    __shared__ float sA[64*32];
    __shared__ float sBx[32*64];
    __shared__ float sBz[32*64];
    int tid = threadIdx.x;
    int tx = tid & 15, ty = tid >> 4;     // ty 0..15
    int row0 = blockIdx.x * 64;
    int c0   = blockIdx.y * 64;

    float4 accX[4], accZ[4];
    #pragma unroll
    for (int i = 0; i < 4; i++) { accX[i] = make_float4(0,0,0,0); accZ[i] = make_float4(0,0,0,0); }

    for (int kt = 0; kt < D_; kt += 32) {
        #pragma unroll
        for (int i = 0; i < 8; i++) {
            int q = tid + i*256;
            int r = q >> 5, kk = q & 31;
            sA[q] = g_t[(size_t)(row0 + r) * D_ + kt + kk];
        }
        #pragma unroll
        for (int i = 0; i < 8; i++) {
            int q = tid + i*256;
            int kk = q >> 6, c = q & 63;
            sBx[q] = Wx[(size_t)(kt + kk) * E_ + c0 + c];
            sBz[q] = Wz[(size_t)(kt + kk) * E_ + c0 + c];
        }
        __syncthreads();
        #pragma unroll
        for (int kk = 0; kk < 32; kk++) {
            float a0 = sA[(ty     )*32 + kk];
            float a1 = sA[(ty + 16)*32 + kk];
            float a2 = sA[(ty + 32)*32 + kk];
            float a3 = sA[(ty + 48)*32 + kk];
            float4 bxv = *(const float4*)&sBx[kk*64 + tx*4];
            float4 bzv = *(const float4*)&sBz[kk*64 + tx*4];
            accX[0].x += a0*bxv.x; accX[0].y += a0*bxv.y; accX[0].z += a0*bxv.z; accX[0].w += a0*bxv.w;
            accX[1].x += a1*bxv.x; accX[1].y += a1*bxv.y; accX[1].z += a1*bxv.z; accX[1].w += a1*bxv.w;
            accX[2].x += a2*bxv.x; accX[2].y += a2*bxv.y; accX[2].z += a2*bxv.z; accX[2].w += a2*bxv.w;
            accX[3].x += a3*bxv.x; accX[3].y += a3*bxv.y; accX[3].z += a3*bxv.z; accX[3].w += a3*bxv.w;
            accZ[0].x += a0*bzv.x; accZ[0].y += a0*bzv.y; accZ[0].z += a0*bzv.z; accZ[0].w += a0*bzv.w;
            accZ[1].x += a1*bzv.x; accZ[1].y += a1*bzv.y; accZ[1].z += a1*bzv.z; accZ[1].w += a1*bzv.w;
            accZ[2].x += a2*bzv.x; accZ[2].y += a2*bzv.y; accZ[2].z += a2*bzv.z; accZ[2].w += a2*bzv.w;
            accZ[3].x += a3*bzv.x; accZ[3].y += a3*bzv.y; accZ[3].z += a3*bzv.z; accZ[3].w += a3*bzv.w;
        }
        __syncthreads();
    }
    float4 bxb = *(const float4*)&bx[c0 + tx*4];
    float4 bzb = *(const float4*)&bz[c0 + tx*4];
    #pragma unroll
    for (int i = 0; i < 4; i++) {
        int row = row0 + ty + 16*i;
        float4 vx = accX[i];
        vx.x += bxb.x; vx.y += bxb.y; vx.z += bxb.z; vx.w += bxb.w;
        *(float4*)&g_x[(size_t)row * E_ + c0 + tx*4] = vx;
        float4 vz = accZ[i];
        float zc, sl;
        float4 gt;
        zc = vz.x + bzb.x; sl = zc / (1.f + __expf(-zc)); gt.x = 1.f / (1.f + __expf(-sl));
        zc = vz.y + bzb.y; sl = zc / (1.f + __expf(-zc)); gt.y = 1.f / (1.f + __expf(-sl));
        zc = vz.z + bzb.z; sl = zc / (1.f + __expf(-zc)); gt.z = 1.f / (1.f + __expf(-sl));
        zc = vz.w + bzb.w; sl = zc / (1.f + __expf(-zc)); gt.w = 1.f / (1.f + __expf(-sl));
        *(float4*)&g_gate[(size_t)row * E_ + c0 + tx*4] = gt;
    }
}

// ---------------- K2: depthwise conv + 4 projections + ZOH discretization ----------------
// one block: 64 sequence positions of one (b, dir), all 64 outputs (Bt|Ct|Dt|u)
__global__ __launch_bounds__(256) void proj_kernel(
        const float* __restrict__ cwf, const float* __restrict__ cbf,
        const float* __restrict__ cwb, const float* __restrict__ cbb,
        const float* __restrict__ WBf, const float* __restrict__ bBf,
        const float* __restrict__ WCf, const float* __restrict__ bCf,
        const float* __restrict__ WDf, const float* __restrict__ bDf,
        const float* __restrict__ WBb, const float* __restrict__ bBb,
        const float* __restrict__ WCb, const float* __restrict__ bCb,
        const float* __restrict__ WDb, const float* __restrict__ bDb,
        const float* __restrict__ A_log,
        const float* __restrict__ Wi,  const float* __restrict__ bi) {
    __shared__ float sA[64*32];
    __shared__ float sB[32*64];
    int tid = threadIdx.x;
    int tx = tid & 15, ty = tid >> 4;
    int s0 = blockIdx.x * 64;
    int b  = blockIdx.y;
    int dir = blockIdx.z;

    const float* cw = dir ? cwb : cwf;
    const float* cb = dir ? cbb : cbf;
    const float* WB = dir ? WBb : WBf;
    const float* WC = dir ? WCb : WCf;
    const float* WD = dir ? WDb : WDf;
    const float* bB = dir ? bBb : bBf;
    const float* bC = dir ? bCb : bCf;
    const float* bD = dir ? bDb : bDf;

    float acc[4][4];
    #pragma unroll
    for (int i = 0; i < 4; i++)
        #pragma unroll
        for (int m = 0; m < 4; m++) acc[i][m] = 0.f;

    for (int kt = 0; kt < E_; kt += 32) {
        // xc tile via conv (on flipped sequence when dir==1)
        #pragma unroll
        for (int i = 0; i < 8; i++) {
            int q = tid + i*256;
            int r = q >> 5, kk = q & 31;
            int e = kt + kk;
            int s = s0 + r;
            int j0 = dir ? (J_ - 1 - s) : s;
            float x1 = g_x[(size_t)(b*J_ + j0) * E_ + e];
            float x0 = 0.f, x2 = 0.f;
            if (s > 0)      { int jm = dir ? j0 + 1 : j0 - 1; x0 = g_x[(size_t)(b*J_ + jm) * E_ + e]; }
            if (s < J_ - 1) { int jp = dir ? j0 - 1 : j0 + 1; x2 = g_x[(size_t)(b*J_ + jp) * E_ + e]; }
            sA[q] = cw[e*3]*x0 + cw[e*3+1]*x1 + cw[e*3+2]*x2 + cb[e];
        }
        #pragma unroll
        for (int i = 0; i < 8; i++) {
            int q = tid + i*256;
            int kk = q >> 6, c = q & 63;
            int m = c >> 4, n = c & 15;
            const float* W = (m == 0) ? WB : (m == 1) ? WC : (m == 2) ? WD : Wi;
            sB[q] = W[(size_t)(kt + kk) * N_ + n];
        }
        __syncthreads();
        #pragma unroll
        for (int kk = 0; kk < 32; kk++) {
            float b0 = sB[kk*64 + tx];
            float b1 = sB[kk*64 + tx + 16];
            float b2 = sB[kk*64 + tx + 32];
            float b3 = sB[kk*64 + tx + 48];
            #pragma unroll
            for (int i = 0; i < 4; i++) {
                float a = sA[(ty + 16*i)*32 + kk];
                acc[i][0] += a*b0; acc[i][1] += a*b1; acc[i][2] += a*b2; acc[i][3] += a*b3;
            }
        }
        __syncthreads();
    }

    int n = tx;
    float al = A_log[n];
    float A_n = -log1pf(expf(al));               // -softplus
    float invA = 1.f / (A_n + 1e-6f);
    float bBv = bB[n], bCv = bC[n], bDv = bD[n], biv = bi[n];
    #pragma unroll
    for (int i = 0; i < 4; i++) {
        int s = s0 + ty + 16*i;
        float bt  = acc[i][0] + bBv;
        float ct  = acc[i][1] + bCv;
        float dtr = acc[i][2] + bDv;
        float u   = acc[i][3] + biv;
        float dt  = (dtr > 20.f) ? dtr : log1pf(__expf(dtr));   // softplus
        float abar = __expf(dt * A_n);
        float bu = (abar - 1.f) * invA * bt * u;
        size_t base = (size_t)(b*N_ + n) * J_ + s;
        g_Abar[dir][base] = abar;
        g_Bu[dir][base]   = bu;
        g_Ct[dir][base]   = ct;
    }
}

// ---------------- K3: segmented warp scan, h = a*h + bu ----------------
__global__ __launch_bounds__(512) void scan_kernel() {
    int b   = blockIdx.x;
    int dir = blockIdx.y;
    int w    = threadIdx.x >> 5;   // state n
    int lane = threadIdx.x & 31;
    size_t base = (size_t)(b*N_ + w) * J_;
    const float* Aa = g_Abar[dir] + base;
    const float* Bu = g_Bu[dir]   + base;
    const float* Ct = g_Ct[dir]   + base;
    float carry = 0.f;
    for (int seg = 0; seg < J_/32; seg++) {
        int s = seg*32 + lane;
        float a  = Aa[s];
        float bu = Bu[s];
        #pragma unroll
        for (int off = 1; off < 32; off <<= 1) {
            float ap = __shfl_up_sync(0xffffffffu, a,  off);
            float bp = __shfl_up_sync(0xffffffffu, bu, off);
            if (lane >= off) { bu = fmaf(a, bp, bu); a *= ap; }
        }
        float h = fmaf(a, carry, bu);
        carry = __shfl_sync(0xffffffffu, h, 31);
        float g = h * Ct[s];
        int jorig = dir ? (J_ - 1 - s) : s;
        g_g[dir][(size_t)(b*J_ + jorig) * N_ + w] = g;
    }
}

// ---------------- K4: y=((gf+gb)@Wr+2br)*gate ; out = tokens + y@Wo + bo ----------------
// 16 rows per block
__global__ __launch_bounds__(256) void out_kernel(
        const float* __restrict__ tokens,
        const float* __restrict__ Wr, const float* __restrict__ br,
        const float* __restrict__ Wo, const float* __restrict__ bo,
        float* __restrict__ out) {
    __shared__ float gsm[16*16];     // summed g
    __shared__ float ysm[16*384];
    __shared__ float wbuf[16*192];   // Wo tile / output staging
    int tid = threadIdx.x;
    int j0 = blockIdx.x * 16;
    int b  = blockIdx.y;

    // load gsum
    if (tid < 256) {
        int r = tid >> 4, n = tid & 15;
        size_t row = (size_t)(b*J_ + j0 + r);
        gsm[tid] = g_g[0][row*N_ + n] + g_g[1][row*N_ + n];
    }
    __syncthreads();

    // phase A: y rows into ysm
    for (int q = tid; q < 16*E_; q += 256) {
        int r = q / E_, e = q - r*E_;
        float acc = 2.f * br[e];
        #pragma unroll
        for (int nn = 0; nn < 16; nn++) acc += gsm[r*16 + nn] * Wr[(size_t)nn*E_ + e];
        size_t row = (size_t)(b*J_ + j0 + r);
        ysm[q] = acc * g_gate[row*E_ + e];
    }
    __syncthreads();

    // phase B: y @ Wo with smem-tiled Wo, 16-row x 192-col output
    int cg = tid & 15;        // col group (12 d each)
    int r  = tid >> 4;        // row 0..15
    float acc[12];
    #pragma unroll
    for (int jj = 0; jj < 12; jj++) acc[jj] = 0.f;

    for (int et = 0; et < E_/16; et++) {
        for (int q = tid; q < 16*192; q += 256) {
            int kk = q / 192, d = q - kk*192;
            wbuf[q] = Wo[(size_t)(et*16 + kk) * D_ + d];
        }
        __syncthreads();
        #pragma unroll
        for (int el = 0; el < 16; el++) {
            float ys = ysm[r*E_ + et*16 + el];
            const float* wrow = &wbuf[el*192 + cg*12];
            #pragma unroll
            for (int jj = 0; jj < 12; jj++) acc[jj] += ys * wrow[jj];
        }
        __syncthreads();
    }

    // stage through smem for coalesced final write
    #pragma unroll
    for (int jj = 0; jj < 12; jj++) wbuf[r*192 + cg*12 + jj] = acc[jj];
    __syncthreads();
    for (int q = tid; q < 16*192; q += 256) {
        int rr = q / 192, dd = q - rr*192;
        size_t row = (size_t)(b*J_ + j0 + rr);
        out[row*D_ + dd] = tokens[row*D_ + dd] + wbuf[q] + bo[dd];
    }
}

// ---------------- launch ----------------
extern "C" void kernel_launch(void* const* d_in, const int* in_sizes, int n_in,
                              void* d_out, int out_size) {
    const float* tokens = (const float*)d_in[0];
    const float* norm_g = (const float*)d_in[1];
    const float* norm_b = (const float*)d_in[2];
    const float* Wx  = (const float*)d_in[3];
    const float* bx  = (const float*)d_in[4];
    const float* Wz  = (const float*)d_in[5];
    const float* bz  = (const float*)d_in[6];
    const float* cwf = (const float*)d_in[7];
    const float* cbf = (const float*)d_in[8];
    const float* cwb = (const float*)d_in[9];
    const float* cbb = (const float*)d_in[10];
    const float* WBf = (const float*)d_in[11];
    const float* bBf = (const float*)d_in[12];
    const float* WCf = (const float*)d_in[13];
    const float* bCf = (const float*)d_in[14];
    const float* WDf = (const float*)d_in[15];
    const float* bDf = (const float*)d_in[16];
    const float* WBb = (const float*)d_in[17];
    const float* bBb = (const float*)d_in[18];
    const float* WCb = (const float*)d_in[19];
    const float* bCb = (const float*)d_in[20];
    const float* WDb = (const float*)d_in[21];
    const float* bDb = (const float*)d_in[22];
    const float* A_log = (const float*)d_in[23];
    const float* Wi  = (const float*)d_in[24];
    const float* bi  = (const float*)d_in[25];
    const float* Wr  = (const float*)d_in[26];
    const float* br  = (const float*)d_in[27];
    const float* Wo  = (const float*)d_in[28];
    const float* bo  = (const float*)d_in[29];
    float* out = (float*)d_out;

    ln_kernel<<<BJ_/8, 256>>>(tokens, norm_g, norm_b);
    gemm1_kernel<<<dim3(BJ_/64, E_/64), 256>>>(Wx, bx, Wz, bz);
    proj_kernel<<<dim3(J_/64, B_, 2), 256>>>(cwf, cbf, cwb, cbb,
                                             WBf, bBf, WCf, bCf, WDf, bDf,
                                             WBb, bBb, WCb, bCb, WDb, bDb,
                                             A_log, Wi, bi);
    scan_kernel<<<dim3(B_, 2), 512>>>();
    out_kernel<<<dim3(J_/16, B_), 256>>>(tokens, Wr, br, Wo, bo, out);
}

// round 3
// speedup vs baseline: 1.1032x; 1.1032x over previous
#include <cuda_runtime.h>
#include <cuda_bf16.h>
#include <math.h>
#include <stdint.h>

#define B_ 32
#define J_ 1024
#define D_ 192
#define E_ 384
#define N_ 16
#define BJ_ (B_*J_)

// ---------------- device scratch (no allocs allowed) ----------------
__device__ __nv_bfloat16 g_th[BJ_*D_];     // LN output hi (bf16)
__device__ __nv_bfloat16 g_tl[BJ_*D_];     // LN output lo (bf16)
__device__ __nv_bfloat16 g_wht[768*D_];    // [Wx|Wz] transposed hi: [col][k]
__device__ __nv_bfloat16 g_wlt[768*D_];    // [Wx|Wz] transposed lo
__device__ float g_x[BJ_*E_];              // x = t@Wx + bx
__device__ float g_gate[BJ_*E_];           // sigmoid(silu(z))
__device__ float g_Abar[2][B_*N_*J_];      // [dir][b][n][s]
__device__ float g_Bu  [2][B_*N_*J_];
__device__ float g_Ct  [2][B_*N_*J_];
__device__ float g_g   [2][BJ_*N_];        // hs*Ct at ORIGINAL j

// ---------------- K0: LayerNorm -> bf16 hi/lo ----------------
__global__ void ln_kernel(const float* __restrict__ tok,
                          const float* __restrict__ gamma,
                          const float* __restrict__ beta) {
    int row  = blockIdx.x * 8 + (threadIdx.x >> 5);
    int lane = threadIdx.x & 31;
    const float* tr = tok + (size_t)row * D_;
    float v[6];
    float s = 0.f;
    #pragma unroll
    for (int i = 0; i < 6; i++) { v[i] = tr[lane + 32*i]; s += v[i]; }
    #pragma unroll
    for (int o = 16; o > 0; o >>= 1) s += __shfl_xor_sync(0xffffffffu, s, o);
    float mu = s * (1.f / D_);
    float vs = 0.f;
    #pragma unroll
    for (int i = 0; i < 6; i++) { float d = v[i] - mu; vs += d * d; }
    #pragma unroll
    for (int o = 16; o > 0; o >>= 1) vs += __shfl_xor_sync(0xffffffffu, vs, o);
    float inv = rsqrtf(vs * (1.f / D_) + 1e-5f);
    #pragma unroll
    for (int i = 0; i < 6; i++) {
        int c = lane + 32*i;
        float t = (v[i] - mu) * inv * gamma[c] + beta[c];
        __nv_bfloat16 h = __float2bfloat16(t);
        g_th[(size_t)row * D_ + c] = h;
        g_tl[(size_t)row * D_ + c] = __float2bfloat16(t - __bfloat162float(h));
    }
}

// ---------------- K0b: W prep (transpose + hi/lo split) ----------------
__global__ void wprep_kernel(const float* __restrict__ Wx, const float* __restrict__ Wz) {
    int i = blockIdx.x * 256 + threadIdx.x;
    if (i >= 768 * D_) return;
    int c = i / D_, k = i - c * D_;
    float w = (c < E_) ? Wx[(size_t)k * E_ + c] : Wz[(size_t)k * E_ + (c - E_)];
    __nv_bfloat16 h = __float2bfloat16(w);
    g_wht[i] = h;
    g_wlt[i] = __float2bfloat16(w - __bfloat162float(h));
}

// ---------------- K1: HMMA dual GEMM (bf16 hi/lo split) ----------------
// block: 128 rows x 64 cols, 8 warps in 4x2, warp tile 32x32
#define SW 40   // smem row stride in bf16 (conflict-free for quad pattern)

__device__ __forceinline__ void mma16816(float* c, const uint32_t* a, const uint32_t* b) {
    asm volatile(
        "mma.sync.aligned.m16n8k16.row.col.f32.bf16.bf16.f32 "
        "{%0,%1,%2,%3}, {%4,%5,%6,%7}, {%8,%9}, {%0,%1,%2,%3};"
        : "+f"(c[0]), "+f"(c[1]), "+f"(c[2]), "+f"(c[3])
        : "r"(a[0]), "r"(a[1]), "r"(a[2]), "r"(a[3]), "r"(b[0]), "r"(b[1]));
}

__global__ __launch_bounds__(256) void gemm1_mma(const float* __restrict__ bxv,
                                                 const float* __restrict__ bzv) {
    __shared__ __nv_bfloat16 sAh[128*SW];
    __shared__ __nv_bfloat16 sAl[128*SW];
    __shared__ __nv_bfloat16 sBh[64*SW];
    __shared__ __nv_bfloat16 sBl[64*SW];

    int tid  = threadIdx.x;
    int wid  = tid >> 5;
    int lane = tid & 31;
    int grp  = lane >> 2;   // 0..7
    int qd   = lane & 3;    // 0..3
    int row0 = blockIdx.x * 128;
    int yb   = blockIdx.y;
    int isZ  = (yb >= 6);
    int cb   = (isZ ? yb - 6 : yb) * 64;
    int csrc = cb + (isZ ? E_ : 0);
    int wm = (wid & 3) * 32;     // warp row base in tile
    int wn = (wid >> 2) * 32;    // warp col base in tile

    float acc[2][4][4];
    #pragma unroll
    for (int mi = 0; mi < 2; mi++)
        #pragma unroll
        for (int ni = 0; ni < 4; ni++)
            #pragma unroll
            for (int q = 0; q < 4; q++) acc[mi][ni][q] = 0.f;

    for (int kt = 0; kt < D_; kt += 32) {
        // stage A tile (128 x 32, hi+lo): 512 uint4 per buffer
        #pragma unroll
        for (int i = 0; i < 2; i++) {
            int q = tid + i * 256;
            int r = q >> 2, kc = (q & 3) * 8;
            const size_t go = (size_t)(row0 + r) * D_ + kt + kc;
            *(uint4*)&sAh[r*SW + kc] = *(const uint4*)(g_th + go);
            *(uint4*)&sAl[r*SW + kc] = *(const uint4*)(g_tl + go);
        }
        // stage B tile (64 x 32, hi+lo): 256 uint4 per buffer
        {
            int r = tid >> 2, kc = (tid & 3) * 8;
            const size_t go = (size_t)(csrc + r) * D_ + kt + kc;
            *(uint4*)&sBh[r*SW + kc] = *(const uint4*)(g_wht + go);
            *(uint4*)&sBl[r*SW + kc] = *(const uint4*)(g_wlt + go);
        }
        __syncthreads();

        #pragma unroll
        for (int ks = 0; ks < 2; ks++) {
            int k0 = ks * 16;
            uint32_t ah[2][4], al[2][4], bh[4][2], bl[4][2];
            #pragma unroll
            for (int mi = 0; mi < 2; mi++) {
                int rb = wm + mi * 16 + grp;
                int kk = k0 + qd * 2;
                ah[mi][0] = *(const uint32_t*)&sAh[(rb    )*SW + kk    ];
                ah[mi][1] = *(const uint32_t*)&sAh[(rb + 8)*SW + kk    ];
                ah[mi][2] = *(const uint32_t*)&sAh[(rb    )*SW + kk + 8];
                ah[mi][3] = *(const uint32_t*)&sAh[(rb + 8)*SW + kk + 8];
                al[mi][0] = *(const uint32_t*)&sAl[(rb    )*SW + kk    ];
                al[mi][1] = *(const uint32_t*)&sAl[(rb + 8)*SW + kk    ];
                al[mi][2] = *(const uint32_t*)&sAl[(rb    )*SW + kk + 8];
                al[mi][3] = *(const uint32_t*)&sAl[(rb + 8)*SW + kk + 8];
            }
            #pragma unroll
            for (int ni = 0; ni < 4; ni++) {
                int nb = wn + ni * 8 + grp;
                int kk = k0 + qd * 2;
                bh[ni][0] = *(const uint32_t*)&sBh[nb*SW + kk    ];
                bh[ni][1] = *(const uint32_t*)&sBh[nb*SW + kk + 8];
                bl[ni][0] = *(const uint32_t*)&sBl[nb*SW + kk    ];
                bl[ni][1] = *(const uint32_t*)&sBl[nb*SW + kk + 8];
            }
            #pragma unroll
            for (int mi = 0; mi < 2; mi++)
                #pragma unroll
                for (int ni = 0; ni < 4; ni++) {
                    mma16816(acc[mi][ni], ah[mi], bh[ni]);
                    mma16816(acc[mi][ni], ah[mi], bl[ni]);
                    mma16816(acc[mi][ni], al[mi], bh[ni]);
                }
        }
        __syncthreads();
    }

    // epilogue: bias (+activation for gate path), direct global stores
    #pragma unroll
    for (int mi = 0; mi < 2; mi++) {
        #pragma unroll
        for (int ni = 0; ni < 4; ni++) {
            int c = cb + wn + ni * 8 + qd * 2;
            int r0 = row0 + wm + mi * 16 + grp;
            #pragma unroll
            for (int h = 0; h < 2; h++) {
                int row = r0 + h * 8;
                float v0 = acc[mi][ni][h*2 + 0];
                float v1 = acc[mi][ni][h*2 + 1];
                if (!isZ) {
                    float2 o;
                    o.x = v0 + bxv[c];
                    o.y = v1 + bxv[c + 1];
                    *(float2*)&g_x[(size_t)row * E_ + c] = o;
                } else {
                    float zc, sl;
                    float2 o;
                    zc = v0 + bzv[c];     sl = zc / (1.f + __expf(-zc)); o.x = 1.f / (1.f + __expf(-sl));
                    zc = v1 + bzv[c + 1]; sl = zc / (1.f + __expf(-zc)); o.y = 1.f / (1.f + __expf(-sl));
                    *(float2*)&g_gate[(size_t)row * E_ + c] = o;
                }
            }
        }
    }
}

// ---------------- K2: depthwise conv + 4 projections + ZOH discretization ----------------
__global__ __launch_bounds__(256) void proj_kernel(
        const float* __restrict__ cwf, const float* __restrict__ cbf,
        const float* __restrict__ cwb, const float* __restrict__ cbb,
        const float* __restrict__ WBf, const float* __restrict__ bBf,
        const float* __restrict__ WCf, const float* __restrict__ bCf,
        const float* __restrict__ WDf, const float* __restrict__ bDf,
        const float* __restrict__ WBb, const float* __restrict__ bBb,
        const float* __restrict__ WCb, const float* __restrict__ bCb,
        const float* __restrict__ WDb, const float* __restrict__ bDb,
        const float* __restrict__ A_log,
        const float* __restrict__ Wi,  const float* __restrict__ bi) {
    __shared__ float sA[64*32];
    __shared__ float sB[32*64];
    int tid = threadIdx.x;
    int tx = tid & 15, ty = tid >> 4;
    int s0 = blockIdx.x * 64;
    int b  = blockIdx.y;
    int dir = blockIdx.z;

    const float* cw = dir ? cwb : cwf;
    const float* cb = dir ? cbb : cbf;
    const float* WB = dir ? WBb : WBf;
    const float* WC = dir ? WCb : WCf;
    const float* WD = dir ? WDb : WDf;
    const float* bB = dir ? bBb : bBf;
    const float* bC = dir ? bCb : bCf;
    const float* bD = dir ? bDb : bDf;

    float acc[4][4];
    #pragma unroll
    for (int i = 0; i < 4; i++)
        #pragma unroll
        for (int m = 0; m < 4; m++) acc[i][m] = 0.f;

    for (int kt = 0; kt < E_; kt += 32) {
        #pragma unroll
        for (int i = 0; i < 8; i++) {
            int q = tid + i*256;
            int r = q >> 5, kk = q & 31;
            int e = kt + kk;
            int s = s0 + r;
            int j0 = dir ? (J_ - 1 - s) : s;
            float x1 = g_x[(size_t)(b*J_ + j0) * E_ + e];
            float x0 = 0.f, x2 = 0.f;
            if (s > 0)      { int jm = dir ? j0 + 1 : j0 - 1; x0 = g_x[(size_t)(b*J_ + jm) * E_ + e]; }
            if (s < J_ - 1) { int jp = dir ? j0 - 1 : j0 + 1; x2 = g_x[(size_t)(b*J_ + jp) * E_ + e]; }
            sA[q] = cw[e*3]*x0 + cw[e*3+1]*x1 + cw[e*3+2]*x2 + cb[e];
        }
        #pragma unroll
        for (int i = 0; i < 8; i++) {
            int q = tid + i*256;
            int kk = q >> 6, c = q & 63;
            int m = c >> 4, n = c & 15;
            const float* W = (m == 0) ? WB : (m == 1) ? WC : (m == 2) ? WD : Wi;
            sB[q] = W[(size_t)(kt + kk) * N_ + n];
        }
        __syncthreads();
        #pragma unroll
        for (int kk = 0; kk < 32; kk++) {
            float b0 = sB[kk*64 + tx];
            float b1 = sB[kk*64 + tx + 16];
            float b2 = sB[kk*64 + tx + 32];
            float b3 = sB[kk*64 + tx + 48];
            #pragma unroll
            for (int i = 0; i < 4; i++) {
                float a = sA[(ty + 16*i)*32 + kk];
                acc[i][0] += a*b0; acc[i][1] += a*b1; acc[i][2] += a*b2; acc[i][3] += a*b3;
            }
        }
        __syncthreads();
    }

    int n = tx;
    float al = A_log[n];
    float A_n = -log1pf(expf(al));
    float invA = 1.f / (A_n + 1e-6f);
    float bBv = bB[n], bCv = bC[n], bDv = bD[n], biv = bi[n];
    #pragma unroll
    for (int i = 0; i < 4; i++) {
        int s = s0 + ty + 16*i;
        float bt  = acc[i][0] + bBv;
        float ct  = acc[i][1] + bCv;
        float dtr = acc[i][2] + bDv;
        float u   = acc[i][3] + biv;
        float dt  = (dtr > 20.f) ? dtr : log1pf(__expf(dtr));
        float abar = __expf(dt * A_n);
        float bu = (abar - 1.f) * invA * bt * u;
        size_t base = (size_t)(b*N_ + n) * J_ + s;
        g_Abar[dir][base] = abar;
        g_Bu[dir][base]   = bu;
        g_Ct[dir][base]   = ct;
    }
}

// ---------------- K3: segmented warp scan ----------------
__global__ __launch_bounds__(512) void scan_kernel() {
    int b   = blockIdx.x;
    int dir = blockIdx.y;
    int w    = threadIdx.x >> 5;
    int lane = threadIdx.x & 31;
    size_t base = (size_t)(b*N_ + w) * J_;
    const float* Aa = g_Abar[dir] + base;
    const float* Bu = g_Bu[dir]   + base;
    const float* Ct = g_Ct[dir]   + base;
    float carry = 0.f;
    for (int seg = 0; seg < J_/32; seg++) {
        int s = seg*32 + lane;
        float a  = Aa[s];
        float bu = Bu[s];
        #pragma unroll
        for (int off = 1; off < 32; off <<= 1) {
            float ap = __shfl_up_sync(0xffffffffu, a,  off);
            float bp = __shfl_up_sync(0xffffffffu, bu, off);
            if (lane >= off) { bu = fmaf(a, bp, bu); a *= ap; }
        }
        float h = fmaf(a, carry, bu);
        carry = __shfl_sync(0xffffffffu, h, 31);
        float g = h * Ct[s];
        int jorig = dir ? (J_ - 1 - s) : s;
        g_g[dir][(size_t)(b*J_ + jorig) * N_ + w] = g;
    }
}

// ---------------- K4: readout + gate + output projection + residual ----------------
__global__ __launch_bounds__(256) void out_kernel(
        const float* __restrict__ tokens,
        const float* __restrict__ Wr, const float* __restrict__ br,
        const float* __restrict__ Wo, const float* __restrict__ bo,
        float* __restrict__ out) {
    __shared__ float gsm[16*16];
    __shared__ float ysm[16*384];
    __shared__ float wbuf[16*192];
    int tid = threadIdx.x;
    int j0 = blockIdx.x * 16;
    int b  = blockIdx.y;

    if (tid < 256) {
        int r = tid >> 4, n = tid & 15;
        size_t row = (size_t)(b*J_ + j0 + r);
        gsm[tid] = g_g[0][row*N_ + n] + g_g[1][row*N_ + n];
    }
    __syncthreads();

    for (int q = tid; q < 16*E_; q += 256) {
        int r = q / E_, e = q - r*E_;
        float acc = 2.f * br[e];
        #pragma unroll
        for (int nn = 0; nn < 16; nn++) acc += gsm[r*16 + nn] * Wr[(size_t)nn*E_ + e];
        size_t row = (size_t)(b*J_ + j0 + r);
        ysm[q] = acc * g_gate[row*E_ + e];
    }
    __syncthreads();

    int cg = tid & 15;
    int r  = tid >> 4;
    float acc[12];
    #pragma unroll
    for (int jj = 0; jj < 12; jj++) acc[jj] = 0.f;

    for (int et = 0; et < E_/16; et++) {
        for (int q = tid; q < 16*192; q += 256) {
            int kk = q / 192, d = q - kk*192;
            wbuf[q] = Wo[(size_t)(et*16 + kk) * D_ + d];
        }
        __syncthreads();
        #pragma unroll
        for (int el = 0; el < 16; el++) {
            float ys = ysm[r*E_ + et*16 + el];
            const float* wrow = &wbuf[el*192 + cg*12];
            #pragma unroll
            for (int jj = 0; jj < 12; jj++) acc[jj] += ys * wrow[jj];
        }
        __syncthreads();
    }

    #pragma unroll
    for (int jj = 0; jj < 12; jj++) wbuf[r*192 + cg*12 + jj] = acc[jj];
    __syncthreads();
    for (int q = tid; q < 16*192; q += 256) {
        int rr = q / 192, dd = q - rr*192;
        size_t row = (size_t)(b*J_ + j0 + rr);
        out[row*D_ + dd] = tokens[row*D_ + dd] + wbuf[q] + bo[dd];
    }
}

// ---------------- launch ----------------
extern "C" void kernel_launch(void* const* d_in, const int* in_sizes, int n_in,
                              void* d_out, int out_size) {
    const float* tokens = (const float*)d_in[0];
    const float* norm_g = (const float*)d_in[1];
    const float* norm_b = (const float*)d_in[2];
    const float* Wx  = (const float*)d_in[3];
    const float* bx  = (const float*)d_in[4];
    const float* Wz  = (const float*)d_in[5];
    const float* bz  = (const float*)d_in[6];
    const float* cwf = (const float*)d_in[7];
    const float* cbf = (const float*)d_in[8];
    const float* cwb = (const float*)d_in[9];
    const float* cbb = (const float*)d_in[10];
    const float* WBf = (const float*)d_in[11];
    const float* bBf = (const float*)d_in[12];
    const float* WCf = (const float*)d_in[13];
    const float* bCf = (const float*)d_in[14];
    const float* WDf = (const float*)d_in[15];
    const float* bDf = (const float*)d_in[16];
    const float* WBb = (const float*)d_in[17];
    const float* bBb = (const float*)d_in[18];
    const float* WCb = (const float*)d_in[19];
    const float* bCb = (const float*)d_in[20];
    const float* WDb = (const float*)d_in[21];
    const float* bDb = (const float*)d_in[22];
    const float* A_log = (const float*)d_in[23];
    const float* Wi  = (const float*)d_in[24];
    const float* bi  = (const float*)d_in[25];
    const float* Wr  = (const float*)d_in[26];
    const float* br  = (const float*)d_in[27];
    const float* Wo  = (const float*)d_in[28];
    const float* bo  = (const float*)d_in[29];
    float* out = (float*)d_out;

    ln_kernel<<<BJ_/8, 256>>>(tokens, norm_g, norm_b);
    wprep_kernel<<<(768*D_ + 255)/256, 256>>>(Wx, Wz);
    gemm1_mma<<<dim3(BJ_/128, 12), 256>>>(bx, bz);
    proj_kernel<<<dim3(J_/64, B_, 2), 256>>>(cwf, cbf, cwb, cbb,
                                             WBf, bBf, WCf, bCf, WDf, bDf,
                                             WBb, bBb, WCb, bCb, WDb, bDb,
                                             A_log, Wi, bi);
    scan_kernel<<<dim3(B_, 2), 512>>>();
    out_kernel<<<dim3(J_/16, B_), 256>>>(tokens, Wr, br, Wo, bo, out);
}

// round 4
// speedup vs baseline: 1.4536x; 1.3177x over previous
#include <cuda_runtime.h>
#include <cuda_bf16.h>
#include <math.h>
#include <stdint.h>

#define B_ 32
#define J_ 1024
#define D_ 192
#define E_ 384
#define N_ 16
#define BJ_ (B_*J_)

// ---------------- device scratch (no allocs allowed) ----------------
__device__ __nv_bfloat16 g_th[BJ_*D_];     // LN output hi (bf16)
__device__ __nv_bfloat16 g_tl[BJ_*D_];     // LN output lo (bf16)
__device__ __nv_bfloat16 g_wht[768*D_];    // [Wx|Wz] transposed hi: [col][k]
__device__ __nv_bfloat16 g_wlt[768*D_];    // [Wx|Wz] transposed lo
__device__ float g_x[BJ_*E_];              // x = t@Wx + bx
__device__ float g_gate[BJ_*E_];           // sigmoid(silu(z))
__device__ __nv_bfloat16 g_xch[2][BJ_*E_]; // conv output hi, scan order per dir
__device__ __nv_bfloat16 g_xcl[2][BJ_*E_]; // conv output lo
__device__ __nv_bfloat16 g_wph[2][64*E_];  // [dir][col][k] packed [WB|WC|WD|Wi] hi
__device__ __nv_bfloat16 g_wpl[2][64*E_];  // lo
__device__ float g_Abar[2][B_*N_*J_];      // [dir][b][n][s]
__device__ float g_Bu  [2][B_*N_*J_];
__device__ float g_Ct  [2][B_*N_*J_];
__device__ float g_g   [2][BJ_*N_];        // hs*Ct at ORIGINAL j

// ---------------- K0: LayerNorm -> bf16 hi/lo ----------------
__global__ void ln_kernel(const float* __restrict__ tok,
                          const float* __restrict__ gamma,
                          const float* __restrict__ beta) {
    int row  = blockIdx.x * 8 + (threadIdx.x >> 5);
    int lane = threadIdx.x & 31;
    const float* tr = tok + (size_t)row * D_;
    float v[6];
    float s = 0.f;
    #pragma unroll
    for (int i = 0; i < 6; i++) { v[i] = tr[lane + 32*i]; s += v[i]; }
    #pragma unroll
    for (int o = 16; o > 0; o >>= 1) s += __shfl_xor_sync(0xffffffffu, s, o);
    float mu = s * (1.f / D_);
    float vs = 0.f;
    #pragma unroll
    for (int i = 0; i < 6; i++) { float d = v[i] - mu; vs += d * d; }
    #pragma unroll
    for (int o = 16; o > 0; o >>= 1) vs += __shfl_xor_sync(0xffffffffu, vs, o);
    float inv = rsqrtf(vs * (1.f / D_) + 1e-5f);
    #pragma unroll
    for (int i = 0; i < 6; i++) {
        int c = lane + 32*i;
        float t = (v[i] - mu) * inv * gamma[c] + beta[c];
        __nv_bfloat16 h = __float2bfloat16(t);
        g_th[(size_t)row * D_ + c] = h;
        g_tl[(size_t)row * D_ + c] = __float2bfloat16(t - __bfloat162float(h));
    }
}

// ---------------- K0b: W prep for gemm1 (transpose + hi/lo split) ----------------
__global__ void wprep_kernel(const float* __restrict__ Wx, const float* __restrict__ Wz) {
    int i = blockIdx.x * 256 + threadIdx.x;
    if (i >= 768 * D_) return;
    int c = i / D_, k = i - c * D_;
    float w = (c < E_) ? Wx[(size_t)k * E_ + c] : Wz[(size_t)k * E_ + (c - E_)];
    __nv_bfloat16 h = __float2bfloat16(w);
    g_wht[i] = h;
    g_wlt[i] = __float2bfloat16(w - __bfloat162float(h));
}

// ---------------- K0c: W prep for proj MMA ----------------
__global__ void wprep2_kernel(
        const float* __restrict__ WBf, const float* __restrict__ WCf,
        const float* __restrict__ WDf, const float* __restrict__ WBb,
        const float* __restrict__ WCb, const float* __restrict__ WDb,
        const float* __restrict__ Wi) {
    int i = blockIdx.x * 256 + threadIdx.x;
    if (i >= 2 * 64 * E_) return;
    int dir = i / (64 * E_);
    int rem = i - dir * 64 * E_;
    int c = rem / E_, k = rem - c * E_;
    int m = c >> 4, n = c & 15;
    const float* W;
    if (m == 0) W = dir ? WBb : WBf;
    else if (m == 1) W = dir ? WCb : WCf;
    else if (m == 2) W = dir ? WDb : WDf;
    else W = Wi;
    float w = W[(size_t)k * N_ + n];
    __nv_bfloat16 h = __float2bfloat16(w);
    g_wph[dir][rem] = h;
    g_wpl[dir][rem] = __float2bfloat16(w - __bfloat162float(h));
}

// ---------------- MMA helper ----------------
#define SW 40   // smem row stride in bf16 (conflict-free for quad pattern)

__device__ __forceinline__ void mma16816(float* c, const uint32_t* a, const uint32_t* b) {
    asm volatile(
        "mma.sync.aligned.m16n8k16.row.col.f32.bf16.bf16.f32 "
        "{%0,%1,%2,%3}, {%4,%5,%6,%7}, {%8,%9}, {%0,%1,%2,%3};"
        : "+f"(c[0]), "+f"(c[1]), "+f"(c[2]), "+f"(c[3])
        : "r"(a[0]), "r"(a[1]), "r"(a[2]), "r"(a[3]), "r"(b[0]), "r"(b[1]));
}

// ---------------- K1: HMMA dual GEMM (bf16 hi/lo split) ----------------
__global__ __launch_bounds__(256) void gemm1_mma(const float* __restrict__ bxv,
                                                 const float* __restrict__ bzv) {
    __shared__ __nv_bfloat16 sAh[128*SW];
    __shared__ __nv_bfloat16 sAl[128*SW];
    __shared__ __nv_bfloat16 sBh[64*SW];
    __shared__ __nv_bfloat16 sBl[64*SW];

    int tid  = threadIdx.x;
    int wid  = tid >> 5;
    int lane = tid & 31;
    int grp  = lane >> 2;
    int qd   = lane & 3;
    int row0 = blockIdx.x * 128;
    int yb   = blockIdx.y;
    int isZ  = (yb >= 6);
    int cb   = (isZ ? yb - 6 : yb) * 64;
    int csrc = cb + (isZ ? E_ : 0);
    int wm = (wid & 3) * 32;
    int wn = (wid >> 2) * 32;

    float acc[2][4][4];
    #pragma unroll
    for (int mi = 0; mi < 2; mi++)
        #pragma unroll
        for (int ni = 0; ni < 4; ni++)
            #pragma unroll
            for (int q = 0; q < 4; q++) acc[mi][ni][q] = 0.f;

    for (int kt = 0; kt < D_; kt += 32) {
        #pragma unroll
        for (int i = 0; i < 2; i++) {
            int q = tid + i * 256;
            int r = q >> 2, kc = (q & 3) * 8;
            const size_t go = (size_t)(row0 + r) * D_ + kt + kc;
            *(uint4*)&sAh[r*SW + kc] = *(const uint4*)(g_th + go);
            *(uint4*)&sAl[r*SW + kc] = *(const uint4*)(g_tl + go);
        }
        {
            int r = tid >> 2, kc = (tid & 3) * 8;
            const size_t go = (size_t)(csrc + r) * D_ + kt + kc;
            *(uint4*)&sBh[r*SW + kc] = *(const uint4*)(g_wht + go);
            *(uint4*)&sBl[r*SW + kc] = *(const uint4*)(g_wlt + go);
        }
        __syncthreads();

        #pragma unroll
        for (int ks = 0; ks < 2; ks++) {
            int k0 = ks * 16;
            uint32_t ah[2][4], al[2][4], bh[4][2], bl[4][2];
            #pragma unroll
            for (int mi = 0; mi < 2; mi++) {
                int rb = wm + mi * 16 + grp;
                int kk = k0 + qd * 2;
                ah[mi][0] = *(const uint32_t*)&sAh[(rb    )*SW + kk    ];
                ah[mi][1] = *(const uint32_t*)&sAh[(rb + 8)*SW + kk    ];
                ah[mi][2] = *(const uint32_t*)&sAh[(rb    )*SW + kk + 8];
                ah[mi][3] = *(const uint32_t*)&sAh[(rb + 8)*SW + kk + 8];
                al[mi][0] = *(const uint32_t*)&sAl[(rb    )*SW + kk    ];
                al[mi][1] = *(const uint32_t*)&sAl[(rb + 8)*SW + kk    ];
                al[mi][2] = *(const uint32_t*)&sAl[(rb    )*SW + kk + 8];
                al[mi][3] = *(const uint32_t*)&sAl[(rb + 8)*SW + kk + 8];
            }
            #pragma unroll
            for (int ni = 0; ni < 4; ni++) {
                int nb = wn + ni * 8 + grp;
                int kk = k0 + qd * 2;
                bh[ni][0] = *(const uint32_t*)&sBh[nb*SW + kk    ];
                bh[ni][1] = *(const uint32_t*)&sBh[nb*SW + kk + 8];
                bl[ni][0] = *(const uint32_t*)&sBl[nb*SW + kk    ];
                bl[ni][1] = *(const uint32_t*)&sBl[nb*SW + kk + 8];
            }
            #pragma unroll
            for (int mi = 0; mi < 2; mi++)
                #pragma unroll
                for (int ni = 0; ni < 4; ni++) {
                    mma16816(acc[mi][ni], ah[mi], bh[ni]);
                    mma16816(acc[mi][ni], ah[mi], bl[ni]);
                    mma16816(acc[mi][ni], al[mi], bh[ni]);
                }
        }
        __syncthreads();
    }

    #pragma unroll
    for (int mi = 0; mi < 2; mi++) {
        #pragma unroll
        for (int ni = 0; ni < 4; ni++) {
            int c = cb + wn + ni * 8 + qd * 2;
            int r0 = row0 + wm + mi * 16 + grp;
            #pragma unroll
            for (int h = 0; h < 2; h++) {
                int row = r0 + h * 8;
                float v0 = acc[mi][ni][h*2 + 0];
                float v1 = acc[mi][ni][h*2 + 1];
                if (!isZ) {
                    float2 o;
                    o.x = v0 + bxv[c];
                    o.y = v1 + bxv[c + 1];
                    *(float2*)&g_x[(size_t)row * E_ + c] = o;
                } else {
                    float zc, sl;
                    float2 o;
                    zc = v0 + bzv[c];     sl = zc / (1.f + __expf(-zc)); o.x = 1.f / (1.f + __expf(-sl));
                    zc = v1 + bzv[c + 1]; sl = zc / (1.f + __expf(-zc)); o.y = 1.f / (1.f + __expf(-sl));
                    *(float2*)&g_gate[(size_t)row * E_ + c] = o;
                }
            }
        }
    }
}

// ---------------- K2a: depthwise conv (both dirs), fp32 -> bf16 hi/lo ----------------
// block 384 threads = 4 rows x 96 e-quads
__global__ __launch_bounds__(384) void conv_kernel(
        const float* __restrict__ cwf, const float* __restrict__ cbf,
        const float* __restrict__ cwb, const float* __restrict__ cbb) {
    int tid = threadIdx.x;
    int rl  = tid / 96;
    int eq  = tid - rl * 96;
    int e   = eq * 4;
    int row = blockIdx.x * 4 + rl;          // global row = b*J + j
    int j   = row & (J_ - 1);
    int b   = row >> 10;

    const float* xr = g_x + (size_t)row * E_ + e;
    float4 x1 = *(const float4*)xr;
    float4 x0 = make_float4(0,0,0,0), x2 = make_float4(0,0,0,0);
    if (j > 0)      x0 = *(const float4*)(xr - E_);
    if (j < J_ - 1) x2 = *(const float4*)(xr + E_);

    float vf[4], vb[4];
    #pragma unroll
    for (int q = 0; q < 4; q++) {
        int ec = e + q;
        float a0 = (&x0.x)[q], a1 = (&x1.x)[q], a2 = (&x2.x)[q];
        float wf0 = cwf[ec*3], wf1 = cwf[ec*3+1], wf2 = cwf[ec*3+2];
        float wb0 = cwb[ec*3], wb1 = cwb[ec*3+1], wb2 = cwb[ec*3+2];
        vf[q] = wf0*a0 + wf1*a1 + wf2*a2 + cbf[ec];
        vb[q] = wb0*a2 + wb1*a1 + wb2*a0 + cbb[ec];   // dir1 at s=J-1-j
    }
    // pack 4 bf16 hi + 4 lo per dir
    __nv_bfloat16 fh[4], fl[4], bh[4], bl[4];
    #pragma unroll
    for (int q = 0; q < 4; q++) {
        fh[q] = __float2bfloat16(vf[q]); fl[q] = __float2bfloat16(vf[q] - __bfloat162float(fh[q]));
        bh[q] = __float2bfloat16(vb[q]); bl[q] = __float2bfloat16(vb[q] - __bfloat162float(bh[q]));
    }
    size_t of = (size_t)row * E_ + e;
    size_t ob = (size_t)(b * J_ + (J_ - 1 - j)) * E_ + e;
    *(uint2*)&g_xch[0][of] = *(uint2*)fh;
    *(uint2*)&g_xcl[0][of] = *(uint2*)fl;
    *(uint2*)&g_xch[1][ob] = *(uint2*)bh;
    *(uint2*)&g_xcl[1][ob] = *(uint2*)bl;
}

// ---------------- K2b: proj MMA (xc @ [WB|WC|WD|Wi]) + ZOH epilogue ----------------
#define EPS 65   // epilogue smem stride (floats)
__global__ __launch_bounds__(256) void projmma_kernel(
        const float* __restrict__ bBf, const float* __restrict__ bCf,
        const float* __restrict__ bDf, const float* __restrict__ bBb,
        const float* __restrict__ bCb, const float* __restrict__ bDb,
        const float* __restrict__ A_log, const float* __restrict__ bi) {
    __shared__ __align__(16) char smraw[128*EPS*4];   // 33280 B; stage needs 30720
    __nv_bfloat16* sAh = (__nv_bfloat16*)smraw;               // 128*SW
    __nv_bfloat16* sAl = sAh + 128*SW;
    __nv_bfloat16* sBh = sAl + 128*SW;                        // 64*SW
    __nv_bfloat16* sBl = sBh + 64*SW;
    float* ep = (float*)smraw;
    __shared__ float sbias[4][N_];
    __shared__ float sAn[N_], sInv[N_];

    int tid  = threadIdx.x;
    int wid  = tid >> 5;
    int lane = tid & 31;
    int grp  = lane >> 2;
    int qd   = lane & 3;
    int row0 = blockIdx.x * 128;           // global scan-order row
    int dir  = blockIdx.y;
    int b    = row0 >> 10;
    int s0   = row0 & (J_ - 1);
    int wm = (wid & 3) * 32;
    int wn = (wid >> 2) * 32;

    if (tid < N_) {
        int n = tid;
        sbias[0][n] = dir ? bBb[n] : bBf[n];
        sbias[1][n] = dir ? bCb[n] : bCf[n];
        sbias[2][n] = dir ? bDb[n] : bDf[n];
        sbias[3][n] = bi[n];
        float al = A_log[n];
        float An = -log1pf(expf(al));
        sAn[n] = An;
        sInv[n] = 1.f / (An + 1e-6f);
    }

    const __nv_bfloat16* Ah = g_xch[dir];
    const __nv_bfloat16* Al = g_xcl[dir];
    const __nv_bfloat16* Bh = g_wph[dir];
    const __nv_bfloat16* Bl = g_wpl[dir];

    float acc[2][4][4];
    #pragma unroll
    for (int mi = 0; mi < 2; mi++)
        #pragma unroll
        for (int ni = 0; ni < 4; ni++)
            #pragma unroll
            for (int q = 0; q < 4; q++) acc[mi][ni][q] = 0.f;

    for (int kt = 0; kt < E_; kt += 32) {
        __syncthreads();    // protect smem reuse across iterations + epilogue union
        #pragma unroll
        for (int i = 0; i < 2; i++) {
            int q = tid + i * 256;
            int r = q >> 2, kc = (q & 3) * 8;
            const size_t go = (size_t)(row0 + r) * E_ + kt + kc;
            *(uint4*)&sAh[r*SW + kc] = *(const uint4*)(Ah + go);
            *(uint4*)&sAl[r*SW + kc] = *(const uint4*)(Al + go);
        }
        {
            int r = tid >> 2, kc = (tid & 3) * 8;
            const size_t go = (size_t)r * E_ + kt + kc;
            *(uint4*)&sBh[r*SW + kc] = *(const uint4*)(Bh + go);
            *(uint4*)&sBl[r*SW + kc] = *(const uint4*)(Bl + go);
        }
        __syncthreads();

        #pragma unroll
        for (int ks = 0; ks < 2; ks++) {
            int k0 = ks * 16;
            uint32_t ah[2][4], al[2][4], bh[4][2], bl[4][2];
            #pragma unroll
            for (int mi = 0; mi < 2; mi++) {
                int rb = wm + mi * 16 + grp;
                int kk = k0 + qd * 2;
                ah[mi][0] = *(const uint32_t*)&sAh[(rb    )*SW + kk    ];
                ah[mi][1] = *(const uint32_t*)&sAh[(rb + 8)*SW + kk    ];
                ah[mi][2] = *(const uint32_t*)&sAh[(rb    )*SW + kk + 8];
                ah[mi][3] = *(const uint32_t*)&sAh[(rb + 8)*SW + kk + 8];
                al[mi][0] = *(const uint32_t*)&sAl[(rb    )*SW + kk    ];
                al[mi][1] = *(const uint32_t*)&sAl[(rb + 8)*SW + kk    ];
                al[mi][2] = *(const uint32_t*)&sAl[(rb    )*SW + kk + 8];
                al[mi][3] = *(const uint32_t*)&sAl[(rb + 8)*SW + kk + 8];
            }
            #pragma unroll
            for (int ni = 0; ni < 4; ni++) {
                int nb = wn + ni * 8 + grp;
                int kk = k0 + qd * 2;
                bh[ni][0] = *(const uint32_t*)&sBh[nb*SW + kk    ];
                bh[ni][1] = *(const uint32_t*)&sBh[nb*SW + kk + 8];
                bl[ni][0] = *(const uint32_t*)&sBl[nb*SW + kk    ];
                bl[ni][1] = *(const uint32_t*)&sBl[nb*SW + kk + 8];
            }
            #pragma unroll
            for (int mi = 0; mi < 2; mi++)
                #pragma unroll
                for (int ni = 0; ni < 4; ni++) {
                    mma16816(acc[mi][ni], ah[mi], bh[ni]);
                    mma16816(acc[mi][ni], ah[mi], bl[ni]);
                    mma16816(acc[mi][ni], al[mi], bh[ni]);
                }
        }
    }
    __syncthreads();

    // stage accumulators to smem [row][col], stride EPS
    #pragma unroll
    for (int mi = 0; mi < 2; mi++)
        #pragma unroll
        for (int ni = 0; ni < 4; ni++) {
            int c = wn + ni * 8 + qd * 2;
            int r0 = wm + mi * 16 + grp;
            #pragma unroll
            for (int h = 0; h < 2; h++) {
                ep[(r0 + h*8)*EPS + c    ] = acc[mi][ni][h*2 + 0];
                ep[(r0 + h*8)*EPS + c + 1] = acc[mi][ni][h*2 + 1];
            }
        }
    __syncthreads();

    // ZOH epilogue: each item = (s_local, n)
    #pragma unroll
    for (int it = 0; it < 8; it++) {
        int idx = tid + it * 256;
        int s = idx & 127;
        int n = idx >> 7;
        float bt  = ep[s*EPS + n     ] + sbias[0][n];
        float ct  = ep[s*EPS + n + 16] + sbias[1][n];
        float dtr = ep[s*EPS + n + 32] + sbias[2][n];
        float u   = ep[s*EPS + n + 48] + sbias[3][n];
        float An  = sAn[n];
        float dt  = (dtr > 20.f) ? dtr : log1pf(__expf(dtr));
        float abar = __expf(dt * An);
        float bu = (abar - 1.f) * sInv[n] * bt * u;
        size_t base = (size_t)(b*N_ + n) * J_ + s0 + s;
        g_Abar[dir][base] = abar;
        g_Bu[dir][base]   = bu;
        g_Ct[dir][base]   = ct;
    }
}

// ---------------- K3: segmented warp scan ----------------
__global__ __launch_bounds__(512) void scan_kernel() {
    int b   = blockIdx.x;
    int dir = blockIdx.y;
    int w    = threadIdx.x >> 5;
    int lane = threadIdx.x & 31;
    size_t base = (size_t)(b*N_ + w) * J_;
    const float* Aa = g_Abar[dir] + base;
    const float* Bu = g_Bu[dir]   + base;
    const float* Ct = g_Ct[dir]   + base;
    float carry = 0.f;
    for (int seg = 0; seg < J_/32; seg++) {
        int s = seg*32 + lane;
        float a  = Aa[s];
        float bu = Bu[s];
        #pragma unroll
        for (int off = 1; off < 32; off <<= 1) {
            float ap = __shfl_up_sync(0xffffffffu, a,  off);
            float bp = __shfl_up_sync(0xffffffffu, bu, off);
            if (lane >= off) { bu = fmaf(a, bp, bu); a *= ap; }
        }
        float h = fmaf(a, carry, bu);
        carry = __shfl_sync(0xffffffffu, h, 31);
        float g = h * Ct[s];
        int jorig = dir ? (J_ - 1 - s) : s;
        g_g[dir][(size_t)(b*J_ + jorig) * N_ + w] = g;
    }
}

// ---------------- K4: readout + gate + output projection + residual ----------------
__global__ __launch_bounds__(256) void out_kernel(
        const float* __restrict__ tokens,
        const float* __restrict__ Wr, const float* __restrict__ br,
        const float* __restrict__ Wo, const float* __restrict__ bo,
        float* __restrict__ out) {
    __shared__ float gsm[16*16];
    __shared__ float ysm[16*384];
    __shared__ float wbuf[16*192];
    int tid = threadIdx.x;
    int j0 = blockIdx.x * 16;
    int b  = blockIdx.y;

    if (tid < 256) {
        int r = tid >> 4, n = tid & 15;
        size_t row = (size_t)(b*J_ + j0 + r);
        gsm[tid] = g_g[0][row*N_ + n] + g_g[1][row*N_ + n];
    }
    __syncthreads();

    for (int q = tid; q < 16*E_; q += 256) {
        int r = q / E_, e = q - r*E_;
        float acc = 2.f * br[e];
        #pragma unroll
        for (int nn = 0; nn < 16; nn++) acc += gsm[r*16 + nn] * Wr[(size_t)nn*E_ + e];
        size_t row = (size_t)(b*J_ + j0 + r);
        ysm[q] = acc * g_gate[row*E_ + e];
    }
    __syncthreads();

    int cg = tid & 15;
    int r  = tid >> 4;
    float acc[12];
    #pragma unroll
    for (int jj = 0; jj < 12; jj++) acc[jj] = 0.f;

    for (int et = 0; et < E_/16; et++) {
        for (int q = tid; q < 16*192; q += 256) {
            int kk = q / 192, d = q - kk*192;
            wbuf[q] = Wo[(size_t)(et*16 + kk) * D_ + d];
        }
        __syncthreads();
        #pragma unroll
        for (int el = 0; el < 16; el++) {
            float ys = ysm[r*E_ + et*16 + el];
            const float* wrow = &wbuf[el*192 + cg*12];
            #pragma unroll
            for (int jj = 0; jj < 12; jj++) acc[jj] += ys * wrow[jj];
        }
        __syncthreads();
    }

    #pragma unroll
    for (int jj = 0; jj < 12; jj++) wbuf[r*192 + cg*12 + jj] = acc[jj];
    __syncthreads();
    for (int q = tid; q < 16*192; q += 256) {
        int rr = q / 192, dd = q - rr*192;
        size_t row = (size_t)(b*J_ + j0 + rr);
        out[row*D_ + dd] = tokens[row*D_ + dd] + wbuf[q] + bo[dd];
    }
}

// ---------------- launch ----------------
extern "C" void kernel_launch(void* const* d_in, const int* in_sizes, int n_in,
                              void* d_out, int out_size) {
    const float* tokens = (const float*)d_in[0];
    const float* norm_g = (const float*)d_in[1];
    const float* norm_b = (const float*)d_in[2];
    const float* Wx  = (const float*)d_in[3];
    const float* bx  = (const float*)d_in[4];
    const float* Wz  = (const float*)d_in[5];
    const float* bz  = (const float*)d_in[6];
    const float* cwf = (const float*)d_in[7];
    const float* cbf = (const float*)d_in[8];
    const float* cwb = (const float*)d_in[9];
    const float* cbb = (const float*)d_in[10];
    const float* WBf = (const float*)d_in[11];
    const float* bBf = (const float*)d_in[12];
    const float* WCf = (const float*)d_in[13];
    const float* bCf = (const float*)d_in[14];
    const float* WDf = (const float*)d_in[15];
    const float* bDf = (const float*)d_in[16];
    const float* WBb = (const float*)d_in[17];
    const float* bBb = (const float*)d_in[18];
    const float* WCb = (const float*)d_in[19];
    const float* bCb = (const float*)d_in[20];
    const float* WDb = (const float*)d_in[21];
    const float* bDb = (const float*)d_in[22];
    const float* A_log = (const float*)d_in[23];
    const float* Wi  = (const float*)d_in[24];
    const float* bi  = (const float*)d_in[25];
    const float* Wr  = (const float*)d_in[26];
    const float* br  = (const float*)d_in[27];
    const float* Wo  = (const float*)d_in[28];
    const float* bo  = (const float*)d_in[29];
    float* out = (float*)d_out;

    ln_kernel<<<BJ_/8, 256>>>(tokens, norm_g, norm_b);
    wprep_kernel<<<(768*D_ + 255)/256, 256>>>(Wx, Wz);
    wprep2_kernel<<<(2*64*E_ + 255)/256, 256>>>(WBf, WCf, WDf, WBb, WCb, WDb, Wi);
    gemm1_mma<<<dim3(BJ_/128, 12), 256>>>(bx, bz);
    conv_kernel<<<BJ_/4, 384>>>(cwf, cbf, cwb, cbb);
    projmma_kernel<<<dim3(BJ_/128, 2), 256>>>(bBf, bCf, bDf, bBb, bCb, bDb, A_log, bi);
    scan_kernel<<<dim3(B_, 2), 512>>>();
    out_kernel<<<dim3(J_/16, B_), 256>>>(tokens, Wr, br, Wo, bo, out);
}

// round 5
// speedup vs baseline: 2.4462x; 1.6828x over previous
#include <cuda_runtime.h>
#include <cuda_bf16.h>
#include <math.h>
#include <stdint.h>

#define B_ 32
#define J_ 1024
#define D_ 192
#define E_ 384
#define N_ 16
#define BJ_ (B_*J_)

// ---------------- device scratch (no allocs allowed) ----------------
__device__ __nv_bfloat16 g_th[BJ_*D_];     // LN output hi (bf16)
__device__ __nv_bfloat16 g_tl[BJ_*D_];     // LN output lo (bf16)
__device__ __nv_bfloat16 g_wht[768*D_];    // [Wx|Wz] transposed hi: [col][k]
__device__ __nv_bfloat16 g_wlt[768*D_];    // [Wx|Wz] transposed lo
__device__ float g_x[BJ_*E_];              // x = t@Wx + bx
__device__ float g_gate[BJ_*E_];           // sigmoid(silu(z))
__device__ __nv_bfloat16 g_xch[2][BJ_*E_]; // conv output hi (later: [0] reused as y hi)
__device__ __nv_bfloat16 g_xcl[2][BJ_*E_]; // conv output lo (later: [0] reused as y lo)
__device__ __nv_bfloat16 g_wph[2][64*E_];  // [dir][col][k] packed [WB|WC|WD|Wi] hi
__device__ __nv_bfloat16 g_wpl[2][64*E_];  // lo
__device__ __nv_bfloat16 g_woh[192*E_];    // Wo transposed hi: [d][k]
__device__ __nv_bfloat16 g_wol[192*E_];    // lo
__device__ float g_Abar[2][B_*N_*J_];      // [dir][b][n][s]
__device__ float g_Bu  [2][B_*N_*J_];
__device__ float g_Ct  [2][B_*N_*J_];
__device__ float g_g   [2][BJ_*N_];        // hs*Ct at ORIGINAL j

// ---------------- helpers ----------------
#define SW 40   // smem row stride in bf16 (80B: conflict-free for ldmatrix phases)

__device__ __forceinline__ uint32_t smem_u32(const void* p) {
    return (uint32_t)__cvta_generic_to_shared(p);
}
__device__ __forceinline__ void ldsm_x4(uint32_t* r, uint32_t addr) {
    asm volatile("ldmatrix.sync.aligned.m8n8.x4.shared.b16 {%0,%1,%2,%3}, [%4];"
        : "=r"(r[0]), "=r"(r[1]), "=r"(r[2]), "=r"(r[3]) : "r"(addr));
}
// A fragment (16x16): rows rb..rb+15, k halves k0 / k0+8
__device__ __forceinline__ void lda_frag(uint32_t* a, uint32_t sbase, int rb, int k0, int lane) {
    uint32_t addr = sbase + (uint32_t)((rb + (lane & 15)) * (SW*2) + k0*2 + ((lane >> 4) << 4));
    ldsm_x4(a, addr);
}
// B fragments for two ni blocks (ni, ni+1): rows = n (K-major), k halves
__device__ __forceinline__ void ldb_frag(uint32_t* b, uint32_t sbase, int nb_pair, int k0, int lane) {
    int sub = lane >> 3;
    int row = nb_pair + ((sub >> 1) << 3) + (lane & 7);
    uint32_t addr = sbase + (uint32_t)(row * (SW*2) + (k0 + ((sub & 1) << 3)) * 2);
    ldsm_x4(b, addr);
}
__device__ __forceinline__ void mma16816(float* c, const uint32_t* a, const uint32_t* b) {
    asm volatile(
        "mma.sync.aligned.m16n8k16.row.col.f32.bf16.bf16.f32 "
        "{%0,%1,%2,%3}, {%4,%5,%6,%7}, {%8,%9}, {%0,%1,%2,%3};"
        : "+f"(c[0]), "+f"(c[1]), "+f"(c[2]), "+f"(c[3])
        : "r"(a[0]), "r"(a[1]), "r"(a[2]), "r"(a[3]), "r"(b[0]), "r"(b[1]));
}

// ---------------- K0: LayerNorm -> bf16 hi/lo ----------------
__global__ void ln_kernel(const float* __restrict__ tok,
                          const float* __restrict__ gamma,
                          const float* __restrict__ beta) {
    int row  = blockIdx.x * 8 + (threadIdx.x >> 5);
    int lane = threadIdx.x & 31;
    const float* tr = tok + (size_t)row * D_;
    float v[6];
    float s = 0.f;
    #pragma unroll
    for (int i = 0; i < 6; i++) { v[i] = tr[lane + 32*i]; s += v[i]; }
    #pragma unroll
    for (int o = 16; o > 0; o >>= 1) s += __shfl_xor_sync(0xffffffffu, s, o);
    float mu = s * (1.f / D_);
    float vs = 0.f;
    #pragma unroll
    for (int i = 0; i < 6; i++) { float d = v[i] - mu; vs += d * d; }
    #pragma unroll
    for (int o = 16; o > 0; o >>= 1) vs += __shfl_xor_sync(0xffffffffu, vs, o);
    float inv = rsqrtf(vs * (1.f / D_) + 1e-5f);
    #pragma unroll
    for (int i = 0; i < 6; i++) {
        int c = lane + 32*i;
        float t = (v[i] - mu) * inv * gamma[c] + beta[c];
        __nv_bfloat16 h = __float2bfloat16(t);
        g_th[(size_t)row * D_ + c] = h;
        g_tl[(size_t)row * D_ + c] = __float2bfloat16(t - __bfloat162float(h));
    }
}

// ---------------- K0b/c/d: weight prep ----------------
__global__ void wprep_kernel(const float* __restrict__ Wx, const float* __restrict__ Wz) {
    int i = blockIdx.x * 256 + threadIdx.x;
    if (i >= 768 * D_) return;
    int c = i / D_, k = i - c * D_;
    float w = (c < E_) ? Wx[(size_t)k * E_ + c] : Wz[(size_t)k * E_ + (c - E_)];
    __nv_bfloat16 h = __float2bfloat16(w);
    g_wht[i] = h;
    g_wlt[i] = __float2bfloat16(w - __bfloat162float(h));
}
__global__ void wprep2_kernel(
        const float* __restrict__ WBf, const float* __restrict__ WCf,
        const float* __restrict__ WDf, const float* __restrict__ WBb,
        const float* __restrict__ WCb, const float* __restrict__ WDb,
        const float* __restrict__ Wi) {
    int i = blockIdx.x * 256 + threadIdx.x;
    if (i >= 2 * 64 * E_) return;
    int dir = i / (64 * E_);
    int rem = i - dir * 64 * E_;
    int c = rem / E_, k = rem - c * E_;
    int m = c >> 4, n = c & 15;
    const float* W;
    if (m == 0) W = dir ? WBb : WBf;
    else if (m == 1) W = dir ? WCb : WCf;
    else if (m == 2) W = dir ? WDb : WDf;
    else W = Wi;
    float w = W[(size_t)k * N_ + n];
    __nv_bfloat16 h = __float2bfloat16(w);
    g_wph[dir][rem] = h;
    g_wpl[dir][rem] = __float2bfloat16(w - __bfloat162float(h));
}
__global__ void wprep3_kernel(const float* __restrict__ Wo) {
    int i = blockIdx.x * 256 + threadIdx.x;
    if (i >= 192 * E_) return;
    int d = i / E_, k = i - d * E_;
    float w = Wo[(size_t)k * D_ + d];
    __nv_bfloat16 h = __float2bfloat16(w);
    g_woh[i] = h;
    g_wol[i] = __float2bfloat16(w - __bfloat162float(h));
}

// ---------------- K1: HMMA dual GEMM (bf16 hi/lo, ldmatrix) ----------------
__global__ __launch_bounds__(256) void gemm1_mma(const float* __restrict__ bxv,
                                                 const float* __restrict__ bzv) {
    __shared__ __nv_bfloat16 sAh[128*SW];
    __shared__ __nv_bfloat16 sAl[128*SW];
    __shared__ __nv_bfloat16 sBh[64*SW];
    __shared__ __nv_bfloat16 sBl[64*SW];

    int tid  = threadIdx.x;
    int wid  = tid >> 5;
    int lane = tid & 31;
    int grp  = lane >> 2;
    int qd   = lane & 3;
    int row0 = blockIdx.x * 128;
    int yb   = blockIdx.y;
    int isZ  = (yb >= 6);
    int cb   = (isZ ? yb - 6 : yb) * 64;
    int csrc = cb + (isZ ? E_ : 0);
    int wm = (wid & 3) * 32;
    int wn = (wid >> 2) * 32;
    uint32_t aAh = smem_u32(sAh), aAl = smem_u32(sAl);
    uint32_t aBh = smem_u32(sBh), aBl = smem_u32(sBl);

    float acc[2][4][4];
    #pragma unroll
    for (int mi = 0; mi < 2; mi++)
        #pragma unroll
        for (int ni = 0; ni < 4; ni++)
            #pragma unroll
            for (int q = 0; q < 4; q++) acc[mi][ni][q] = 0.f;

    for (int kt = 0; kt < D_; kt += 32) {
        #pragma unroll
        for (int i = 0; i < 2; i++) {
            int q = tid + i * 256;
            int r = q >> 2, kc = (q & 3) * 8;
            const size_t go = (size_t)(row0 + r) * D_ + kt + kc;
            *(uint4*)&sAh[r*SW + kc] = *(const uint4*)(g_th + go);
            *(uint4*)&sAl[r*SW + kc] = *(const uint4*)(g_tl + go);
        }
        {
            int r = tid >> 2, kc = (tid & 3) * 8;
            const size_t go = (size_t)(csrc + r) * D_ + kt + kc;
            *(uint4*)&sBh[r*SW + kc] = *(const uint4*)(g_wht + go);
            *(uint4*)&sBl[r*SW + kc] = *(const uint4*)(g_wlt + go);
        }
        __syncthreads();

        #pragma unroll
        for (int ks = 0; ks < 2; ks++) {
            int k0 = ks * 16;
            uint32_t ah[2][4], al[2][4], bh[8], bl[8];
            #pragma unroll
            for (int mi = 0; mi < 2; mi++) {
                lda_frag(ah[mi], aAh, wm + mi*16, k0, lane);
                lda_frag(al[mi], aAl, wm + mi*16, k0, lane);
            }
            #pragma unroll
            for (int p = 0; p < 2; p++) {
                ldb_frag(&bh[p*4], aBh, wn + p*16, k0, lane);
                ldb_frag(&bl[p*4], aBl, wn + p*16, k0, lane);
            }
            #pragma unroll
            for (int mi = 0; mi < 2; mi++)
                #pragma unroll
                for (int ni = 0; ni < 4; ni++) {
                    mma16816(acc[mi][ni], ah[mi], &bh[ni*2]);
                    mma16816(acc[mi][ni], ah[mi], &bl[ni*2]);
                    mma16816(acc[mi][ni], al[mi], &bh[ni*2]);
                }
        }
        __syncthreads();
    }

    #pragma unroll
    for (int mi = 0; mi < 2; mi++) {
        #pragma unroll
        for (int ni = 0; ni < 4; ni++) {
            int c = cb + wn + ni * 8 + qd * 2;
            int r0 = row0 + wm + mi * 16 + grp;
            #pragma unroll
            for (int h = 0; h < 2; h++) {
                int row = r0 + h * 8;
                float v0 = acc[mi][ni][h*2 + 0];
                float v1 = acc[mi][ni][h*2 + 1];
                if (!isZ) {
                    float2 o;
                    o.x = v0 + bxv[c];
                    o.y = v1 + bxv[c + 1];
                    *(float2*)&g_x[(size_t)row * E_ + c] = o;
                } else {
                    float zc, sl;
                    float2 o;
                    zc = v0 + bzv[c];     sl = zc / (1.f + __expf(-zc)); o.x = 1.f / (1.f + __expf(-sl));
                    zc = v1 + bzv[c + 1]; sl = zc / (1.f + __expf(-zc)); o.y = 1.f / (1.f + __expf(-sl));
                    *(float2*)&g_gate[(size_t)row * E_ + c] = o;
                }
            }
        }
    }
}

// ---------------- K2a: depthwise conv (both dirs), fp32 -> bf16 hi/lo ----------------
__global__ __launch_bounds__(384) void conv_kernel(
        const float* __restrict__ cwf, const float* __restrict__ cbf,
        const float* __restrict__ cwb, const float* __restrict__ cbb) {
    int tid = threadIdx.x;
    int rl  = tid / 96;
    int eq  = tid - rl * 96;
    int e   = eq * 4;
    int row = blockIdx.x * 4 + rl;
    int j   = row & (J_ - 1);
    int b   = row >> 10;

    const float* xr = g_x + (size_t)row * E_ + e;
    float4 x1 = *(const float4*)xr;
    float4 x0 = make_float4(0,0,0,0), x2 = make_float4(0,0,0,0);
    if (j > 0)      x0 = *(const float4*)(xr - E_);
    if (j < J_ - 1) x2 = *(const float4*)(xr + E_);

    float vf[4], vb[4];
    #pragma unroll
    for (int q = 0; q < 4; q++) {
        int ec = e + q;
        float a0 = (&x0.x)[q], a1 = (&x1.x)[q], a2 = (&x2.x)[q];
        vf[q] = cwf[ec*3]*a0 + cwf[ec*3+1]*a1 + cwf[ec*3+2]*a2 + cbf[ec];
        vb[q] = cwb[ec*3]*a2 + cwb[ec*3+1]*a1 + cwb[ec*3+2]*a0 + cbb[ec];
    }
    __nv_bfloat16 fh[4], fl[4], bh[4], bl[4];
    #pragma unroll
    for (int q = 0; q < 4; q++) {
        fh[q] = __float2bfloat16(vf[q]); fl[q] = __float2bfloat16(vf[q] - __bfloat162float(fh[q]));
        bh[q] = __float2bfloat16(vb[q]); bl[q] = __float2bfloat16(vb[q] - __bfloat162float(bh[q]));
    }
    size_t of = (size_t)row * E_ + e;
    size_t ob = (size_t)(b * J_ + (J_ - 1 - j)) * E_ + e;
    *(uint2*)&g_xch[0][of] = *(uint2*)fh;
    *(uint2*)&g_xcl[0][of] = *(uint2*)fl;
    *(uint2*)&g_xch[1][ob] = *(uint2*)bh;
    *(uint2*)&g_xcl[1][ob] = *(uint2*)bl;
}

// ---------------- K2b: proj MMA + ZOH epilogue (ldmatrix) ----------------
#define EPS 65
__global__ __launch_bounds__(256) void projmma_kernel(
        const float* __restrict__ bBf, const float* __restrict__ bCf,
        const float* __restrict__ bDf, const float* __restrict__ bBb,
        const float* __restrict__ bCb, const float* __restrict__ bDb,
        const float* __restrict__ A_log, const float* __restrict__ bi) {
    __shared__ __align__(16) char smraw[128*EPS*4];
    __nv_bfloat16* sAh = (__nv_bfloat16*)smraw;
    __nv_bfloat16* sAl = sAh + 128*SW;
    __nv_bfloat16* sBh = sAl + 128*SW;
    __nv_bfloat16* sBl = sBh + 64*SW;
    float* ep = (float*)smraw;
    __shared__ float sbias[4][N_];
    __shared__ float sAn[N_], sInv[N_];

    int tid  = threadIdx.x;
    int wid  = tid >> 5;
    int lane = tid & 31;
    int row0 = blockIdx.x * 128;
    int dir  = blockIdx.y;
    int b    = row0 >> 10;
    int s0   = row0 & (J_ - 1);
    int wm = (wid & 3) * 32;
    int wn = (wid >> 2) * 32;
    int grp  = lane >> 2;
    int qd   = lane & 3;
    uint32_t aAh = smem_u32(sAh), aAl = smem_u32(sAl);
    uint32_t aBh = smem_u32(sBh), aBl = smem_u32(sBl);

    if (tid < N_) {
        int n = tid;
        sbias[0][n] = dir ? bBb[n] : bBf[n];
        sbias[1][n] = dir ? bCb[n] : bCf[n];
        sbias[2][n] = dir ? bDb[n] : bDf[n];
        sbias[3][n] = bi[n];
        float al = A_log[n];
        float An = -log1pf(expf(al));
        sAn[n] = An;
        sInv[n] = 1.f / (An + 1e-6f);
    }

    const __nv_bfloat16* Ah = g_xch[dir];
    const __nv_bfloat16* Al = g_xcl[dir];
    const __nv_bfloat16* Bh = g_wph[dir];
    const __nv_bfloat16* Bl = g_wpl[dir];

    float acc[2][4][4];
    #pragma unroll
    for (int mi = 0; mi < 2; mi++)
        #pragma unroll
        for (int ni = 0; ni < 4; ni++)
            #pragma unroll
            for (int q = 0; q < 4; q++) acc[mi][ni][q] = 0.f;

    for (int kt = 0; kt < E_; kt += 32) {
        __syncthreads();
        #pragma unroll
        for (int i = 0; i < 2; i++) {
            int q = tid + i * 256;
            int r = q >> 2, kc = (q & 3) * 8;
            const size_t go = (size_t)(row0 + r) * E_ + kt + kc;
            *(uint4*)&sAh[r*SW + kc] = *(const uint4*)(Ah + go);
            *(uint4*)&sAl[r*SW + kc] = *(const uint4*)(Al + go);
        }
        {
            int r = tid >> 2, kc = (tid & 3) * 8;
            const size_t go = (size_t)r * E_ + kt + kc;
            *(uint4*)&sBh[r*SW + kc] = *(const uint4*)(Bh + go);
            *(uint4*)&sBl[r*SW + kc] = *(const uint4*)(Bl + go);
        }
        __syncthreads();

        #pragma unroll
        for (int ks = 0; ks < 2; ks++) {
            int k0 = ks * 16;
            uint32_t ah[2][4], al[2][4], bh[8], bl[8];
            #pragma unroll
            for (int mi = 0; mi < 2; mi++) {
                lda_frag(ah[mi], aAh, wm + mi*16, k0, lane);
                lda_frag(al[mi], aAl, wm + mi*16, k0, lane);
            }
            #pragma unroll
            for (int p = 0; p < 2; p++) {
                ldb_frag(&bh[p*4], aBh, wn + p*16, k0, lane);
                ldb_frag(&bl[p*4], aBl, wn + p*16, k0, lane);
            }
            #pragma unroll
            for (int mi = 0; mi < 2; mi++)
                #pragma unroll
                for (int ni = 0; ni < 4; ni++) {
                    mma16816(acc[mi][ni], ah[mi], &bh[ni*2]);
                    mma16816(acc[mi][ni], ah[mi], &bl[ni*2]);
                    mma16816(acc[mi][ni], al[mi], &bh[ni*2]);
                }
        }
    }
    __syncthreads();

    #pragma unroll
    for (int mi = 0; mi < 2; mi++)
        #pragma unroll
        for (int ni = 0; ni < 4; ni++) {
            int c = wn + ni * 8 + qd * 2;
            int r0 = wm + mi * 16 + grp;
            #pragma unroll
            for (int h = 0; h < 2; h++) {
                ep[(r0 + h*8)*EPS + c    ] = acc[mi][ni][h*2 + 0];
                ep[(r0 + h*8)*EPS + c + 1] = acc[mi][ni][h*2 + 1];
            }
        }
    __syncthreads();

    #pragma unroll
    for (int it = 0; it < 8; it++) {
        int idx = tid + it * 256;
        int s = idx & 127;
        int n = idx >> 7;
        float bt  = ep[s*EPS + n     ] + sbias[0][n];
        float ct  = ep[s*EPS + n + 16] + sbias[1][n];
        float dtr = ep[s*EPS + n + 32] + sbias[2][n];
        float u   = ep[s*EPS + n + 48] + sbias[3][n];
        float An  = sAn[n];
        float dt  = (dtr > 20.f) ? dtr : log1pf(__expf(dtr));
        float abar = __expf(dt * An);
        float bu = (abar - 1.f) * sInv[n] * bt * u;
        size_t base = (size_t)(b*N_ + n) * J_ + s0 + s;
        g_Abar[dir][base] = abar;
        g_Bu[dir][base]   = bu;
        g_Ct[dir][base]   = ct;
    }
}

// ---------------- K3: segmented warp scan ----------------
__global__ __launch_bounds__(512) void scan_kernel() {
    int b   = blockIdx.x;
    int dir = blockIdx.y;
    int w    = threadIdx.x >> 5;
    int lane = threadIdx.x & 31;
    size_t base = (size_t)(b*N_ + w) * J_;
    const float* Aa = g_Abar[dir] + base;
    const float* Bu = g_Bu[dir]   + base;
    const float* Ct = g_Ct[dir]   + base;
    float carry = 0.f;
    for (int seg = 0; seg < J_/32; seg++) {
        int s = seg*32 + lane;
        float a  = Aa[s];
        float bu = Bu[s];
        #pragma unroll
        for (int off = 1; off < 32; off <<= 1) {
            float ap = __shfl_up_sync(0xffffffffu, a,  off);
            float bp = __shfl_up_sync(0xffffffffu, bu, off);
            if (lane >= off) { bu = fmaf(a, bp, bu); a *= ap; }
        }
        float h = fmaf(a, carry, bu);
        carry = __shfl_sync(0xffffffffu, h, 31);
        float g = h * Ct[s];
        int jorig = dir ? (J_ - 1 - s) : s;
        g_g[dir][(size_t)(b*J_ + jorig) * N_ + w] = g;
    }
}

// ---------------- K4a: y = (gsum@Wr + 2br) * gate -> bf16 hi/lo (into g_xch[0]/g_xcl[0]) ----------------
__global__ __launch_bounds__(256) void y_kernel(const float* __restrict__ Wr,
                                                const float* __restrict__ br) {
    __shared__ float sWr[N_*E_];
    __shared__ float sbr[E_];
    __shared__ float gsm[8*N_];
    int tid = threadIdx.x;
    int row0 = blockIdx.x * 8;

    #pragma unroll
    for (int i = 0; i < 24; i++) sWr[tid + i*256] = Wr[tid + i*256];
    if (tid < 128) {
        sbr[tid]       = 2.f * br[tid];
        sbr[tid + 128] = 2.f * br[tid + 128];
        if (tid < 64)  sbr[tid + 256] = 2.f * br[tid + 256];
        else {
            int q = tid - 64;  // 0..63
            sbr[q + 320] = 2.f * br[q + 320];
        }
    }
    if (tid < 128) {
        int r = tid >> 4, n = tid & 15;
        size_t row = (size_t)(row0 + r);
        gsm[tid] = g_g[0][row*N_ + n] + g_g[1][row*N_ + n];
    }
    __syncthreads();

    #pragma unroll
    for (int i = 0; i < 12; i++) {
        int q = tid + i * 256;
        int r = q / E_, e = q - r * E_;
        const float* gv = &gsm[r*N_];
        float acc = sbr[e];
        #pragma unroll
        for (int nn = 0; nn < N_; nn++) acc += gv[nn] * sWr[nn*E_ + e];
        size_t row = (size_t)(row0 + r);
        float y = acc * g_gate[row*E_ + e];
        __nv_bfloat16 h = __float2bfloat16(y);
        g_xch[0][row*E_ + e] = h;
        g_xcl[0][row*E_ + e] = __float2bfloat16(y - __bfloat162float(h));
    }
}

// ---------------- K4b: out = tokens + y @ Wo + bo (HMMA + ldmatrix) ----------------
__global__ __launch_bounds__(256) void outmma_kernel(const float* __restrict__ tokens,
                                                     const float* __restrict__ bo,
                                                     float* __restrict__ out) {
    __shared__ __nv_bfloat16 sAh[128*SW];
    __shared__ __nv_bfloat16 sAl[128*SW];
    __shared__ __nv_bfloat16 sBh[64*SW];
    __shared__ __nv_bfloat16 sBl[64*SW];

    int tid  = threadIdx.x;
    int wid  = tid >> 5;
    int lane = tid & 31;
    int grp  = lane >> 2;
    int qd   = lane & 3;
    int row0 = blockIdx.x * 128;
    int cb   = blockIdx.y * 64;
    int wm = (wid & 3) * 32;
    int wn = (wid >> 2) * 32;
    uint32_t aAh = smem_u32(sAh), aAl = smem_u32(sAl);
    uint32_t aBh = smem_u32(sBh), aBl = smem_u32(sBl);

    float acc[2][4][4];
    #pragma unroll
    for (int mi = 0; mi < 2; mi++)
        #pragma unroll
        for (int ni = 0; ni < 4; ni++)
            #pragma unroll
            for (int q = 0; q < 4; q++) acc[mi][ni][q] = 0.f;

    for (int kt = 0; kt < E_; kt += 32) {
        #pragma unroll
        for (int i = 0; i < 2; i++) {
            int q = tid + i * 256;
            int r = q >> 2, kc = (q & 3) * 8;
            const size_t go = (size_t)(row0 + r) * E_ + kt + kc;
            *(uint4*)&sAh[r*SW + kc] = *(const uint4*)(g_xch[0] + go);
            *(uint4*)&sAl[r*SW + kc] = *(const uint4*)(g_xcl[0] + go);
        }
        {
            int r = tid >> 2, kc = (tid & 3) * 8;
            const size_t go = (size_t)(cb + r) * E_ + kt + kc;
            *(uint4*)&sBh[r*SW + kc] = *(const uint4*)(g_woh + go);
            *(uint4*)&sBl[r*SW + kc] = *(const uint4*)(g_wol + go);
        }
        __syncthreads();

        #pragma unroll
        for (int ks = 0; ks < 2; ks++) {
            int k0 = ks * 16;
            uint32_t ah[2][4], al[2][4], bh[8], bl[8];
            #pragma unroll
            for (int mi = 0; mi < 2; mi++) {
                lda_frag(ah[mi], aAh, wm + mi*16, k0, lane);
                lda_frag(al[mi], aAl, wm + mi*16, k0, lane);
            }
            #pragma unroll
            for (int p = 0; p < 2; p++) {
                ldb_frag(&bh[p*4], aBh, wn + p*16, k0, lane);
                ldb_frag(&bl[p*4], aBl, wn + p*16, k0, lane);
            }
            #pragma unroll
            for (int mi = 0; mi < 2; mi++)
                #pragma unroll
                for (int ni = 0; ni < 4; ni++) {
                    mma16816(acc[mi][ni], ah[mi], &bh[ni*2]);
                    mma16816(acc[mi][ni], ah[mi], &bl[ni*2]);
                    mma16816(acc[mi][ni], al[mi], &bh[ni*2]);
                }
        }
        __syncthreads();
    }

    #pragma unroll
    for (int mi = 0; mi < 2; mi++) {
        #pragma unroll
        for (int ni = 0; ni < 4; ni++) {
            int c = cb + wn + ni * 8 + qd * 2;
            int r0 = row0 + wm + mi * 16 + grp;
            float2 bov = *(const float2*)&bo[c];
            #pragma unroll
            for (int h = 0; h < 2; h++) {
                int row = r0 + h * 8;
                float2 tk = *(const float2*)&tokens[(size_t)row * D_ + c];
                float2 o;
                o.x = tk.x + acc[mi][ni][h*2 + 0] + bov.x;
                o.y = tk.y + acc[mi][ni][h*2 + 1] + bov.y;
                *(float2*)&out[(size_t)row * D_ + c] = o;
            }
        }
    }
}

// ---------------- launch ----------------
extern "C" void kernel_launch(void* const* d_in, const int* in_sizes, int n_in,
                              void* d_out, int out_size) {
    const float* tokens = (const float*)d_in[0];
    const float* norm_g = (const float*)d_in[1];
    const float* norm_b = (const float*)d_in[2];
    const float* Wx  = (const float*)d_in[3];
    const float* bx  = (const float*)d_in[4];
    const float* Wz  = (const float*)d_in[5];
    const float* bz  = (const float*)d_in[6];
    const float* cwf = (const float*)d_in[7];
    const float* cbf = (const float*)d_in[8];
    const float* cwb = (const float*)d_in[9];
    const float* cbb = (const float*)d_in[10];
    const float* WBf = (const float*)d_in[11];
    const float* bBf = (const float*)d_in[12];
    const float* WCf = (const float*)d_in[13];
    const float* bCf = (const float*)d_in[14];
    const float* WDf = (const float*)d_in[15];
    const float* bDf = (const float*)d_in[16];
    const float* WBb = (const float*)d_in[17];
    const float* bBb = (const float*)d_in[18];
    const float* WCb = (const float*)d_in[19];
    const float* bCb = (const float*)d_in[20];
    const float* WDb = (const float*)d_in[21];
    const float* bDb = (const float*)d_in[22];
    const float* A_log = (const float*)d_in[23];
    const float* Wi  = (const float*)d_in[24];
    const float* bi  = (const float*)d_in[25];
    const float* Wr  = (const float*)d_in[26];
    const float* br  = (const float*)d_in[27];
    const float* Wo  = (const float*)d_in[28];
    const float* bo  = (const float*)d_in[29];
    float* out = (float*)d_out;

    ln_kernel<<<BJ_/8, 256>>>(tokens, norm_g, norm_b);
    wprep_kernel<<<(768*D_ + 255)/256, 256>>>(Wx, Wz);
    wprep2_kernel<<<(2*64*E_ + 255)/256, 256>>>(WBf, WCf, WDf, WBb, WCb, WDb, Wi);
    wprep3_kernel<<<(192*E_ + 255)/256, 256>>>(Wo);
    gemm1_mma<<<dim3(BJ_/128, 12), 256>>>(bx, bz);
    conv_kernel<<<BJ_/4, 384>>>(cwf, cbf, cwb, cbb);
    projmma_kernel<<<dim3(BJ_/128, 2), 256>>>(bBf, bCf, bDf, bBb, bCb, bDb, A_log, bi);
    scan_kernel<<<dim3(B_, 2), 512>>>();
    y_kernel<<<BJ_/8, 256>>>(Wr, br);
    outmma_kernel<<<dim3(BJ_/128, 3), 256>>>(tokens, bo, out);
}

// round 6
// speedup vs baseline: 2.6011x; 1.0633x over previous
#include <cuda_runtime.h>
#include <cuda_bf16.h>
#include <math.h>
#include <stdint.h>

#define B_ 32
#define J_ 1024
#define D_ 192
#define E_ 384
#define N_ 16
#define BJ_ (B_*J_)

// ---------------- device scratch (no allocs allowed) ----------------
__device__ __nv_bfloat16 g_th[BJ_*D_];     // LN output hi (bf16)
__device__ __nv_bfloat16 g_tl[BJ_*D_];     // LN output lo (bf16)
__device__ __nv_bfloat16 g_wht[768*D_];    // [Wx|Wz] transposed hi: [col][k]
__device__ __nv_bfloat16 g_wlt[768*D_];    // [Wx|Wz] transposed lo
__device__ float g_x[BJ_*E_];              // x = t@Wx + bx
__device__ float g_gate[BJ_*E_];           // sigmoid(silu(z))
__device__ __nv_bfloat16 g_xch[2][BJ_*E_]; // conv output hi ([0] reused as y hi)
__device__ __nv_bfloat16 g_xcl[2][BJ_*E_]; // conv output lo ([0] reused as y lo)
__device__ __nv_bfloat16 g_wph[2][64*E_];  // [dir][col][k] packed [WB|WC|WD|Wi] hi
__device__ __nv_bfloat16 g_wpl[2][64*E_];  // lo
__device__ __nv_bfloat16 g_woh[192*E_];    // Wo transposed hi: [d][k]
__device__ __nv_bfloat16 g_wol[192*E_];    // lo
__device__ float g_Abar[2][B_*N_*J_];      // [dir][b][n][s]
__device__ float g_Bu  [2][B_*N_*J_];
__device__ float g_Ct  [2][B_*N_*J_];
__device__ float g_g   [2][BJ_*N_];        // hs*Ct at ORIGINAL j

// ---------------- helpers ----------------
#define SW 40   // smem row stride in bf16 (80B: conflict-free for ldmatrix phases)

__device__ __forceinline__ uint32_t smem_u32(const void* p) {
    return (uint32_t)__cvta_generic_to_shared(p);
}
__device__ __forceinline__ void cp16(void* dst_smem, const void* src) {
    uint32_t d = smem_u32(dst_smem);
    asm volatile("cp.async.ca.shared.global [%0], [%1], 16;" :: "r"(d), "l"(src));
}
#define CP_COMMIT() asm volatile("cp.async.commit_group;" ::: "memory")
#define CP_WAIT1()  asm volatile("cp.async.wait_group 1;" ::: "memory")
#define CP_WAIT0()  asm volatile("cp.async.wait_group 0;" ::: "memory")

__device__ __forceinline__ void ldsm_x4(uint32_t* r, uint32_t addr) {
    asm volatile("ldmatrix.sync.aligned.m8n8.x4.shared.b16 {%0,%1,%2,%3}, [%4];"
        : "=r"(r[0]), "=r"(r[1]), "=r"(r[2]), "=r"(r[3]) : "r"(addr));
}
__device__ __forceinline__ void lda_frag(uint32_t* a, uint32_t sbase, int rb, int k0, int lane) {
    uint32_t addr = sbase + (uint32_t)((rb + (lane & 15)) * (SW*2) + k0*2 + ((lane >> 4) << 4));
    ldsm_x4(a, addr);
}
__device__ __forceinline__ void ldb_frag(uint32_t* b, uint32_t sbase, int nb_pair, int k0, int lane) {
    int sub = lane >> 3;
    int row = nb_pair + ((sub >> 1) << 3) + (lane & 7);
    uint32_t addr = sbase + (uint32_t)(row * (SW*2) + (k0 + ((sub & 1) << 3)) * 2);
    ldsm_x4(b, addr);
}
__device__ __forceinline__ void mma16816(float* c, const uint32_t* a, const uint32_t* b) {
    asm volatile(
        "mma.sync.aligned.m16n8k16.row.col.f32.bf16.bf16.f32 "
        "{%0,%1,%2,%3}, {%4,%5,%6,%7}, {%8,%9}, {%0,%1,%2,%3};"
        : "+f"(c[0]), "+f"(c[1]), "+f"(c[2]), "+f"(c[3])
        : "r"(a[0]), "r"(a[1]), "r"(a[2]), "r"(a[3]), "r"(b[0]), "r"(b[1]));
}

// ---------------- K0: LayerNorm -> bf16 hi/lo ----------------
__global__ void ln_kernel(const float* __restrict__ tok,
                          const float* __restrict__ gamma,
                          const float* __restrict__ beta) {
    int row  = blockIdx.x * 8 + (threadIdx.x >> 5);
    int lane = threadIdx.x & 31;
    const float* tr = tok + (size_t)row * D_;
    float v[6];
    float s = 0.f;
    #pragma unroll
    for (int i = 0; i < 6; i++) { v[i] = tr[lane + 32*i]; s += v[i]; }
    #pragma unroll
    for (int o = 16; o > 0; o >>= 1) s += __shfl_xor_sync(0xffffffffu, s, o);
    float mu = s * (1.f / D_);
    float vs = 0.f;
    #pragma unroll
    for (int i = 0; i < 6; i++) { float d = v[i] - mu; vs += d * d; }
    #pragma unroll
    for (int o = 16; o > 0; o >>= 1) vs += __shfl_xor_sync(0xffffffffu, vs, o);
    float inv = rsqrtf(vs * (1.f / D_) + 1e-5f);
    #pragma unroll
    for (int i = 0; i < 6; i++) {
        int c = lane + 32*i;
        float t = (v[i] - mu) * inv * gamma[c] + beta[c];
        __nv_bfloat16 h = __float2bfloat16(t);
        g_th[(size_t)row * D_ + c] = h;
        g_tl[(size_t)row * D_ + c] = __float2bfloat16(t - __bfloat162float(h));
    }
}

// ---------------- K0b: merged weight prep ----------------
__global__ void wprep_all(
        const float* __restrict__ Wx, const float* __restrict__ Wz,
        const float* __restrict__ WBf, const float* __restrict__ WCf,
        const float* __restrict__ WDf, const float* __restrict__ WBb,
        const float* __restrict__ WCb, const float* __restrict__ WDb,
        const float* __restrict__ Wi,  const float* __restrict__ Wo) {
    int i = blockIdx.x * 256 + threadIdx.x;
    const int n1 = 768 * D_;
    const int n2 = n1 + 2 * 64 * E_;
    const int n3 = n2 + 192 * E_;
    if (i < n1) {
        int c = i / D_, k = i - c * D_;
        float w = (c < E_) ? Wx[(size_t)k * E_ + c] : Wz[(size_t)k * E_ + (c - E_)];
        __nv_bfloat16 h = __float2bfloat16(w);
        g_wht[i] = h;
        g_wlt[i] = __float2bfloat16(w - __bfloat162float(h));
    } else if (i < n2) {
        int q = i - n1;
        int dir = q / (64 * E_);
        int rem = q - dir * 64 * E_;
        int c = rem / E_, k = rem - c * E_;
        int m = c >> 4, n = c & 15;
        const float* W;
        if (m == 0) W = dir ? WBb : WBf;
        else if (m == 1) W = dir ? WCb : WCf;
        else if (m == 2) W = dir ? WDb : WDf;
        else W = Wi;
        float w = W[(size_t)k * N_ + n];
        __nv_bfloat16 h = __float2bfloat16(w);
        g_wph[dir][rem] = h;
        g_wpl[dir][rem] = __float2bfloat16(w - __bfloat162float(h));
    } else if (i < n3) {
        int q = i - n2;
        int d = q / E_, k = q - d * E_;
        float w = Wo[(size_t)k * D_ + d];
        __nv_bfloat16 h = __float2bfloat16(w);
        g_woh[q] = h;
        g_wol[q] = __float2bfloat16(w - __bfloat162float(h));
    }
}

// ---------------- K1: HMMA dual GEMM (cp.async double-buffer) ----------------
__global__ __launch_bounds__(256) void gemm1_mma(const float* __restrict__ bxv,
                                                 const float* __restrict__ bzv) {
    extern __shared__ char dynsm[];
    __nv_bfloat16* sAh = (__nv_bfloat16*)dynsm;      // [2][128*SW]
    __nv_bfloat16* sAl = sAh + 2*128*SW;
    __nv_bfloat16* sBh = sAl + 2*128*SW;             // [2][64*SW]
    __nv_bfloat16* sBl = sBh + 2*64*SW;

    int tid  = threadIdx.x;
    int wid  = tid >> 5;
    int lane = tid & 31;
    int grp  = lane >> 2;
    int qd   = lane & 3;
    int row0 = blockIdx.x * 128;
    int yb   = blockIdx.y;
    int isZ  = (yb >= 6);
    int cb   = (isZ ? yb - 6 : yb) * 64;
    int csrc = cb + (isZ ? E_ : 0);
    int wm = (wid & 3) * 32;
    int wn = (wid >> 2) * 32;
    uint32_t aAh = smem_u32(sAh), aAl = smem_u32(sAl);
    uint32_t aBh = smem_u32(sBh), aBl = smem_u32(sBl);

    float acc[2][4][4];
    #pragma unroll
    for (int mi = 0; mi < 2; mi++)
        #pragma unroll
        for (int ni = 0; ni < 4; ni++)
            #pragma unroll
            for (int q = 0; q < 4; q++) acc[mi][ni][q] = 0.f;

    auto stage = [&](int p, int kt) {
        #pragma unroll
        for (int i = 0; i < 2; i++) {
            int q = tid + i * 256;
            int r = q >> 2, kc = (q & 3) * 8;
            const size_t go = (size_t)(row0 + r) * D_ + kt + kc;
            cp16(&sAh[p*128*SW + r*SW + kc], g_th + go);
            cp16(&sAl[p*128*SW + r*SW + kc], g_tl + go);
        }
        int r = tid >> 2, kc = (tid & 3) * 8;
        const size_t go = (size_t)(csrc + r) * D_ + kt + kc;
        cp16(&sBh[p*64*SW + r*SW + kc], g_wht + go);
        cp16(&sBl[p*64*SW + r*SW + kc], g_wlt + go);
    };

    stage(0, 0); CP_COMMIT();
    for (int it = 0; it < 6; it++) {
        int p = it & 1;
        if (it < 5) { stage(p ^ 1, (it + 1) * 32); CP_COMMIT(); CP_WAIT1(); }
        else CP_WAIT0();
        __syncthreads();
        uint32_t bAh = aAh + p*128*SW*2, bAl = aAl + p*128*SW*2;
        uint32_t bBh = aBh + p*64*SW*2,  bBl = aBl + p*64*SW*2;
        #pragma unroll
        for (int ks = 0; ks < 2; ks++) {
            int k0 = ks * 16;
            uint32_t ah[2][4], al[2][4], bh[8], bl[8];
            #pragma unroll
            for (int mi = 0; mi < 2; mi++) {
                lda_frag(ah[mi], bAh, wm + mi*16, k0, lane);
                lda_frag(al[mi], bAl, wm + mi*16, k0, lane);
            }
            #pragma unroll
            for (int pp = 0; pp < 2; pp++) {
                ldb_frag(&bh[pp*4], bBh, wn + pp*16, k0, lane);
                ldb_frag(&bl[pp*4], bBl, wn + pp*16, k0, lane);
            }
            #pragma unroll
            for (int mi = 0; mi < 2; mi++)
                #pragma unroll
                for (int ni = 0; ni < 4; ni++) {
                    mma16816(acc[mi][ni], ah[mi], &bh[ni*2]);
                    mma16816(acc[mi][ni], ah[mi], &bl[ni*2]);
                    mma16816(acc[mi][ni], al[mi], &bh[ni*2]);
                }
        }
        __syncthreads();
    }

    #pragma unroll
    for (int mi = 0; mi < 2; mi++) {
        #pragma unroll
        for (int ni = 0; ni < 4; ni++) {
            int c = cb + wn + ni * 8 + qd * 2;
            int r0 = row0 + wm + mi * 16 + grp;
            #pragma unroll
            for (int h = 0; h < 2; h++) {
                int row = r0 + h * 8;
                float v0 = acc[mi][ni][h*2 + 0];
                float v1 = acc[mi][ni][h*2 + 1];
                if (!isZ) {
                    float2 o;
                    o.x = v0 + bxv[c];
                    o.y = v1 + bxv[c + 1];
                    *(float2*)&g_x[(size_t)row * E_ + c] = o;
                } else {
                    float zc, sl;
                    float2 o;
                    zc = v0 + bzv[c];     sl = zc / (1.f + __expf(-zc)); o.x = 1.f / (1.f + __expf(-sl));
                    zc = v1 + bzv[c + 1]; sl = zc / (1.f + __expf(-zc)); o.y = 1.f / (1.f + __expf(-sl));
                    *(float2*)&g_gate[(size_t)row * E_ + c] = o;
                }
            }
        }
    }
}

// ---------------- K2a: depthwise conv (both dirs), fp32 -> bf16 hi/lo ----------------
__global__ __launch_bounds__(384) void conv_kernel(
        const float* __restrict__ cwf, const float* __restrict__ cbf,
        const float* __restrict__ cwb, const float* __restrict__ cbb) {
    int tid = threadIdx.x;
    int rl  = tid / 96;
    int eq  = tid - rl * 96;
    int e   = eq * 4;
    int row = blockIdx.x * 4 + rl;
    int j   = row & (J_ - 1);
    int b   = row >> 10;

    const float* xr = g_x + (size_t)row * E_ + e;
    float4 x1 = *(const float4*)xr;
    float4 x0 = make_float4(0,0,0,0), x2 = make_float4(0,0,0,0);
    if (j > 0)      x0 = *(const float4*)(xr - E_);
    if (j < J_ - 1) x2 = *(const float4*)(xr + E_);

    float vf[4], vb[4];
    #pragma unroll
    for (int q = 0; q < 4; q++) {
        int ec = e + q;
        float a0 = (&x0.x)[q], a1 = (&x1.x)[q], a2 = (&x2.x)[q];
        vf[q] = cwf[ec*3]*a0 + cwf[ec*3+1]*a1 + cwf[ec*3+2]*a2 + cbf[ec];
        vb[q] = cwb[ec*3]*a2 + cwb[ec*3+1]*a1 + cwb[ec*3+2]*a0 + cbb[ec];
    }
    __nv_bfloat16 fh[4], fl[4], bh[4], bl[4];
    #pragma unroll
    for (int q = 0; q < 4; q++) {
        fh[q] = __float2bfloat16(vf[q]); fl[q] = __float2bfloat16(vf[q] - __bfloat162float(fh[q]));
        bh[q] = __float2bfloat16(vb[q]); bl[q] = __float2bfloat16(vb[q] - __bfloat162float(bh[q]));
    }
    size_t of = (size_t)row * E_ + e;
    size_t ob = (size_t)(b * J_ + (J_ - 1 - j)) * E_ + e;
    *(uint2*)&g_xch[0][of] = *(uint2*)fh;
    *(uint2*)&g_xcl[0][of] = *(uint2*)fl;
    *(uint2*)&g_xch[1][ob] = *(uint2*)bh;
    *(uint2*)&g_xcl[1][ob] = *(uint2*)bl;
}

// ---------------- K2b: proj MMA + ZOH epilogue (cp.async double-buffer) ----------------
#define EPS 65
__global__ __launch_bounds__(256) void projmma_kernel(
        const float* __restrict__ bBf, const float* __restrict__ bCf,
        const float* __restrict__ bDf, const float* __restrict__ bBb,
        const float* __restrict__ bCb, const float* __restrict__ bDb,
        const float* __restrict__ A_log, const float* __restrict__ bi) {
    extern __shared__ char dynsm[];
    __nv_bfloat16* sAh = (__nv_bfloat16*)dynsm;
    __nv_bfloat16* sAl = sAh + 2*128*SW;
    __nv_bfloat16* sBh = sAl + 2*128*SW;
    __nv_bfloat16* sBl = sBh + 2*64*SW;
    float* ep = (float*)dynsm;                 // epilogue overlay (33280 B)
    __shared__ float sbias[4][N_];
    __shared__ float sAn[N_], sInv[N_];

    int tid  = threadIdx.x;
    int wid  = tid >> 5;
    int lane = tid & 31;
    int row0 = blockIdx.x * 128;
    int dir  = blockIdx.y;
    int b    = row0 >> 10;
    int s0   = row0 & (J_ - 1);
    int wm = (wid & 3) * 32;
    int wn = (wid >> 2) * 32;
    int grp  = lane >> 2;
    int qd   = lane & 3;
    uint32_t aAh = smem_u32(sAh), aAl = smem_u32(sAl);
    uint32_t aBh = smem_u32(sBh), aBl = smem_u32(sBl);

    if (tid < N_) {
        int n = tid;
        sbias[0][n] = dir ? bBb[n] : bBf[n];
        sbias[1][n] = dir ? bCb[n] : bCf[n];
        sbias[2][n] = dir ? bDb[n] : bDf[n];
        sbias[3][n] = bi[n];
        float al = A_log[n];
        float An = -log1pf(expf(al));
        sAn[n] = An;
        sInv[n] = 1.f / (An + 1e-6f);
    }

    const __nv_bfloat16* Ah = g_xch[dir];
    const __nv_bfloat16* Al = g_xcl[dir];
    const __nv_bfloat16* Bh = g_wph[dir];
    const __nv_bfloat16* Bl = g_wpl[dir];

    float acc[2][4][4];
    #pragma unroll
    for (int mi = 0; mi < 2; mi++)
        #pragma unroll
        for (int ni = 0; ni < 4; ni++)
            #pragma unroll
            for (int q = 0; q < 4; q++) acc[mi][ni][q] = 0.f;

    auto stage = [&](int p, int kt) {
        #pragma unroll
        for (int i = 0; i < 2; i++) {
            int q = tid + i * 256;
            int r = q >> 2, kc = (q & 3) * 8;
            const size_t go = (size_t)(row0 + r) * E_ + kt + kc;
            cp16(&sAh[p*128*SW + r*SW + kc], Ah + go);
            cp16(&sAl[p*128*SW + r*SW + kc], Al + go);
        }
        int r = tid >> 2, kc = (tid & 3) * 8;
        const size_t go = (size_t)r * E_ + kt + kc;
        cp16(&sBh[p*64*SW + r*SW + kc], Bh + go);
        cp16(&sBl[p*64*SW + r*SW + kc], Bl + go);
    };

    stage(0, 0); CP_COMMIT();
    for (int it = 0; it < 12; it++) {
        int p = it & 1;
        if (it < 11) { stage(p ^ 1, (it + 1) * 32); CP_COMMIT(); CP_WAIT1(); }
        else CP_WAIT0();
        __syncthreads();
        uint32_t bAhp = aAh + p*128*SW*2, bAlp = aAl + p*128*SW*2;
        uint32_t bBhp = aBh + p*64*SW*2,  bBlp = aBl + p*64*SW*2;
        #pragma unroll
        for (int ks = 0; ks < 2; ks++) {
            int k0 = ks * 16;
            uint32_t ah[2][4], al[2][4], bh[8], bl[8];
            #pragma unroll
            for (int mi = 0; mi < 2; mi++) {
                lda_frag(ah[mi], bAhp, wm + mi*16, k0, lane);
                lda_frag(al[mi], bAlp, wm + mi*16, k0, lane);
            }
            #pragma unroll
            for (int pp = 0; pp < 2; pp++) {
                ldb_frag(&bh[pp*4], bBhp, wn + pp*16, k0, lane);
                ldb_frag(&bl[pp*4], bBlp, wn + pp*16, k0, lane);
            }
            #pragma unroll
            for (int mi = 0; mi < 2; mi++)
                #pragma unroll
                for (int ni = 0; ni < 4; ni++) {
                    mma16816(acc[mi][ni], ah[mi], &bh[ni*2]);
                    mma16816(acc[mi][ni], ah[mi], &bl[ni*2]);
                    mma16816(acc[mi][ni], al[mi], &bh[ni*2]);
                }
        }
        __syncthreads();
    }

    #pragma unroll
    for (int mi = 0; mi < 2; mi++)
        #pragma unroll
        for (int ni = 0; ni < 4; ni++) {
            int c = wn + ni * 8 + qd * 2;
            int r0 = wm + mi * 16 + grp;
            #pragma unroll
            for (int h = 0; h < 2; h++) {
                ep[(r0 + h*8)*EPS + c    ] = acc[mi][ni][h*2 + 0];
                ep[(r0 + h*8)*EPS + c + 1] = acc[mi][ni][h*2 + 1];
            }
        }
    __syncthreads();

    #pragma unroll
    for (int it = 0; it < 8; it++) {
        int idx = tid + it * 256;
        int s = idx & 127;
        int n = idx >> 7;
        float bt  = ep[s*EPS + n     ] + sbias[0][n];
        float ct  = ep[s*EPS + n + 16] + sbias[1][n];
        float dtr = ep[s*EPS + n + 32] + sbias[2][n];
        float u   = ep[s*EPS + n + 48] + sbias[3][n];
        float An  = sAn[n];
        float dt  = (dtr > 20.f) ? dtr : log1pf(__expf(dtr));
        float abar = __expf(dt * An);
        float bu = (abar - 1.f) * sInv[n] * bt * u;
        size_t base = (size_t)(b*N_ + n) * J_ + s0 + s;
        g_Abar[dir][base] = abar;
        g_Bu[dir][base]   = bu;
        g_Ct[dir][base]   = ct;
    }
}

// ---------------- K3: blocked segmented scan (8 elems/lane) ----------------
__global__ __launch_bounds__(512) void scan_kernel() {
    int b   = blockIdx.x;
    int dir = blockIdx.y;
    int w    = threadIdx.x >> 5;
    int lane = threadIdx.x & 31;
    size_t base = (size_t)(b*N_ + w) * J_;
    const float* Aa = g_Abar[dir] + base;
    const float* Bu = g_Bu[dir]   + base;
    const float* Ct = g_Ct[dir]   + base;
    float carry = 0.f;
    #pragma unroll
    for (int seg = 0; seg < 4; seg++) {
        int s = seg*256 + lane*8;
        float a[8], bu[8];
        *(float4*)&a[0]  = *(const float4*)(Aa + s);
        *(float4*)&a[4]  = *(const float4*)(Aa + s + 4);
        *(float4*)&bu[0] = *(const float4*)(Bu + s);
        *(float4*)&bu[4] = *(const float4*)(Bu + s + 4);
        #pragma unroll
        for (int i = 1; i < 8; i++) { bu[i] = fmaf(a[i], bu[i-1], bu[i]); a[i] *= a[i-1]; }
        float As = a[7], Bs = bu[7];
        #pragma unroll
        for (int off = 1; off < 32; off <<= 1) {
            float ap = __shfl_up_sync(0xffffffffu, As, off);
            float bp = __shfl_up_sync(0xffffffffu, Bs, off);
            if (lane >= off) { Bs = fmaf(As, bp, Bs); As *= ap; }
        }
        float Ae = __shfl_up_sync(0xffffffffu, As, 1);
        float Be = __shfl_up_sync(0xffffffffu, Bs, 1);
        float Hprev = (lane == 0) ? carry : fmaf(Ae, carry, Be);
        float ct[8];
        *(float4*)&ct[0] = *(const float4*)(Ct + s);
        *(float4*)&ct[4] = *(const float4*)(Ct + s + 4);
        float hlast = 0.f;
        #pragma unroll
        for (int i = 0; i < 8; i++) {
            float h = fmaf(a[i], Hprev, bu[i]);
            if (i == 7) hlast = h;
            int sg = s + i;
            int jorig = dir ? (J_ - 1 - sg) : sg;
            g_g[dir][(size_t)(b*J_ + jorig) * N_ + w] = h * ct[i];
        }
        carry = __shfl_sync(0xffffffffu, hlast, 31);
    }
}

// ---------------- K4a: y = (gsum@Wr + 2br) * gate -> bf16 hi/lo ----------------
__global__ __launch_bounds__(256) void y_kernel(const float* __restrict__ Wr,
                                                const float* __restrict__ br) {
    __shared__ float sWr[N_*E_];
    __shared__ float sbr[E_];
    __shared__ float gsm[8*N_];
    int tid = threadIdx.x;
    int row0 = blockIdx.x * 8;

    #pragma unroll
    for (int i = 0; i < 24; i++) sWr[tid + i*256] = Wr[tid + i*256];
    if (tid < 128) {
        sbr[tid]       = 2.f * br[tid];
        sbr[tid + 128] = 2.f * br[tid + 128];
        if (tid < 64)  sbr[tid + 256] = 2.f * br[tid + 256];
        else           sbr[(tid - 64) + 320] = 2.f * br[(tid - 64) + 320];
    }
    if (tid < 128) {
        int r = tid >> 4, n = tid & 15;
        size_t row = (size_t)(row0 + r);
        gsm[tid] = g_g[0][row*N_ + n] + g_g[1][row*N_ + n];
    }
    __syncthreads();

    #pragma unroll
    for (int i = 0; i < 12; i++) {
        int q = tid + i * 256;
        int r = q / E_, e = q - r * E_;
        const float* gv = &gsm[r*N_];
        float acc = sbr[e];
        #pragma unroll
        for (int nn = 0; nn < N_; nn++) acc += gv[nn] * sWr[nn*E_ + e];
        size_t row = (size_t)(row0 + r);
        float y = acc * g_gate[row*E_ + e];
        __nv_bfloat16 h = __float2bfloat16(y);
        g_xch[0][row*E_ + e] = h;
        g_xcl[0][row*E_ + e] = __float2bfloat16(y - __bfloat162float(h));
    }
}

// ---------------- K4b: out = tokens + y @ Wo + bo (cp.async double-buffer) ----------------
__global__ __launch_bounds__(256) void outmma_kernel(const float* __restrict__ tokens,
                                                     const float* __restrict__ bo,
                                                     float* __restrict__ out) {
    extern __shared__ char dynsm[];
    __nv_bfloat16* sAh = (__nv_bfloat16*)dynsm;
    __nv_bfloat16* sAl = sAh + 2*128*SW;
    __nv_bfloat16* sBh = sAl + 2*128*SW;
    __nv_bfloat16* sBl = sBh + 2*64*SW;

    int tid  = threadIdx.x;
    int wid  = tid >> 5;
    int lane = tid & 31;
    int grp  = lane >> 2;
    int qd   = lane & 3;
    int row0 = blockIdx.x * 128;
    int cb   = blockIdx.y * 64;
    int wm = (wid & 3) * 32;
    int wn = (wid >> 2) * 32;
    uint32_t aAh = smem_u32(sAh), aAl = smem_u32(sAl);
    uint32_t aBh = smem_u32(sBh), aBl = smem_u32(sBl);

    float acc[2][4][4];
    #pragma unroll
    for (int mi = 0; mi < 2; mi++)
        #pragma unroll
        for (int ni = 0; ni < 4; ni++)
            #pragma unroll
            for (int q = 0; q < 4; q++) acc[mi][ni][q] = 0.f;

    auto stage = [&](int p, int kt) {
        #pragma unroll
        for (int i = 0; i < 2; i++) {
            int q = tid + i * 256;
            int r = q >> 2, kc = (q & 3) * 8;
            const size_t go = (size_t)(row0 + r) * E_ + kt + kc;
            cp16(&sAh[p*128*SW + r*SW + kc], g_xch[0] + go);
            cp16(&sAl[p*128*SW + r*SW + kc], g_xcl[0] + go);
        }
        int r = tid >> 2, kc = (tid & 3) * 8;
        const size_t go = (size_t)(cb + r) * E_ + kt + kc;
        cp16(&sBh[p*64*SW + r*SW + kc], g_woh + go);
        cp16(&sBl[p*64*SW + r*SW + kc], g_wol + go);
    };

    stage(0, 0); CP_COMMIT();
    for (int it = 0; it < 12; it++) {
        int p = it & 1;
        if (it < 11) { stage(p ^ 1, (it + 1) * 32); CP_COMMIT(); CP_WAIT1(); }
        else CP_WAIT0();
        __syncthreads();
        uint32_t bAhp = aAh + p*128*SW*2, bAlp = aAl + p*128*SW*2;
        uint32_t bBhp = aBh + p*64*SW*2,  bBlp = aBl + p*64*SW*2;
        #pragma unroll
        for (int ks = 0; ks < 2; ks++) {
            int k0 = ks * 16;
            uint32_t ah[2][4], al[2][4], bh[8], bl[8];
            #pragma unroll
            for (int mi = 0; mi < 2; mi++) {
                lda_frag(ah[mi], bAhp, wm + mi*16, k0, lane);
                lda_frag(al[mi], bAlp, wm + mi*16, k0, lane);
            }
            #pragma unroll
            for (int pp = 0; pp < 2; pp++) {
                ldb_frag(&bh[pp*4], bBhp, wn + pp*16, k0, lane);
                ldb_frag(&bl[pp*4], bBlp, wn + pp*16, k0, lane);
            }
            #pragma unroll
            for (int mi = 0; mi < 2; mi++)
                #pragma unroll
                for (int ni = 0; ni < 4; ni++) {
                    mma16816(acc[mi][ni], ah[mi], &bh[ni*2]);
                    mma16816(acc[mi][ni], ah[mi], &bl[ni*2]);
                    mma16816(acc[mi][ni], al[mi], &bh[ni*2]);
                }
        }
        __syncthreads();
    }

    #pragma unroll
    for (int mi = 0; mi < 2; mi++) {
        #pragma unroll
        for (int ni = 0; ni < 4; ni++) {
            int c = cb + wn + ni * 8 + qd * 2;
            int r0 = row0 + wm + mi * 16 + grp;
            float2 bov = *(const float2*)&bo[c];
            #pragma unroll
            for (int h = 0; h < 2; h++) {
                int row = r0 + h * 8;
                float2 tk = *(const float2*)&tokens[(size_t)row * D_ + c];
                float2 o;
                o.x = tk.x + acc[mi][ni][h*2 + 0] + bov.x;
                o.y = tk.y + acc[mi][ni][h*2 + 1] + bov.y;
                *(float2*)&out[(size_t)row * D_ + c] = o;
            }
        }
    }
}

// ---------------- launch ----------------
#define DYN_SMEM 61440

extern "C" void kernel_launch(void* const* d_in, const int* in_sizes, int n_in,
                              void* d_out, int out_size) {
    const float* tokens = (const float*)d_in[0];
    const float* norm_g = (const float*)d_in[1];
    const float* norm_b = (const float*)d_in[2];
    const float* Wx  = (const float*)d_in[3];
    const float* bx  = (const float*)d_in[4];
    const float* Wz  = (const float*)d_in[5];
    const float* bz  = (const float*)d_in[6];
    const float* cwf = (const float*)d_in[7];
    const float* cbf = (const float*)d_in[8];
    const float* cwb = (const float*)d_in[9];
    const float* cbb = (const float*)d_in[10];
    const float* WBf = (const float*)d_in[11];
    const float* bBf = (const float*)d_in[12];
    const float* WCf = (const float*)d_in[13];
    const float* bCf = (const float*)d_in[14];
    const float* WDf = (const float*)d_in[15];
    const float* bDf = (const float*)d_in[16];
    const float* WBb = (const float*)d_in[17];
    const float* bBb = (const float*)d_in[18];
    const float* WCb = (const float*)d_in[19];
    const float* bCb = (const float*)d_in[20];
    const float* WDb = (const float*)d_in[21];
    const float* bDb = (const float*)d_in[22];
    const float* A_log = (const float*)d_in[23];
    const float* Wi  = (const float*)d_in[24];
    const float* bi  = (const float*)d_in[25];
    const float* Wr  = (const float*)d_in[26];
    const float* br  = (const float*)d_in[27];
    const float* Wo  = (const float*)d_in[28];
    const float* bo  = (const float*)d_in[29];
    float* out = (float*)d_out;

    cudaFuncSetAttribute(gemm1_mma,      cudaFuncAttributeMaxDynamicSharedMemorySize, DYN_SMEM);
    cudaFuncSetAttribute(projmma_kernel, cudaFuncAttributeMaxDynamicSharedMemorySize, DYN_SMEM);
    cudaFuncSetAttribute(outmma_kernel,  cudaFuncAttributeMaxDynamicSharedMemorySize, DYN_SMEM);

    ln_kernel<<<BJ_/8, 256>>>(tokens, norm_g, norm_b);
    wprep_all<<<1056, 256>>>(Wx, Wz, WBf, WCf, WDf, WBb, WCb, WDb, Wi, Wo);
    gemm1_mma<<<dim3(BJ_/128, 12), 256, DYN_SMEM>>>(bx, bz);
    conv_kernel<<<BJ_/4, 384>>>(cwf, cbf, cwb, cbb);
    projmma_kernel<<<dim3(BJ_/128, 2), 256, DYN_SMEM>>>(bBf, bCf, bDf, bBb, bCb, bDb, A_log, bi);
    scan_kernel<<<dim3(B_, 2), 512>>>();
    y_kernel<<<BJ_/8, 256>>>(Wr, br);
    outmma_kernel<<<dim3(BJ_/128, 3), 256, DYN_SMEM>>>(tokens, bo, out);
}

// round 8
// speedup vs baseline: 2.6716x; 1.0271x over previous
#include <cuda_runtime.h>
#include <cuda_bf16.h>
#include <math.h>
#include <stdint.h>

#define B_ 32
#define J_ 1024
#define D_ 192
#define E_ 384
#define N_ 16
#define BJ_ (B_*J_)

// ---------------- device scratch (no allocs allowed) ----------------
__device__ __nv_bfloat16 g_th[BJ_*D_];     // LN output hi (bf16)
__device__ __nv_bfloat16 g_tl[BJ_*D_];     // LN output lo (bf16)
__device__ __nv_bfloat16 g_wht[768*D_];    // [Wx|Wz] transposed hi: [col][k]
__device__ __nv_bfloat16 g_wlt[768*D_];    // [Wx|Wz] transposed lo
__device__ float g_x[BJ_*E_];              // x = t@Wx + bx
__device__ float g_gate[BJ_*E_];           // sigmoid(silu(z))
__device__ __nv_bfloat16 g_xch[2][BJ_*E_]; // conv output hi ([0] reused as y hi)
__device__ __nv_bfloat16 g_xcl[2][BJ_*E_]; // conv output lo ([0] reused as y lo)
__device__ __nv_bfloat16 g_wph[2][64*E_];  // [dir][col][k] packed [WB|WC|WD|Wi] hi
__device__ __nv_bfloat16 g_wpl[2][64*E_];  // lo
__device__ __nv_bfloat16 g_woh[192*E_];    // Wo transposed hi: [d][k]
__device__ __nv_bfloat16 g_wol[192*E_];    // lo
__device__ float g_Abar[2][B_*N_*J_];      // [dir][b][n][s]
__device__ float g_Bu  [2][B_*N_*J_];
__device__ float g_Ct  [2][B_*N_*J_];
__device__ float g_g   [2][BJ_*N_];        // hs*Ct at ORIGINAL j

// ---------------- helpers ----------------
#define SW 40   // smem row stride in bf16 (80B: conflict-free for ldmatrix phases)

__device__ __forceinline__ uint32_t smem_u32(const void* p) {
    return (uint32_t)__cvta_generic_to_shared(p);
}
__device__ __forceinline__ void cp16(void* dst_smem, const void* src) {
    uint32_t d = smem_u32(dst_smem);
    asm volatile("cp.async.ca.shared.global [%0], [%1], 16;" :: "r"(d), "l"(src));
}
#define CP_COMMIT() asm volatile("cp.async.commit_group;" ::: "memory")
#define CP_WAIT1()  asm volatile("cp.async.wait_group 1;" ::: "memory")
#define CP_WAIT0()  asm volatile("cp.async.wait_group 0;" ::: "memory")

__device__ __forceinline__ void ldsm_x4(uint32_t* r, uint32_t addr) {
    asm volatile("ldmatrix.sync.aligned.m8n8.x4.shared.b16 {%0,%1,%2,%3}, [%4];"
        : "=r"(r[0]), "=r"(r[1]), "=r"(r[2]), "=r"(r[3]) : "r"(addr));
}
__device__ __forceinline__ void lda_frag(uint32_t* a, uint32_t sbase, int rb, int k0, int lane) {
    uint32_t addr = sbase + (uint32_t)((rb + (lane & 15)) * (SW*2) + k0*2 + ((lane >> 4) << 4));
    ldsm_x4(a, addr);
}
__device__ __forceinline__ void ldb_frag(uint32_t* b, uint32_t sbase, int nb_pair, int k0, int lane) {
    int sub = lane >> 3;
    int row = nb_pair + ((sub >> 1) << 3) + (lane & 7);
    uint32_t addr = sbase + (uint32_t)(row * (SW*2) + (k0 + ((sub & 1) << 3)) * 2);
    ldsm_x4(b, addr);
}
__device__ __forceinline__ void mma16816(float* c, const uint32_t* a, const uint32_t* b) {
    asm volatile(
        "mma.sync.aligned.m16n8k16.row.col.f32.bf16.bf16.f32 "
        "{%0,%1,%2,%3}, {%4,%5,%6,%7}, {%8,%9}, {%0,%1,%2,%3};"
        : "+f"(c[0]), "+f"(c[1]), "+f"(c[2]), "+f"(c[3])
        : "r"(a[0]), "r"(a[1]), "r"(a[2]), "r"(a[3]), "r"(b[0]), "r"(b[1]));
}

// ---------------- K0: LayerNorm -> bf16 hi/lo ----------------
__global__ void ln_kernel(const float* __restrict__ tok,
                          const float* __restrict__ gamma,
                          const float* __restrict__ beta) {
    int row  = blockIdx.x * 8 + (threadIdx.x >> 5);
    int lane = threadIdx.x & 31;
    const float* tr = tok + (size_t)row * D_;
    float v[6];
    float s = 0.f;
    #pragma unroll
    for (int i = 0; i < 6; i++) { v[i] = tr[lane + 32*i]; s += v[i]; }
    #pragma unroll
    for (int o = 16; o > 0; o >>= 1) s += __shfl_xor_sync(0xffffffffu, s, o);
    float mu = s * (1.f / D_);
    float vs = 0.f;
    #pragma unroll
    for (int i = 0; i < 6; i++) { float d = v[i] - mu; vs += d * d; }
    #pragma unroll
    for (int o = 16; o > 0; o >>= 1) vs += __shfl_xor_sync(0xffffffffu, vs, o);
    float inv = rsqrtf(vs * (1.f / D_) + 1e-5f);
    #pragma unroll
    for (int i = 0; i < 6; i++) {
        int c = lane + 32*i;
        float t = (v[i] - mu) * inv * gamma[c] + beta[c];
        __nv_bfloat16 h = __float2bfloat16(t);
        g_th[(size_t)row * D_ + c] = h;
        g_tl[(size_t)row * D_ + c] = __float2bfloat16(t - __bfloat162float(h));
    }
}

// ---------------- K0b: merged weight prep ----------------
__global__ void wprep_all(
        const float* __restrict__ Wx, const float* __restrict__ Wz,
        const float* __restrict__ WBf, const float* __restrict__ WCf,
        const float* __restrict__ WDf, const float* __restrict__ WBb,
        const float* __restrict__ WCb, const float* __restrict__ WDb,
        const float* __restrict__ Wi,  const float* __restrict__ Wo) {
    int i = blockIdx.x * 256 + threadIdx.x;
    const int n1 = 768 * D_;
    const int n2 = n1 + 2 * 64 * E_;
    const int n3 = n2 + 192 * E_;
    if (i < n1) {
        int c = i / D_, k = i - c * D_;
        float w = (c < E_) ? Wx[(size_t)k * E_ + c] : Wz[(size_t)k * E_ + (c - E_)];
        __nv_bfloat16 h = __float2bfloat16(w);
        g_wht[i] = h;
        g_wlt[i] = __float2bfloat16(w - __bfloat162float(h));
    } else if (i < n2) {
        int q = i - n1;
        int dir = q / (64 * E_);
        int rem = q - dir * 64 * E_;
        int c = rem / E_, k = rem - c * E_;
        int m = c >> 4, n = c & 15;
        const float* W;
        if (m == 0) W = dir ? WBb : WBf;
        else if (m == 1) W = dir ? WCb : WCf;
        else if (m == 2) W = dir ? WDb : WDf;
        else W = Wi;
        float w = W[(size_t)k * N_ + n];
        __nv_bfloat16 h = __float2bfloat16(w);
        g_wph[dir][rem] = h;
        g_wpl[dir][rem] = __float2bfloat16(w - __bfloat162float(h));
    } else if (i < n3) {
        int q = i - n2;
        int d = q / E_, k = q - d * E_;
        float w = Wo[(size_t)k * D_ + d];
        __nv_bfloat16 h = __float2bfloat16(w);
        g_woh[q] = h;
        g_wol[q] = __float2bfloat16(w - __bfloat162float(h));
    }
}

// ---------------- K1: HMMA dual GEMM, 128x128 tiles over packed 768 cols ----------------
__global__ __launch_bounds__(256) void gemm1_mma(const float* __restrict__ bxv,
                                                 const float* __restrict__ bzv) {
    extern __shared__ char dynsm[];
    __nv_bfloat16* sAh = (__nv_bfloat16*)dynsm;      // [2][128*SW]
    __nv_bfloat16* sAl = sAh + 2*128*SW;
    __nv_bfloat16* sBh = sAl + 2*128*SW;             // [2][128*SW]
    __nv_bfloat16* sBl = sBh + 2*128*SW;

    int tid  = threadIdx.x;
    int wid  = tid >> 5;
    int lane = tid & 31;
    int grp  = lane >> 2;
    int qd   = lane & 3;
    int row0 = blockIdx.x * 128;
    int c0   = blockIdx.y * 128;          // packed col base (0..767)
    int isZ  = (c0 >= E_);
    int wm = (wid & 3) * 32;
    int wn = (wid >> 2) * 32;
    uint32_t aAh = smem_u32(sAh), aAl = smem_u32(sAl);
    uint32_t aBh = smem_u32(sBh), aBl = smem_u32(sBl);

    float acc[2][2][4][4];
    #pragma unroll
    for (int mi = 0; mi < 2; mi++)
        #pragma unroll
        for (int nh = 0; nh < 2; nh++)
            #pragma unroll
            for (int ni = 0; ni < 4; ni++)
                #pragma unroll
                for (int q = 0; q < 4; q++) acc[mi][nh][ni][q] = 0.f;

    auto stage = [&](int p, int kt) {
        #pragma unroll
        for (int i = 0; i < 2; i++) {
            int q = tid + i * 256;
            int r = q >> 2, kc = (q & 3) * 8;
            const size_t ga = (size_t)(row0 + r) * D_ + kt + kc;
            cp16(&sAh[p*128*SW + r*SW + kc], g_th + ga);
            cp16(&sAl[p*128*SW + r*SW + kc], g_tl + ga);
            const size_t gb = (size_t)(c0 + r) * D_ + kt + kc;
            cp16(&sBh[p*128*SW + r*SW + kc], g_wht + gb);
            cp16(&sBl[p*128*SW + r*SW + kc], g_wlt + gb);
        }
    };

    stage(0, 0); CP_COMMIT();
    for (int it = 0; it < 6; it++) {
        int p = it & 1;
        if (it < 5) { stage(p ^ 1, (it + 1) * 32); CP_COMMIT(); CP_WAIT1(); }
        else CP_WAIT0();
        __syncthreads();
        uint32_t bAh = aAh + p*128*SW*2, bAl = aAl + p*128*SW*2;
        uint32_t bBh = aBh + p*128*SW*2, bBl = aBl + p*128*SW*2;
        #pragma unroll
        for (int ks = 0; ks < 2; ks++) {
            int k0 = ks * 16;
            uint32_t ah[2][4], al[2][4];
            #pragma unroll
            for (int mi = 0; mi < 2; mi++) {
                lda_frag(ah[mi], bAh, wm + mi*16, k0, lane);
                lda_frag(al[mi], bAl, wm + mi*16, k0, lane);
            }
            #pragma unroll
            for (int nh = 0; nh < 2; nh++) {
                uint32_t bh[8], bl[8];
                #pragma unroll
                for (int pp = 0; pp < 2; pp++) {
                    ldb_frag(&bh[pp*4], bBh, nh*64 + wn + pp*16, k0, lane);
                    ldb_frag(&bl[pp*4], bBl, nh*64 + wn + pp*16, k0, lane);
                }
                #pragma unroll
                for (int mi = 0; mi < 2; mi++)
                    #pragma unroll
                    for (int ni = 0; ni < 4; ni++) {
                        mma16816(acc[mi][nh][ni], ah[mi], &bh[ni*2]);
                        mma16816(acc[mi][nh][ni], ah[mi], &bl[ni*2]);
                        mma16816(acc[mi][nh][ni], al[mi], &bh[ni*2]);
                    }
            }
        }
        __syncthreads();
    }

    #pragma unroll
    for (int mi = 0; mi < 2; mi++) {
        #pragma unroll
        for (int nh = 0; nh < 2; nh++) {
            #pragma unroll
            for (int ni = 0; ni < 4; ni++) {
                int cpk = c0 + nh*64 + wn + ni * 8 + qd * 2;
                int r0 = row0 + wm + mi * 16 + grp;
                #pragma unroll
                for (int h = 0; h < 2; h++) {
                    int row = r0 + h * 8;
                    float v0 = acc[mi][nh][ni][h*2 + 0];
                    float v1 = acc[mi][nh][ni][h*2 + 1];
                    if (!isZ) {
                        float2 o;
                        o.x = v0 + bxv[cpk];
                        o.y = v1 + bxv[cpk + 1];
                        *(float2*)&g_x[(size_t)row * E_ + cpk] = o;
                    } else {
                        int c = cpk - E_;
                        float zc, sl;
                        float2 o;
                        zc = v0 + bzv[c];     sl = zc / (1.f + __expf(-zc)); o.x = 1.f / (1.f + __expf(-sl));
                        zc = v1 + bzv[c + 1]; sl = zc / (1.f + __expf(-zc)); o.y = 1.f / (1.f + __expf(-sl));
                        *(float2*)&g_gate[(size_t)row * E_ + c] = o;
                    }
                }
            }
        }
    }
}

// ---------------- K2a: depthwise conv (both dirs), smem weights, 8e/thread ----------------
__global__ __launch_bounds__(384) void conv_kernel(
        const float* __restrict__ cwf, const float* __restrict__ cbf,
        const float* __restrict__ cwb, const float* __restrict__ cbb) {
    __shared__ float wf0[E_], wf1[E_], wf2[E_], bf[E_];
    __shared__ float wb0[E_], wb1[E_], wb2[E_], bb[E_];
    int tid = threadIdx.x;

    // stage weights transposed [tap][e]
    for (int i = tid; i < 3*E_; i += 384) {
        int e = i / 3, t = i - e*3;
        float vf = cwf[i], vb = cwb[i];
        (t == 0 ? wf0 : t == 1 ? wf1 : wf2)[e] = vf;
        (t == 0 ? wb0 : t == 1 ? wb1 : wb2)[e] = vb;
    }
    if (tid < E_) { bf[tid] = cbf[tid]; bb[tid] = cbb[tid]; }
    __syncthreads();

    int rl = tid / 48;            // 0..7
    int e  = (tid - rl * 48) * 8; // 0..376
    int row = blockIdx.x * 8 + rl;
    int j   = row & (J_ - 1);
    int b   = row >> 10;

    const float* xr = g_x + (size_t)row * E_ + e;
    float x0[8], x1[8], x2[8];
    *(float4*)&x1[0] = *(const float4*)xr;
    *(float4*)&x1[4] = *(const float4*)(xr + 4);
    if (j > 0) {
        *(float4*)&x0[0] = *(const float4*)(xr - E_);
        *(float4*)&x0[4] = *(const float4*)(xr - E_ + 4);
    } else {
        #pragma unroll
        for (int q = 0; q < 8; q++) x0[q] = 0.f;
    }
    if (j < J_ - 1) {
        *(float4*)&x2[0] = *(const float4*)(xr + E_);
        *(float4*)&x2[4] = *(const float4*)(xr + E_ + 4);
    } else {
        #pragma unroll
        for (int q = 0; q < 8; q++) x2[q] = 0.f;
    }

    __nv_bfloat16 fh[8], fl[8], bh[8], bl[8];
    #pragma unroll
    for (int q = 0; q < 8; q++) {
        int ec = e + q;
        float vf = wf0[ec]*x0[q] + wf1[ec]*x1[q] + wf2[ec]*x2[q] + bf[ec];
        float vb = wb0[ec]*x2[q] + wb1[ec]*x1[q] + wb2[ec]*x0[q] + bb[ec];
        fh[q] = __float2bfloat16(vf); fl[q] = __float2bfloat16(vf - __bfloat162float(fh[q]));
        bh[q] = __float2bfloat16(vb); bl[q] = __float2bfloat16(vb - __bfloat162float(bh[q]));
    }
    size_t of = (size_t)row * E_ + e;
    size_t ob = (size_t)(b * J_ + (J_ - 1 - j)) * E_ + e;
    *(uint4*)&g_xch[0][of] = *(uint4*)fh;
    *(uint4*)&g_xcl[0][of] = *(uint4*)fl;
    *(uint4*)&g_xch[1][ob] = *(uint4*)bh;
    *(uint4*)&g_xcl[1][ob] = *(uint4*)bl;
}

// ---------------- K2b: proj MMA + ZOH epilogue (cp.async double-buffer) ----------------
#define EPS 65
__global__ __launch_bounds__(256) void projmma_kernel(
        const float* __restrict__ bBf, const float* __restrict__ bCf,
        const float* __restrict__ bDf, const float* __restrict__ bBb,
        const float* __restrict__ bCb, const float* __restrict__ bDb,
        const float* __restrict__ A_log, const float* __restrict__ bi) {
    extern __shared__ char dynsm[];
    __nv_bfloat16* sAh = (__nv_bfloat16*)dynsm;
    __nv_bfloat16* sAl = sAh + 2*128*SW;
    __nv_bfloat16* sBh = sAl + 2*128*SW;
    __nv_bfloat16* sBl = sBh + 2*64*SW;
    float* ep = (float*)dynsm;                 // epilogue overlay (33280 B)
    __shared__ float sbias[4][N_];
    __shared__ float sAn[N_], sInv[N_];

    int tid  = threadIdx.x;
    int wid  = tid >> 5;
    int lane = tid & 31;
    int row0 = blockIdx.x * 128;
    int dir  = blockIdx.y;
    int b    = row0 >> 10;
    int s0   = row0 & (J_ - 1);
    int wm = (wid & 3) * 32;
    int wn = (wid >> 2) * 32;
    int grp  = lane >> 2;
    int qd   = lane & 3;
    uint32_t aAh = smem_u32(sAh), aAl = smem_u32(sAl);
    uint32_t aBh = smem_u32(sBh), aBl = smem_u32(sBl);

    if (tid < N_) {
        int n = tid;
        sbias[0][n] = dir ? bBb[n] : bBf[n];
        sbias[1][n] = dir ? bCb[n] : bCf[n];
        sbias[2][n] = dir ? bDb[n] : bDf[n];
        sbias[3][n] = bi[n];
        float al = A_log[n];
        float An = -log1pf(expf(al));
        sAn[n] = An;
        sInv[n] = 1.f / (An + 1e-6f);
    }

    const __nv_bfloat16* Ah = g_xch[dir];
    const __nv_bfloat16* Al = g_xcl[dir];
    const __nv_bfloat16* Bh = g_wph[dir];
    const __nv_bfloat16* Bl = g_wpl[dir];

    float acc[2][4][4];
    #pragma unroll
    for (int mi = 0; mi < 2; mi++)
        #pragma unroll
        for (int ni = 0; ni < 4; ni++)
            #pragma unroll
            for (int q = 0; q < 4; q++) acc[mi][ni][q] = 0.f;

    auto stage = [&](int p, int kt) {
        #pragma unroll
        for (int i = 0; i < 2; i++) {
            int q = tid + i * 256;
            int r = q >> 2, kc = (q & 3) * 8;
            const size_t go = (size_t)(row0 + r) * E_ + kt + kc;
            cp16(&sAh[p*128*SW + r*SW + kc], Ah + go);
            cp16(&sAl[p*128*SW + r*SW + kc], Al + go);
        }
        int r = tid >> 2, kc = (tid & 3) * 8;
        const size_t go = (size_t)r * E_ + kt + kc;
        cp16(&sBh[p*64*SW + r*SW + kc], Bh + go);
        cp16(&sBl[p*64*SW + r*SW + kc], Bl + go);
    };

    stage(0, 0); CP_COMMIT();
    for (int it = 0; it < 12; it++) {
        int p = it & 1;
        if (it < 11) { stage(p ^ 1, (it + 1) * 32); CP_COMMIT(); CP_WAIT1(); }
        else CP_WAIT0();
        __syncthreads();
        uint32_t bAhp = aAh + p*128*SW*2, bAlp = aAl + p*128*SW*2;
        uint32_t bBhp = aBh + p*64*SW*2,  bBlp = aBl + p*64*SW*2;
        #pragma unroll
        for (int ks = 0; ks < 2; ks++) {
            int k0 = ks * 16;
            uint32_t ah[2][4], al[2][4], bh[8], bl[8];
            #pragma unroll
            for (int mi = 0; mi < 2; mi++) {
                lda_frag(ah[mi], bAhp, wm + mi*16, k0, lane);
                lda_frag(al[mi], bAlp, wm + mi*16, k0, lane);
            }
            #pragma unroll
            for (int pp = 0; pp < 2; pp++) {
                ldb_frag(&bh[pp*4], bBhp, wn + pp*16, k0, lane);
                ldb_frag(&bl[pp*4], bBlp, wn + pp*16, k0, lane);
            }
            #pragma unroll
            for (int mi = 0; mi < 2; mi++)
                #pragma unroll
                for (int ni = 0; ni < 4; ni++) {
                    mma16816(acc[mi][ni], ah[mi], &bh[ni*2]);
                    mma16816(acc[mi][ni], ah[mi], &bl[ni*2]);
                    mma16816(acc[mi][ni], al[mi], &bh[ni*2]);
                }
        }
        __syncthreads();
    }

    #pragma unroll
    for (int mi = 0; mi < 2; mi++)
        #pragma unroll
        for (int ni = 0; ni < 4; ni++) {
            int c = wn + ni * 8 + qd * 2;
            int r0 = wm + mi * 16 + grp;
            #pragma unroll
            for (int h = 0; h < 2; h++) {
                ep[(r0 + h*8)*EPS + c    ] = acc[mi][ni][h*2 + 0];
                ep[(r0 + h*8)*EPS + c + 1] = acc[mi][ni][h*2 + 1];
            }
        }
    __syncthreads();

    #pragma unroll
    for (int it = 0; it < 8; it++) {
        int idx = tid + it * 256;
        int s = idx & 127;
        int n = idx >> 7;
        float bt  = ep[s*EPS + n     ] + sbias[0][n];
        float ct  = ep[s*EPS + n + 16] + sbias[1][n];
        float dtr = ep[s*EPS + n + 32] + sbias[2][n];
        float u   = ep[s*EPS + n + 48] + sbias[3][n];
        float An  = sAn[n];
        float dt  = (dtr > 20.f) ? dtr : log1pf(__expf(dtr));
        float abar = __expf(dt * An);
        float bu = (abar - 1.f) * sInv[n] * bt * u;
        size_t base = (size_t)(b*N_ + n) * J_ + s0 + s;
        g_Abar[dir][base] = abar;
        g_Bu[dir][base]   = bu;
        g_Ct[dir][base]   = ct;
    }
}

// ---------------- K3: blocked segmented scan (8 elems/lane) ----------------
__global__ __launch_bounds__(512) void scan_kernel() {
    int b   = blockIdx.x;
    int dir = blockIdx.y;
    int w    = threadIdx.x >> 5;
    int lane = threadIdx.x & 31;
    size_t base = (size_t)(b*N_ + w) * J_;
    const float* Aa = g_Abar[dir] + base;
    const float* Bu = g_Bu[dir]   + base;
    const float* Ct = g_Ct[dir]   + base;
    float carry = 0.f;
    #pragma unroll
    for (int seg = 0; seg < 4; seg++) {
        int s = seg*256 + lane*8;
        float a[8], bu[8];
        *(float4*)&a[0]  = *(const float4*)(Aa + s);
        *(float4*)&a[4]  = *(const float4*)(Aa + s + 4);
        *(float4*)&bu[0] = *(const float4*)(Bu + s);
        *(float4*)&bu[4] = *(const float4*)(Bu + s + 4);
        #pragma unroll
        for (int i = 1; i < 8; i++) { bu[i] = fmaf(a[i], bu[i-1], bu[i]); a[i] *= a[i-1]; }
        float As = a[7], Bs = bu[7];
        #pragma unroll
        for (int off = 1; off < 32; off <<= 1) {
            float ap = __shfl_up_sync(0xffffffffu, As, off);
            float bp = __shfl_up_sync(0xffffffffu, Bs, off);
            if (lane >= off) { Bs = fmaf(As, bp, Bs); As *= ap; }
        }
        float Ae = __shfl_up_sync(0xffffffffu, As, 1);
        float Be = __shfl_up_sync(0xffffffffu, Bs, 1);
        float Hprev = (lane == 0) ? carry : fmaf(Ae, carry, Be);
        float ct[8];
        *(float4*)&ct[0] = *(const float4*)(Ct + s);
        *(float4*)&ct[4] = *(const float4*)(Ct + s + 4);
        float hlast = 0.f;
        #pragma unroll
        for (int i = 0; i < 8; i++) {
            float h = fmaf(a[i], Hprev, bu[i]);
            if (i == 7) hlast = h;
            int sg = s + i;
            int jorig = dir ? (J_ - 1 - sg) : sg;
            g_g[dir][(size_t)(b*J_ + jorig) * N_ + w] = h * ct[i];
        }
        carry = __shfl_sync(0xffffffffu, hlast, 31);
    }
}

// ---------------- K4a: y = (gsum@Wr + 2br) * gate -> bf16 hi/lo ----------------
__global__ __launch_bounds__(256) void y_kernel(const float* __restrict__ Wr,
                                                const float* __restrict__ br) {
    __shared__ float sWr[N_*E_];
    __shared__ float sbr[E_];
    __shared__ float gsm[8*N_];
    int tid = threadIdx.x;
    int row0 = blockIdx.x * 8;

    #pragma unroll
    for (int i = 0; i < 24; i++) sWr[tid + i*256] = Wr[tid + i*256];
    if (tid < 128) {
        sbr[tid]       = 2.f * br[tid];
        sbr[tid + 128] = 2.f * br[tid + 128];
        if (tid < 64)  sbr[tid + 256] = 2.f * br[tid + 256];
        else           sbr[(tid - 64) + 320] = 2.f * br[(tid - 64) + 320];
    }
    if (tid < 128) {
        int r = tid >> 4, n = tid & 15;
        size_t row = (size_t)(row0 + r);
        gsm[tid] = g_g[0][row*N_ + n] + g_g[1][row*N_ + n];
    }
    __syncthreads();

    #pragma unroll
    for (int i = 0; i < 12; i++) {
        int q = tid + i * 256;
        int r = q / E_, e = q - r * E_;
        const float* gv = &gsm[r*N_];
        float acc = sbr[e];
        #pragma unroll
        for (int nn = 0; nn < N_; nn++) acc += gv[nn] * sWr[nn*E_ + e];
        size_t row = (size_t)(row0 + r);
        float y = acc * g_gate[row*E_ + e];
        __nv_bfloat16 h = __float2bfloat16(y);
        g_xch[0][row*E_ + e] = h;
        g_xcl[0][row*E_ + e] = __float2bfloat16(y - __bfloat162float(h));
    }
}

// ---------------- K4b: out = tokens + y @ Wo + bo (cp.async double-buffer) ----------------
__global__ __launch_bounds__(256) void outmma_kernel(const float* __restrict__ tokens,
                                                     const float* __restrict__ bo,
                                                     float* __restrict__ out) {
    extern __shared__ char dynsm[];
    __nv_bfloat16* sAh = (__nv_bfloat16*)dynsm;
    __nv_bfloat16* sAl = sAh + 2*128*SW;
    __nv_bfloat16* sBh = sAl + 2*128*SW;
    __nv_bfloat16* sBl = sBh + 2*64*SW;

    int tid  = threadIdx.x;
    int wid  = tid >> 5;
    int lane = tid & 31;
    int grp  = lane >> 2;
    int qd   = lane & 3;
    int row0 = blockIdx.x * 128;
    int cb   = blockIdx.y * 64;
    int wm = (wid & 3) * 32;
    int wn = (wid >> 2) * 32;
    uint32_t aAh = smem_u32(sAh), aAl = smem_u32(sAl);
    uint32_t aBh = smem_u32(sBh), aBl = smem_u32(sBl);

    float acc[2][4][4];
    #pragma unroll
    for (int mi = 0; mi < 2; mi++)
        #pragma unroll
        for (int ni = 0; ni < 4; ni++)
            #pragma unroll
            for (int q = 0; q < 4; q++) acc[mi][ni][q] = 0.f;

    auto stage = [&](int p, int kt) {
        #pragma unroll
        for (int i = 0; i < 2; i++) {
            int q = tid + i * 256;
            int r = q >> 2, kc = (q & 3) * 8;
            const size_t go = (size_t)(row0 + r) * E_ + kt + kc;
            cp16(&sAh[p*128*SW + r*SW + kc], g_xch[0] + go);
            cp16(&sAl[p*128*SW + r*SW + kc], g_xcl[0] + go);
        }
        int r = tid >> 2, kc = (tid & 3) * 8;
        const size_t go = (size_t)(cb + r) * E_ + kt + kc;
        cp16(&sBh[p*64*SW + r*SW + kc], g_woh + go);
        cp16(&sBl[p*64*SW + r*SW + kc], g_wol + go);
    };

    stage(0, 0); CP_COMMIT();
    for (int it = 0; it < 12; it++) {
        int p = it & 1;
        if (it < 11) { stage(p ^ 1, (it + 1) * 32); CP_COMMIT(); CP_WAIT1(); }
        else CP_WAIT0();
        __syncthreads();
        uint32_t bAhp = aAh + p*128*SW*2, bAlp = aAl + p*128*SW*2;
        uint32_t bBhp = aBh + p*64*SW*2,  bBlp = aBl + p*64*SW*2;
        #pragma unroll
        for (int ks = 0; ks < 2; ks++) {
            int k0 = ks * 16;
            uint32_t ah[2][4], al[2][4], bh[8], bl[8];
            #pragma unroll
            for (int mi = 0; mi < 2; mi++) {
                lda_frag(ah[mi], bAhp, wm + mi*16, k0, lane);
                lda_frag(al[mi], bAlp, wm + mi*16, k0, lane);
            }
            #pragma unroll
            for (int pp = 0; pp < 2; pp++) {
                ldb_frag(&bh[pp*4], bBhp, wn + pp*16, k0, lane);
                ldb_frag(&bl[pp*4], bBlp, wn + pp*16, k0, lane);
            }
            #pragma unroll
            for (int mi = 0; mi < 2; mi++)
                #pragma unroll
                for (int ni = 0; ni < 4; ni++) {
                    mma16816(acc[mi][ni], ah[mi], &bh[ni*2]);
                    mma16816(acc[mi][ni], ah[mi], &bl[ni*2]);
                    mma16816(acc[mi][ni], al[mi], &bh[ni*2]);
                }
        }
        __syncthreads();
    }

    #pragma unroll
    for (int mi = 0; mi < 2; mi++) {
        #pragma unroll
        for (int ni = 0; ni < 4; ni++) {
            int c = cb + wn + ni * 8 + qd * 2;
            int r0 = row0 + wm + mi * 16 + grp;
            float2 bov = *(const float2*)&bo[c];
            #pragma unroll
            for (int h = 0; h < 2; h++) {
                int row = r0 + h * 8;
                float2 tk = *(const float2*)&tokens[(size_t)row * D_ + c];
                float2 o;
                o.x = tk.x + acc[mi][ni][h*2 + 0] + bov.x;
                o.y = tk.y + acc[mi][ni][h*2 + 1] + bov.y;
                *(float2*)&out[(size_t)row * D_ + c] = o;
            }
        }
    }
}

// ---------------- launch ----------------
#define DYN_SMEM_G1 81920
#define DYN_SMEM    61440

extern "C" void kernel_launch(void* const* d_in, const int* in_sizes, int n_in,
                              void* d_out, int out_size) {
    const float* tokens = (const float*)d_in[0];
    const float* norm_g = (const float*)d_in[1];
    const float* norm_b = (const float*)d_in[2];
    const float* Wx  = (const float*)d_in[3];
    const float* bx  = (const float*)d_in[4];
    const float* Wz  = (const float*)d_in[5];
    const float* bz  = (const float*)d_in[6];
    const float* cwf = (const float*)d_in[7];
    const float* cbf = (const float*)d_in[8];
    const float* cwb = (const float*)d_in[9];
    const float* cbb = (const float*)d_in[10];
    const float* WBf = (const float*)d_in[11];
    const float* bBf = (const float*)d_in[12];
    const float* WCf = (const float*)d_in[13];
    const float* bCf = (const float*)d_in[14];
    const float* WDf = (const float*)d_in[15];
    const float* bDf = (const float*)d_in[16];
    const float* WBb = (const float*)d_in[17];
    const float* bBb = (const float*)d_in[18];
    const float* WCb = (const float*)d_in[19];
    const float* bCb = (const float*)d_in[20];
    const float* WDb = (const float*)d_in[21];
    const float* bDb = (const float*)d_in[22];
    const float* A_log = (const float*)d_in[23];
    const float* Wi  = (const float*)d_in[24];
    const float* bi  = (const float*)d_in[25];
    const float* Wr  = (const float*)d_in[26];
    const float* br  = (const float*)d_in[27];
    const float* Wo  = (const float*)d_in[28];
    const float* bo  = (const float*)d_in[29];
    float* out = (float*)d_out;

    cudaFuncSetAttribute(gemm1_mma,      cudaFuncAttributeMaxDynamicSharedMemorySize, DYN_SMEM_G1);
    cudaFuncSetAttribute(projmma_kernel, cudaFuncAttributeMaxDynamicSharedMemorySize, DYN_SMEM);
    cudaFuncSetAttribute(outmma_kernel,  cudaFuncAttributeMaxDynamicSharedMemorySize, DYN_SMEM);

    ln_kernel<<<BJ_/8, 256>>>(tokens, norm_g, norm_b);
    wprep_all<<<1056, 256>>>(Wx, Wz, WBf, WCf, WDf, WBb, WCb, WDb, Wi, Wo);
    gemm1_mma<<<dim3(BJ_/128, 6), 256, DYN_SMEM_G1>>>(bx, bz);
    conv_kernel<<<BJ_/8, 384>>>(cwf, cbf, cwb, cbb);
    projmma_kernel<<<dim3(BJ_/128, 2), 256, DYN_SMEM>>>(bBf, bCf, bDf, bBb, bCb, bDb, A_log, bi);
    scan_kernel<<<dim3(B_, 2), 512>>>();
    y_kernel<<<BJ_/8, 256>>>(Wr, br);
    outmma_kernel<<<dim3(BJ_/128, 3), 256, DYN_SMEM>>>(tokens, bo, out);
}

// round 9
// speedup vs baseline: 2.7609x; 1.0334x over previous
#include <cuda_runtime.h>
#include <cuda_bf16.h>
#include <math.h>
#include <stdint.h>

#define B_ 32
#define J_ 1024
#define D_ 192
#define E_ 384
#define N_ 16
#define BJ_ (B_*J_)

// ---------------- device scratch (no allocs allowed) ----------------
__device__ __nv_bfloat16 g_th[BJ_*D_];     // LN output hi (bf16)
__device__ __nv_bfloat16 g_tl[BJ_*D_];     // LN output lo (bf16)
__device__ __nv_bfloat16 g_wht[768*D_];    // [Wx|Wz] transposed hi: [col][k]
__device__ __nv_bfloat16 g_wlt[768*D_];    // [Wx|Wz] transposed lo
__device__ float g_x[BJ_*E_];              // x = t@Wx + bx
__device__ float g_gate[BJ_*E_];           // sigmoid(silu(z))
__device__ __nv_bfloat16 g_xch[2][BJ_*E_]; // conv output hi ([0] reused as y hi)
__device__ __nv_bfloat16 g_xcl[2][BJ_*E_]; // conv output lo ([0] reused as y lo)
__device__ __nv_bfloat16 g_wph[2][64*E_];  // [dir][col][k] packed [WB|WC|WD|Wi] hi
__device__ __nv_bfloat16 g_wpl[2][64*E_];  // lo
__device__ __nv_bfloat16 g_woh[192*E_];    // Wo transposed hi: [d][k]
__device__ __nv_bfloat16 g_wol[192*E_];    // lo
__device__ float g_Abar[2][B_*N_*J_];      // [dir][b][n][s]
__device__ float g_Bu  [2][B_*N_*J_];
__device__ float g_Ct  [2][B_*N_*J_];
__device__ float g_g   [2][BJ_*N_];        // hs*Ct at ORIGINAL j

// ---------------- helpers ----------------
#define SW 40   // smem row stride in bf16 (80B: conflict-free for ldmatrix phases)

__device__ __forceinline__ uint32_t smem_u32(const void* p) {
    return (uint32_t)__cvta_generic_to_shared(p);
}
__device__ __forceinline__ void cp16(void* dst_smem, const void* src) {
    uint32_t d = smem_u32(dst_smem);
    asm volatile("cp.async.ca.shared.global [%0], [%1], 16;" :: "r"(d), "l"(src));
}
#define CP_COMMIT() asm volatile("cp.async.commit_group;" ::: "memory")
#define CP_WAIT1()  asm volatile("cp.async.wait_group 1;" ::: "memory")
#define CP_WAIT0()  asm volatile("cp.async.wait_group 0;" ::: "memory")

__device__ __forceinline__ void ldsm_x4(uint32_t* r, uint32_t addr) {
    asm volatile("ldmatrix.sync.aligned.m8n8.x4.shared.b16 {%0,%1,%2,%3}, [%4];"
        : "=r"(r[0]), "=r"(r[1]), "=r"(r[2]), "=r"(r[3]) : "r"(addr));
}
__device__ __forceinline__ void lda_frag(uint32_t* a, uint32_t sbase, int rb, int k0, int lane) {
    uint32_t addr = sbase + (uint32_t)((rb + (lane & 15)) * (SW*2) + k0*2 + ((lane >> 4) << 4));
    ldsm_x4(a, addr);
}
__device__ __forceinline__ void ldb_frag(uint32_t* b, uint32_t sbase, int nb_pair, int k0, int lane) {
    int sub = lane >> 3;
    int row = nb_pair + ((sub >> 1) << 3) + (lane & 7);
    uint32_t addr = sbase + (uint32_t)(row * (SW*2) + (k0 + ((sub & 1) << 3)) * 2);
    ldsm_x4(b, addr);
}
__device__ __forceinline__ void mma16816(float* c, const uint32_t* a, const uint32_t* b) {
    asm volatile(
        "mma.sync.aligned.m16n8k16.row.col.f32.bf16.bf16.f32 "
        "{%0,%1,%2,%3}, {%4,%5,%6,%7}, {%8,%9}, {%0,%1,%2,%3};"
        : "+f"(c[0]), "+f"(c[1]), "+f"(c[2]), "+f"(c[3])
        : "r"(a[0]), "r"(a[1]), "r"(a[2]), "r"(a[3]), "r"(b[0]), "r"(b[1]));
}

// ---------------- K0: LayerNorm -> bf16 hi/lo ----------------
__global__ void ln_kernel(const float* __restrict__ tok,
                          const float* __restrict__ gamma,
                          const float* __restrict__ beta) {
    int row  = blockIdx.x * 8 + (threadIdx.x >> 5);
    int lane = threadIdx.x & 31;
    const float* tr = tok + (size_t)row * D_;
    float v[6];
    float s = 0.f;
    #pragma unroll
    for (int i = 0; i < 6; i++) { v[i] = tr[lane + 32*i]; s += v[i]; }
    #pragma unroll
    for (int o = 16; o > 0; o >>= 1) s += __shfl_xor_sync(0xffffffffu, s, o);
    float mu = s * (1.f / D_);
    float vs = 0.f;
    #pragma unroll
    for (int i = 0; i < 6; i++) { float d = v[i] - mu; vs += d * d; }
    #pragma unroll
    for (int o = 16; o > 0; o >>= 1) vs += __shfl_xor_sync(0xffffffffu, vs, o);
    float inv = rsqrtf(vs * (1.f / D_) + 1e-5f);
    #pragma unroll
    for (int i = 0; i < 6; i++) {
        int c = lane + 32*i;
        float t = (v[i] - mu) * inv * gamma[c] + beta[c];
        __nv_bfloat16 h = __float2bfloat16(t);
        g_th[(size_t)row * D_ + c] = h;
        g_tl[(size_t)row * D_ + c] = __float2bfloat16(t - __bfloat162float(h));
    }
}

// ---------------- K0b: merged weight prep ----------------
__global__ void wprep_all(
        const float* __restrict__ Wx, const float* __restrict__ Wz,
        const float* __restrict__ WBf, const float* __restrict__ WCf,
        const float* __restrict__ WDf, const float* __restrict__ WBb,
        const float* __restrict__ WCb, const float* __restrict__ WDb,
        const float* __restrict__ Wi,  const float* __restrict__ Wo) {
    int i = blockIdx.x * 256 + threadIdx.x;
    const int n1 = 768 * D_;
    const int n2 = n1 + 2 * 64 * E_;
    const int n3 = n2 + 192 * E_;
    if (i < n1) {
        int c = i / D_, k = i - c * D_;
        float w = (c < E_) ? Wx[(size_t)k * E_ + c] : Wz[(size_t)k * E_ + (c - E_)];
        __nv_bfloat16 h = __float2bfloat16(w);
        g_wht[i] = h;
        g_wlt[i] = __float2bfloat16(w - __bfloat162float(h));
    } else if (i < n2) {
        int q = i - n1;
        int dir = q / (64 * E_);
        int rem = q - dir * 64 * E_;
        int c = rem / E_, k = rem - c * E_;
        int m = c >> 4, n = c & 15;
        const float* W;
        if (m == 0) W = dir ? WBb : WBf;
        else if (m == 1) W = dir ? WCb : WCf;
        else if (m == 2) W = dir ? WDb : WDf;
        else W = Wi;
        float w = W[(size_t)k * N_ + n];
        __nv_bfloat16 h = __float2bfloat16(w);
        g_wph[dir][rem] = h;
        g_wpl[dir][rem] = __float2bfloat16(w - __bfloat162float(h));
    } else if (i < n3) {
        int q = i - n2;
        int d = q / E_, k = q - d * E_;
        float w = Wo[(size_t)k * D_ + d];
        __nv_bfloat16 h = __float2bfloat16(w);
        g_woh[q] = h;
        g_wol[q] = __float2bfloat16(w - __bfloat162float(h));
    }
}

// ---------------- K1: HMMA dual GEMM, 128x128 tiles over packed 768 cols ----------------
__global__ __launch_bounds__(256) void gemm1_mma(const float* __restrict__ bxv,
                                                 const float* __restrict__ bzv) {
    extern __shared__ char dynsm[];
    __nv_bfloat16* sAh = (__nv_bfloat16*)dynsm;      // [2][128*SW]
    __nv_bfloat16* sAl = sAh + 2*128*SW;
    __nv_bfloat16* sBh = sAl + 2*128*SW;             // [2][128*SW]
    __nv_bfloat16* sBl = sBh + 2*128*SW;

    int tid  = threadIdx.x;
    int wid  = tid >> 5;
    int lane = tid & 31;
    int grp  = lane >> 2;
    int qd   = lane & 3;
    int row0 = blockIdx.x * 128;
    int c0   = blockIdx.y * 128;          // packed col base (0..767)
    int isZ  = (c0 >= E_);
    int wm = (wid & 3) * 32;
    int wn = (wid >> 2) * 32;
    uint32_t aAh = smem_u32(sAh), aAl = smem_u32(sAl);
    uint32_t aBh = smem_u32(sBh), aBl = smem_u32(sBl);

    float acc[2][2][4][4];
    #pragma unroll
    for (int mi = 0; mi < 2; mi++)
        #pragma unroll
        for (int nh = 0; nh < 2; nh++)
            #pragma unroll
            for (int ni = 0; ni < 4; ni++)
                #pragma unroll
                for (int q = 0; q < 4; q++) acc[mi][nh][ni][q] = 0.f;

    auto stage = [&](int p, int kt) {
        #pragma unroll
        for (int i = 0; i < 2; i++) {
            int q = tid + i * 256;
            int r = q >> 2, kc = (q & 3) * 8;
            const size_t ga = (size_t)(row0 + r) * D_ + kt + kc;
            cp16(&sAh[p*128*SW + r*SW + kc], g_th + ga);
            cp16(&sAl[p*128*SW + r*SW + kc], g_tl + ga);
            const size_t gb = (size_t)(c0 + r) * D_ + kt + kc;
            cp16(&sBh[p*128*SW + r*SW + kc], g_wht + gb);
            cp16(&sBl[p*128*SW + r*SW + kc], g_wlt + gb);
        }
    };

    stage(0, 0); CP_COMMIT();
    for (int it = 0; it < 6; it++) {
        int p = it & 1;
        if (it < 5) { stage(p ^ 1, (it + 1) * 32); CP_COMMIT(); CP_WAIT1(); }
        else CP_WAIT0();
        __syncthreads();
        uint32_t bAh = aAh + p*128*SW*2, bAl = aAl + p*128*SW*2;
        uint32_t bBh = aBh + p*128*SW*2, bBl = aBl + p*128*SW*2;
        #pragma unroll
        for (int ks = 0; ks < 2; ks++) {
            int k0 = ks * 16;
            uint32_t ah[2][4], al[2][4];
            #pragma unroll
            for (int mi = 0; mi < 2; mi++) {
                lda_frag(ah[mi], bAh, wm + mi*16, k0, lane);
                lda_frag(al[mi], bAl, wm + mi*16, k0, lane);
            }
            #pragma unroll
            for (int nh = 0; nh < 2; nh++) {
                uint32_t bh[8], bl[8];
                #pragma unroll
                for (int pp = 0; pp < 2; pp++) {
                    ldb_frag(&bh[pp*4], bBh, nh*64 + wn + pp*16, k0, lane);
                    ldb_frag(&bl[pp*4], bBl, nh*64 + wn + pp*16, k0, lane);
                }
                #pragma unroll
                for (int mi = 0; mi < 2; mi++)
                    #pragma unroll
                    for (int ni = 0; ni < 4; ni++) {
                        mma16816(acc[mi][nh][ni], ah[mi], &bh[ni*2]);
                        mma16816(acc[mi][nh][ni], ah[mi], &bl[ni*2]);
                        mma16816(acc[mi][nh][ni], al[mi], &bh[ni*2]);
                    }
            }
        }
        __syncthreads();
    }

    #pragma unroll
    for (int mi = 0; mi < 2; mi++) {
        #pragma unroll
        for (int nh = 0; nh < 2; nh++) {
            #pragma unroll
            for (int ni = 0; ni < 4; ni++) {
                int cpk = c0 + nh*64 + wn + ni * 8 + qd * 2;
                int r0 = row0 + wm + mi * 16 + grp;
                #pragma unroll
                for (int h = 0; h < 2; h++) {
                    int row = r0 + h * 8;
                    float v0 = acc[mi][nh][ni][h*2 + 0];
                    float v1 = acc[mi][nh][ni][h*2 + 1];
                    if (!isZ) {
                        float2 o;
                        o.x = v0 + bxv[cpk];
                        o.y = v1 + bxv[cpk + 1];
                        *(float2*)&g_x[(size_t)row * E_ + cpk] = o;
                    } else {
                        int c = cpk - E_;
                        float zc, sl;
                        float2 o;
                        zc = v0 + bzv[c];     sl = zc / (1.f + __expf(-zc)); o.x = 1.f / (1.f + __expf(-sl));
                        zc = v1 + bzv[c + 1]; sl = zc / (1.f + __expf(-zc)); o.y = 1.f / (1.f + __expf(-sl));
                        *(float2*)&g_gate[(size_t)row * E_ + c] = o;
                    }
                }
            }
        }
    }
}

// ---------------- K2a: depthwise conv v3 — register weights, rolling window ----------------
// block: 384 threads = 4 strips x 96 e-groups; strip = 16 rows; block = 64 rows of one batch
__global__ __launch_bounds__(384) void conv_kernel(
        const float* __restrict__ cwf, const float* __restrict__ cbf,
        const float* __restrict__ cwb, const float* __restrict__ cbb) {
    __shared__ float swf[3][E_], swb[3][E_], sbf[E_], sbb[E_];
    int tid = threadIdx.x;

    for (int i = tid; i < 3*E_; i += 384) {
        int e = i / 3, t = i - e*3;
        swf[t][e] = cwf[i];
        swb[t][e] = cwb[i];
    }
    if (tid < E_) { sbf[tid] = cbf[tid]; sbb[tid] = cbb[tid]; }
    __syncthreads();

    int strip = tid / 96;
    int eg    = tid - strip * 96;
    int e     = eg * 4;
    int rowbase = blockIdx.x * 64 + strip * 16;
    int b  = rowbase >> 10;
    int j0 = rowbase & (J_ - 1);

    float wf[3][4], wb[3][4], bfv[4], bbv[4];
    #pragma unroll
    for (int t = 0; t < 3; t++) {
        *(float4*)wf[t] = *(const float4*)&swf[t][e];
        *(float4*)wb[t] = *(const float4*)&swb[t][e];
    }
    *(float4*)bfv = *(const float4*)&sbf[e];
    *(float4*)bbv = *(const float4*)&sbb[e];

    const float* xp = g_x + (size_t)rowbase * E_ + e;
    float x0[4], x1[4], x2[4];
    if (j0 > 0) *(float4*)x0 = *(const float4*)(xp - E_);
    else { x0[0] = x0[1] = x0[2] = x0[3] = 0.f; }
    *(float4*)x1 = *(const float4*)xp;

    #pragma unroll
    for (int r = 0; r < 16; r++) {
        int j = j0 + r;
        if (j < J_ - 1) *(float4*)x2 = *(const float4*)(xp + E_);
        else { x2[0] = x2[1] = x2[2] = x2[3] = 0.f; }

        __nv_bfloat16 fh[4], fl[4], bh[4], bl[4];
        #pragma unroll
        for (int q = 0; q < 4; q++) {
            float vf = wf[0][q]*x0[q] + wf[1][q]*x1[q] + wf[2][q]*x2[q] + bfv[q];
            float vb = wb[0][q]*x2[q] + wb[1][q]*x1[q] + wb[2][q]*x0[q] + bbv[q];
            fh[q] = __float2bfloat16(vf); fl[q] = __float2bfloat16(vf - __bfloat162float(fh[q]));
            bh[q] = __float2bfloat16(vb); bl[q] = __float2bfloat16(vb - __bfloat162float(bh[q]));
        }
        size_t of = (size_t)(b * J_ + j) * E_ + e;
        size_t ob = (size_t)(b * J_ + (J_ - 1 - j)) * E_ + e;
        *(uint2*)&g_xch[0][of] = *(uint2*)fh;
        *(uint2*)&g_xcl[0][of] = *(uint2*)fl;
        *(uint2*)&g_xch[1][ob] = *(uint2*)bh;
        *(uint2*)&g_xcl[1][ob] = *(uint2*)bl;

        #pragma unroll
        for (int q = 0; q < 4; q++) { x0[q] = x1[q]; x1[q] = x2[q]; }
        xp += E_;
    }
}

// ---------------- K2b: proj MMA + ZOH epilogue (cp.async double-buffer) ----------------
#define EPS 65
__global__ __launch_bounds__(256) void projmma_kernel(
        const float* __restrict__ bBf, const float* __restrict__ bCf,
        const float* __restrict__ bDf, const float* __restrict__ bBb,
        const float* __restrict__ bCb, const float* __restrict__ bDb,
        const float* __restrict__ A_log, const float* __restrict__ bi) {
    extern __shared__ char dynsm[];
    __nv_bfloat16* sAh = (__nv_bfloat16*)dynsm;
    __nv_bfloat16* sAl = sAh + 2*128*SW;
    __nv_bfloat16* sBh = sAl + 2*128*SW;
    __nv_bfloat16* sBl = sBh + 2*64*SW;
    float* ep = (float*)dynsm;                 // epilogue overlay (33280 B)
    __shared__ float sbias[4][N_];
    __shared__ float sAn[N_], sInv[N_];

    int tid  = threadIdx.x;
    int wid  = tid >> 5;
    int lane = tid & 31;
    int row0 = blockIdx.x * 128;
    int dir  = blockIdx.y;
    int b    = row0 >> 10;
    int s0   = row0 & (J_ - 1);
    int wm = (wid & 3) * 32;
    int wn = (wid >> 2) * 32;
    int grp  = lane >> 2;
    int qd   = lane & 3;
    uint32_t aAh = smem_u32(sAh), aAl = smem_u32(sAl);
    uint32_t aBh = smem_u32(sBh), aBl = smem_u32(sBl);

    if (tid < N_) {
        int n = tid;
        sbias[0][n] = dir ? bBb[n] : bBf[n];
        sbias[1][n] = dir ? bCb[n] : bCf[n];
        sbias[2][n] = dir ? bDb[n] : bDf[n];
        sbias[3][n] = bi[n];
        float al = A_log[n];
        float An = -log1pf(expf(al));
        sAn[n] = An;
        sInv[n] = 1.f / (An + 1e-6f);
    }

    const __nv_bfloat16* Ah = g_xch[dir];
    const __nv_bfloat16* Al = g_xcl[dir];
    const __nv_bfloat16* Bh = g_wph[dir];
    const __nv_bfloat16* Bl = g_wpl[dir];

    float acc[2][4][4];
    #pragma unroll
    for (int mi = 0; mi < 2; mi++)
        #pragma unroll
        for (int ni = 0; ni < 4; ni++)
            #pragma unroll
            for (int q = 0; q < 4; q++) acc[mi][ni][q] = 0.f;

    auto stage = [&](int p, int kt) {
        #pragma unroll
        for (int i = 0; i < 2; i++) {
            int q = tid + i * 256;
            int r = q >> 2, kc = (q & 3) * 8;
            const size_t go = (size_t)(row0 + r) * E_ + kt + kc;
            cp16(&sAh[p*128*SW + r*SW + kc], Ah + go);
            cp16(&sAl[p*128*SW + r*SW + kc], Al + go);
        }
        int r = tid >> 2, kc = (tid & 3) * 8;
        const size_t go = (size_t)r * E_ + kt + kc;
        cp16(&sBh[p*64*SW + r*SW + kc], Bh + go);
        cp16(&sBl[p*64*SW + r*SW + kc], Bl + go);
    };

    stage(0, 0); CP_COMMIT();
    for (int it = 0; it < 12; it++) {
        int p = it & 1;
        if (it < 11) { stage(p ^ 1, (it + 1) * 32); CP_COMMIT(); CP_WAIT1(); }
        else CP_WAIT0();
        __syncthreads();
        uint32_t bAhp = aAh + p*128*SW*2, bAlp = aAl + p*128*SW*2;
        uint32_t bBhp = aBh + p*64*SW*2,  bBlp = aBl + p*64*SW*2;
        #pragma unroll
        for (int ks = 0; ks < 2; ks++) {
            int k0 = ks * 16;
            uint32_t ah[2][4], al[2][4], bh[8], bl[8];
            #pragma unroll
            for (int mi = 0; mi < 2; mi++) {
                lda_frag(ah[mi], bAhp, wm + mi*16, k0, lane);
                lda_frag(al[mi], bAlp, wm + mi*16, k0, lane);
            }
            #pragma unroll
            for (int pp = 0; pp < 2; pp++) {
                ldb_frag(&bh[pp*4], bBhp, wn + pp*16, k0, lane);
                ldb_frag(&bl[pp*4], bBlp, wn + pp*16, k0, lane);
            }
            #pragma unroll
            for (int mi = 0; mi < 2; mi++)
                #pragma unroll
                for (int ni = 0; ni < 4; ni++) {
                    mma16816(acc[mi][ni], ah[mi], &bh[ni*2]);
                    mma16816(acc[mi][ni], ah[mi], &bl[ni*2]);
                    mma16816(acc[mi][ni], al[mi], &bh[ni*2]);
                }
        }
        __syncthreads();
    }

    #pragma unroll
    for (int mi = 0; mi < 2; mi++)
        #pragma unroll
        for (int ni = 0; ni < 4; ni++) {
            int c = wn + ni * 8 + qd * 2;
            int r0 = wm + mi * 16 + grp;
            #pragma unroll
            for (int h = 0; h < 2; h++) {
                ep[(r0 + h*8)*EPS + c    ] = acc[mi][ni][h*2 + 0];
                ep[(r0 + h*8)*EPS + c + 1] = acc[mi][ni][h*2 + 1];
            }
        }
    __syncthreads();

    #pragma unroll
    for (int it = 0; it < 8; it++) {
        int idx = tid + it * 256;
        int s = idx & 127;
        int n = idx >> 7;
        float bt  = ep[s*EPS + n     ] + sbias[0][n];
        float ct  = ep[s*EPS + n + 16] + sbias[1][n];
        float dtr = ep[s*EPS + n + 32] + sbias[2][n];
        float u   = ep[s*EPS + n + 48] + sbias[3][n];
        float An  = sAn[n];
        float dt  = (dtr > 20.f) ? dtr : log1pf(__expf(dtr));
        float abar = __expf(dt * An);
        float bu = (abar - 1.f) * sInv[n] * bt * u;
        size_t base = (size_t)(b*N_ + n) * J_ + s0 + s;
        g_Abar[dir][base] = abar;
        g_Bu[dir][base]   = bu;
        g_Ct[dir][base]   = ct;
    }
}

// ---------------- K3: blocked segmented scan (8 elems/lane) ----------------
__global__ __launch_bounds__(512) void scan_kernel() {
    int b   = blockIdx.x;
    int dir = blockIdx.y;
    int w    = threadIdx.x >> 5;
    int lane = threadIdx.x & 31;
    size_t base = (size_t)(b*N_ + w) * J_;
    const float* Aa = g_Abar[dir] + base;
    const float* Bu = g_Bu[dir]   + base;
    const float* Ct = g_Ct[dir]   + base;
    float carry = 0.f;
    #pragma unroll
    for (int seg = 0; seg < 4; seg++) {
        int s = seg*256 + lane*8;
        float a[8], bu[8];
        *(float4*)&a[0]  = *(const float4*)(Aa + s);
        *(float4*)&a[4]  = *(const float4*)(Aa + s + 4);
        *(float4*)&bu[0] = *(const float4*)(Bu + s);
        *(float4*)&bu[4] = *(const float4*)(Bu + s + 4);
        #pragma unroll
        for (int i = 1; i < 8; i++) { bu[i] = fmaf(a[i], bu[i-1], bu[i]); a[i] *= a[i-1]; }
        float As = a[7], Bs = bu[7];
        #pragma unroll
        for (int off = 1; off < 32; off <<= 1) {
            float ap = __shfl_up_sync(0xffffffffu, As, off);
            float bp = __shfl_up_sync(0xffffffffu, Bs, off);
            if (lane >= off) { Bs = fmaf(As, bp, Bs); As *= ap; }
        }
        float Ae = __shfl_up_sync(0xffffffffu, As, 1);
        float Be = __shfl_up_sync(0xffffffffu, Bs, 1);
        float Hprev = (lane == 0) ? carry : fmaf(Ae, carry, Be);
        float ct[8];
        *(float4*)&ct[0] = *(const float4*)(Ct + s);
        *(float4*)&ct[4] = *(const float4*)(Ct + s + 4);
        float hlast = 0.f;
        #pragma unroll
        for (int i = 0; i < 8; i++) {
            float h = fmaf(a[i], Hprev, bu[i]);
            if (i == 7) hlast = h;
            int sg = s + i;
            int jorig = dir ? (J_ - 1 - sg) : sg;
            g_g[dir][(size_t)(b*J_ + jorig) * N_ + w] = h * ct[i];
        }
        carry = __shfl_sync(0xffffffffu, hlast, 31);
    }
}

// ---------------- K4a: y = (gsum@Wr + 2br) * gate -> bf16 hi/lo ----------------
__global__ __launch_bounds__(256) void y_kernel(const float* __restrict__ Wr,
                                                const float* __restrict__ br) {
    __shared__ float sWr[N_*E_];
    __shared__ float sbr[E_];
    __shared__ float gsm[8*N_];
    int tid = threadIdx.x;
    int row0 = blockIdx.x * 8;

    #pragma unroll
    for (int i = 0; i < 24; i++) sWr[tid + i*256] = Wr[tid + i*256];
    if (tid < 128) {
        sbr[tid]       = 2.f * br[tid];
        sbr[tid + 128] = 2.f * br[tid + 128];
        if (tid < 64)  sbr[tid + 256] = 2.f * br[tid + 256];
        else           sbr[(tid - 64) + 320] = 2.f * br[(tid - 64) + 320];
    }
    if (tid < 128) {
        int r = tid >> 4, n = tid & 15;
        size_t row = (size_t)(row0 + r);
        gsm[tid] = g_g[0][row*N_ + n] + g_g[1][row*N_ + n];
    }
    __syncthreads();

    #pragma unroll
    for (int i = 0; i < 12; i++) {
        int q = tid + i * 256;
        int r = q / E_, e = q - r * E_;
        const float* gv = &gsm[r*N_];
        float acc = sbr[e];
        #pragma unroll
        for (int nn = 0; nn < N_; nn++) acc += gv[nn] * sWr[nn*E_ + e];
        size_t row = (size_t)(row0 + r);
        float y = acc * g_gate[row*E_ + e];
        __nv_bfloat16 h = __float2bfloat16(y);
        g_xch[0][row*E_ + e] = h;
        g_xcl[0][row*E_ + e] = __float2bfloat16(y - __bfloat162float(h));
    }
}

// ---------------- K4b: out = tokens + y @ Wo + bo (cp.async double-buffer) ----------------
__global__ __launch_bounds__(256) void outmma_kernel(const float* __restrict__ tokens,
                                                     const float* __restrict__ bo,
                                                     float* __restrict__ out) {
    extern __shared__ char dynsm[];
    __nv_bfloat16* sAh = (__nv_bfloat16*)dynsm;
    __nv_bfloat16* sAl = sAh + 2*128*SW;
    __nv_bfloat16* sBh = sAl + 2*128*SW;
    __nv_bfloat16* sBl = sBh + 2*64*SW;

    int tid  = threadIdx.x;
    int wid  = tid >> 5;
    int lane = tid & 31;
    int grp  = lane >> 2;
    int qd   = lane & 3;
    int row0 = blockIdx.x * 128;
    int cb   = blockIdx.y * 64;
    int wm = (wid & 3) * 32;
    int wn = (wid >> 2) * 32;
    uint32_t aAh = smem_u32(sAh), aAl = smem_u32(sAl);
    uint32_t aBh = smem_u32(sBh), aBl = smem_u32(sBl);

    float acc[2][4][4];
    #pragma unroll
    for (int mi = 0; mi < 2; mi++)
        #pragma unroll
        for (int ni = 0; ni < 4; ni++)
            #pragma unroll
            for (int q = 0; q < 4; q++) acc[mi][ni][q] = 0.f;

    auto stage = [&](int p, int kt) {
        #pragma unroll
        for (int i = 0; i < 2; i++) {
            int q = tid + i * 256;
            int r = q >> 2, kc = (q & 3) * 8;
            const size_t go = (size_t)(row0 + r) * E_ + kt + kc;
            cp16(&sAh[p*128*SW + r*SW + kc], g_xch[0] + go);
            cp16(&sAl[p*128*SW + r*SW + kc], g_xcl[0] + go);
        }
        int r = tid >> 2, kc = (tid & 3) * 8;
        const size_t go = (size_t)(cb + r) * E_ + kt + kc;
        cp16(&sBh[p*64*SW + r*SW + kc], g_woh + go);
        cp16(&sBl[p*64*SW + r*SW + kc], g_wol + go);
    };

    stage(0, 0); CP_COMMIT();
    for (int it = 0; it < 12; it++) {
        int p = it & 1;
        if (it < 11) { stage(p ^ 1, (it + 1) * 32); CP_COMMIT(); CP_WAIT1(); }
        else CP_WAIT0();
        __syncthreads();
        uint32_t bAhp = aAh + p*128*SW*2, bAlp = aAl + p*128*SW*2;
        uint32_t bBhp = aBh + p*64*SW*2,  bBlp = aBl + p*64*SW*2;
        #pragma unroll
        for (int ks = 0; ks < 2; ks++) {
            int k0 = ks * 16;
            uint32_t ah[2][4], al[2][4], bh[8], bl[8];
            #pragma unroll
            for (int mi = 0; mi < 2; mi++) {
                lda_frag(ah[mi], bAhp, wm + mi*16, k0, lane);
                lda_frag(al[mi], bAlp, wm + mi*16, k0, lane);
            }
            #pragma unroll
            for (int pp = 0; pp < 2; pp++) {
                ldb_frag(&bh[pp*4], bBhp, wn + pp*16, k0, lane);
                ldb_frag(&bl[pp*4], bBlp, wn + pp*16, k0, lane);
            }
            #pragma unroll
            for (int mi = 0; mi < 2; mi++)
                #pragma unroll
                for (int ni = 0; ni < 4; ni++) {
                    mma16816(acc[mi][ni], ah[mi], &bh[ni*2]);
                    mma16816(acc[mi][ni], ah[mi], &bl[ni*2]);
                    mma16816(acc[mi][ni], al[mi], &bh[ni*2]);
                }
        }
        __syncthreads();
    }

    #pragma unroll
    for (int mi = 0; mi < 2; mi++) {
        #pragma unroll
        for (int ni = 0; ni < 4; ni++) {
            int c = cb + wn + ni * 8 + qd * 2;
            int r0 = row0 + wm + mi * 16 + grp;
            float2 bov = *(const float2*)&bo[c];
            #pragma unroll
            for (int h = 0; h < 2; h++) {
                int row = r0 + h * 8;
                float2 tk = *(const float2*)&tokens[(size_t)row * D_ + c];
                float2 o;
                o.x = tk.x + acc[mi][ni][h*2 + 0] + bov.x;
                o.y = tk.y + acc[mi][ni][h*2 + 1] + bov.y;
                *(float2*)&out[(size_t)row * D_ + c] = o;
            }
        }
    }
}

// ---------------- launch ----------------
#define DYN_SMEM_G1 81920
#define DYN_SMEM    61440

extern "C" void kernel_launch(void* const* d_in, const int* in_sizes, int n_in,
                              void* d_out, int out_size) {
    const float* tokens = (const float*)d_in[0];
    const float* norm_g = (const float*)d_in[1];
    const float* norm_b = (const float*)d_in[2];
    const float* Wx  = (const float*)d_in[3];
    const float* bx  = (const float*)d_in[4];
    const float* Wz  = (const float*)d_in[5];
    const float* bz  = (const float*)d_in[6];
    const float* cwf = (const float*)d_in[7];
    const float* cbf = (const float*)d_in[8];
    const float* cwb = (const float*)d_in[9];
    const float* cbb = (const float*)d_in[10];
    const float* WBf = (const float*)d_in[11];
    const float* bBf = (const float*)d_in[12];
    const float* WCf = (const float*)d_in[13];
    const float* bCf = (const float*)d_in[14];
    const float* WDf = (const float*)d_in[15];
    const float* bDf = (const float*)d_in[16];
    const float* WBb = (const float*)d_in[17];
    const float* bBb = (const float*)d_in[18];
    const float* WCb = (const float*)d_in[19];
    const float* bCb = (const float*)d_in[20];
    const float* WDb = (const float*)d_in[21];
    const float* bDb = (const float*)d_in[22];
    const float* A_log = (const float*)d_in[23];
    const float* Wi  = (const float*)d_in[24];
    const float* bi  = (const float*)d_in[25];
    const float* Wr  = (const float*)d_in[26];
    const float* br  = (const float*)d_in[27];
    const float* Wo  = (const float*)d_in[28];
    const float* bo  = (const float*)d_in[29];
    float* out = (float*)d_out;

    cudaFuncSetAttribute(gemm1_mma,      cudaFuncAttributeMaxDynamicSharedMemorySize, DYN_SMEM_G1);
    cudaFuncSetAttribute(projmma_kernel, cudaFuncAttributeMaxDynamicSharedMemorySize, DYN_SMEM);
    cudaFuncSetAttribute(outmma_kernel,  cudaFuncAttributeMaxDynamicSharedMemorySize, DYN_SMEM);

    ln_kernel<<<BJ_/8, 256>>>(tokens, norm_g, norm_b);
    wprep_all<<<1056, 256>>>(Wx, Wz, WBf, WCf, WDf, WBb, WCb, WDb, Wi, Wo);
    gemm1_mma<<<dim3(BJ_/128, 6), 256, DYN_SMEM_G1>>>(bx, bz);
    conv_kernel<<<BJ_/64, 384>>>(cwf, cbf, cwb, cbb);
    projmma_kernel<<<dim3(BJ_/128, 2), 256, DYN_SMEM>>>(bBf, bCf, bDf, bBb, bCb, bDb, A_log, bi);
    scan_kernel<<<dim3(B_, 2), 512>>>();
    y_kernel<<<BJ_/8, 256>>>(Wr, br);
    outmma_kernel<<<dim3(BJ_/128, 3), 256, DYN_SMEM>>>(tokens, bo, out);
}

// round 10
// speedup vs baseline: 2.7919x; 1.0112x over previous
#include <cuda_runtime.h>
#include <cuda_bf16.h>
#include <math.h>
#include <stdint.h>

#define B_ 32
#define J_ 1024
#define D_ 192
#define E_ 384
#define N_ 16
#define BJ_ (B_*J_)

// ---------------- device scratch (no allocs allowed) ----------------
__device__ __nv_bfloat16 g_th[BJ_*D_];     // LN output hi (bf16)
__device__ __nv_bfloat16 g_tl[BJ_*D_];     // LN output lo (bf16)
__device__ __nv_bfloat16 g_wht[768*D_];    // [Wx|Wz] transposed hi: [col][k]
__device__ __nv_bfloat16 g_wlt[768*D_];    // [Wx|Wz] transposed lo
__device__ float g_x[BJ_*E_];              // x = t@Wx + bx
__device__ float g_gate[BJ_*E_];           // sigmoid(silu(z))
__device__ __nv_bfloat16 g_xch[2][BJ_*E_]; // conv output hi ([0] reused as y hi)
__device__ __nv_bfloat16 g_xcl[2][BJ_*E_]; // conv output lo ([0] reused as y lo)
__device__ __nv_bfloat16 g_wph[2][64*E_];  // [dir][col][k] packed [WB|WC|WD|Wi] hi
__device__ __nv_bfloat16 g_wpl[2][64*E_];  // lo
__device__ __nv_bfloat16 g_woh[192*E_];    // Wo transposed hi: [d][k]
__device__ __nv_bfloat16 g_wol[192*E_];    // lo
__device__ float g_Abar[2][B_*N_*J_];      // [dir][b][n][s]
__device__ float g_Bu  [2][B_*N_*J_];
__device__ float g_Ct  [2][B_*N_*J_];
__device__ float g_g   [2][BJ_*N_];        // hs*Ct at ORIGINAL j

// ---------------- helpers ----------------
#define SW 40   // smem row stride in bf16 (80B: conflict-free for ldmatrix phases)

__device__ __forceinline__ uint32_t smem_u32(const void* p) {
    return (uint32_t)__cvta_generic_to_shared(p);
}
__device__ __forceinline__ void cp16(void* dst_smem, const void* src) {
    uint32_t d = smem_u32(dst_smem);
    asm volatile("cp.async.ca.shared.global [%0], [%1], 16;" :: "r"(d), "l"(src));
}
#define CP_COMMIT() asm volatile("cp.async.commit_group;" ::: "memory")
#define CP_WAIT1()  asm volatile("cp.async.wait_group 1;" ::: "memory")
#define CP_WAIT0()  asm volatile("cp.async.wait_group 0;" ::: "memory")

__device__ __forceinline__ void ldsm_x4(uint32_t* r, uint32_t addr) {
    asm volatile("ldmatrix.sync.aligned.m8n8.x4.shared.b16 {%0,%1,%2,%3}, [%4];"
        : "=r"(r[0]), "=r"(r[1]), "=r"(r[2]), "=r"(r[3]) : "r"(addr));
}
__device__ __forceinline__ void lda_frag(uint32_t* a, uint32_t sbase, int rb, int k0, int lane) {
    uint32_t addr = sbase + (uint32_t)((rb + (lane & 15)) * (SW*2) + k0*2 + ((lane >> 4) << 4));
    ldsm_x4(a, addr);
}
__device__ __forceinline__ void ldb_frag(uint32_t* b, uint32_t sbase, int nb_pair, int k0, int lane) {
    int sub = lane >> 3;
    int row = nb_pair + ((sub >> 1) << 3) + (lane & 7);
    uint32_t addr = sbase + (uint32_t)(row * (SW*2) + (k0 + ((sub & 1) << 3)) * 2);
    ldsm_x4(b, addr);
}
__device__ __forceinline__ void mma16816(float* c, const uint32_t* a, const uint32_t* b) {
    asm volatile(
        "mma.sync.aligned.m16n8k16.row.col.f32.bf16.bf16.f32 "
        "{%0,%1,%2,%3}, {%4,%5,%6,%7}, {%8,%9}, {%0,%1,%2,%3};"
        : "+f"(c[0]), "+f"(c[1]), "+f"(c[2]), "+f"(c[3])
        : "r"(a[0]), "r"(a[1]), "r"(a[2]), "r"(a[3]), "r"(b[0]), "r"(b[1]));
}

// ---------------- K0: merged LayerNorm + weight prep ----------------
__global__ void prep_kernel(const float* __restrict__ tok,
                            const float* __restrict__ gamma,
                            const float* __restrict__ beta,
                            const float* __restrict__ Wx, const float* __restrict__ Wz,
                            const float* __restrict__ WBf, const float* __restrict__ WCf,
                            const float* __restrict__ WDf, const float* __restrict__ WBb,
                            const float* __restrict__ WCb, const float* __restrict__ WDb,
                            const float* __restrict__ Wi,  const float* __restrict__ Wo) {
    if (blockIdx.x < BJ_/8) {
        // LayerNorm -> bf16 hi/lo
        int row  = blockIdx.x * 8 + (threadIdx.x >> 5);
        int lane = threadIdx.x & 31;
        const float* tr = tok + (size_t)row * D_;
        float v[6];
        float s = 0.f;
        #pragma unroll
        for (int i = 0; i < 6; i++) { v[i] = tr[lane + 32*i]; s += v[i]; }
        #pragma unroll
        for (int o = 16; o > 0; o >>= 1) s += __shfl_xor_sync(0xffffffffu, s, o);
        float mu = s * (1.f / D_);
        float vs = 0.f;
        #pragma unroll
        for (int i = 0; i < 6; i++) { float d = v[i] - mu; vs += d * d; }
        #pragma unroll
        for (int o = 16; o > 0; o >>= 1) vs += __shfl_xor_sync(0xffffffffu, vs, o);
        float inv = rsqrtf(vs * (1.f / D_) + 1e-5f);
        #pragma unroll
        for (int i = 0; i < 6; i++) {
            int c = lane + 32*i;
            float t = (v[i] - mu) * inv * gamma[c] + beta[c];
            __nv_bfloat16 h = __float2bfloat16(t);
            g_th[(size_t)row * D_ + c] = h;
            g_tl[(size_t)row * D_ + c] = __float2bfloat16(t - __bfloat162float(h));
        }
    } else {
        int i = (blockIdx.x - BJ_/8) * 256 + threadIdx.x;
        const int n1 = 768 * D_;
        const int n2 = n1 + 2 * 64 * E_;
        const int n3 = n2 + 192 * E_;
        if (i < n1) {
            int c = i / D_, k = i - c * D_;
            float w = (c < E_) ? Wx[(size_t)k * E_ + c] : Wz[(size_t)k * E_ + (c - E_)];
            __nv_bfloat16 h = __float2bfloat16(w);
            g_wht[i] = h;
            g_wlt[i] = __float2bfloat16(w - __bfloat162float(h));
        } else if (i < n2) {
            int q = i - n1;
            int dir = q / (64 * E_);
            int rem = q - dir * 64 * E_;
            int c = rem / E_, k = rem - c * E_;
            int m = c >> 4, n = c & 15;
            const float* W;
            if (m == 0) W = dir ? WBb : WBf;
            else if (m == 1) W = dir ? WCb : WCf;
            else if (m == 2) W = dir ? WDb : WDf;
            else W = Wi;
            float w = W[(size_t)k * N_ + n];
            __nv_bfloat16 h = __float2bfloat16(w);
            g_wph[dir][rem] = h;
            g_wpl[dir][rem] = __float2bfloat16(w - __bfloat162float(h));
        } else if (i < n3) {
            int q = i - n2;
            int d = q / E_, k = q - d * E_;
            float w = Wo[(size_t)k * D_ + d];
            __nv_bfloat16 h = __float2bfloat16(w);
            g_woh[q] = h;
            g_wol[q] = __float2bfloat16(w - __bfloat162float(h));
        }
    }
}

// ---------------- K1: HMMA dual GEMM, 128x128 tiles over packed 768 cols ----------------
__global__ __launch_bounds__(256) void gemm1_mma(const float* __restrict__ bxv,
                                                 const float* __restrict__ bzv) {
    extern __shared__ char dynsm[];
    __nv_bfloat16* sAh = (__nv_bfloat16*)dynsm;      // [2][128*SW]
    __nv_bfloat16* sAl = sAh + 2*128*SW;
    __nv_bfloat16* sBh = sAl + 2*128*SW;             // [2][128*SW]
    __nv_bfloat16* sBl = sBh + 2*128*SW;

    int tid  = threadIdx.x;
    int wid  = tid >> 5;
    int lane = tid & 31;
    int grp  = lane >> 2;
    int qd   = lane & 3;
    int row0 = blockIdx.x * 128;
    int c0   = blockIdx.y * 128;          // packed col base (0..767)
    int isZ  = (c0 >= E_);
    int wm = (wid & 3) * 32;
    int wn = (wid >> 2) * 32;
    uint32_t aAh = smem_u32(sAh), aAl = smem_u32(sAl);
    uint32_t aBh = smem_u32(sBh), aBl = smem_u32(sBl);

    float acc[2][2][4][4];
    #pragma unroll
    for (int mi = 0; mi < 2; mi++)
        #pragma unroll
        for (int nh = 0; nh < 2; nh++)
            #pragma unroll
            for (int ni = 0; ni < 4; ni++)
                #pragma unroll
                for (int q = 0; q < 4; q++) acc[mi][nh][ni][q] = 0.f;

    auto stage = [&](int p, int kt) {
        #pragma unroll
        for (int i = 0; i < 2; i++) {
            int q = tid + i * 256;
            int r = q >> 2, kc = (q & 3) * 8;
            const size_t ga = (size_t)(row0 + r) * D_ + kt + kc;
            cp16(&sAh[p*128*SW + r*SW + kc], g_th + ga);
            cp16(&sAl[p*128*SW + r*SW + kc], g_tl + ga);
            const size_t gb = (size_t)(c0 + r) * D_ + kt + kc;
            cp16(&sBh[p*128*SW + r*SW + kc], g_wht + gb);
            cp16(&sBl[p*128*SW + r*SW + kc], g_wlt + gb);
        }
    };

    stage(0, 0); CP_COMMIT();
    for (int it = 0; it < 6; it++) {
        int p = it & 1;
        if (it < 5) { stage(p ^ 1, (it + 1) * 32); CP_COMMIT(); CP_WAIT1(); }
        else CP_WAIT0();
        __syncthreads();
        uint32_t bAh = aAh + p*128*SW*2, bAl = aAl + p*128*SW*2;
        uint32_t bBh = aBh + p*128*SW*2, bBl = aBl + p*128*SW*2;
        #pragma unroll
        for (int ks = 0; ks < 2; ks++) {
            int k0 = ks * 16;
            uint32_t ah[2][4], al[2][4];
            #pragma unroll
            for (int mi = 0; mi < 2; mi++) {
                lda_frag(ah[mi], bAh, wm + mi*16, k0, lane);
                lda_frag(al[mi], bAl, wm + mi*16, k0, lane);
            }
            #pragma unroll
            for (int nh = 0; nh < 2; nh++) {
                uint32_t bh[8], bl[8];
                #pragma unroll
                for (int pp = 0; pp < 2; pp++) {
                    ldb_frag(&bh[pp*4], bBh, nh*64 + wn + pp*16, k0, lane);
                    ldb_frag(&bl[pp*4], bBl, nh*64 + wn + pp*16, k0, lane);
                }
                #pragma unroll
                for (int mi = 0; mi < 2; mi++)
                    #pragma unroll
                    for (int ni = 0; ni < 4; ni++) {
                        mma16816(acc[mi][nh][ni], ah[mi], &bh[ni*2]);
                        mma16816(acc[mi][nh][ni], ah[mi], &bl[ni*2]);
                        mma16816(acc[mi][nh][ni], al[mi], &bh[ni*2]);
                    }
            }
        }
        __syncthreads();
    }

    #pragma unroll
    for (int mi = 0; mi < 2; mi++) {
        #pragma unroll
        for (int nh = 0; nh < 2; nh++) {
            #pragma unroll
            for (int ni = 0; ni < 4; ni++) {
                int cpk = c0 + nh*64 + wn + ni * 8 + qd * 2;
                int r0 = row0 + wm + mi * 16 + grp;
                #pragma unroll
                for (int h = 0; h < 2; h++) {
                    int row = r0 + h * 8;
                    float v0 = acc[mi][nh][ni][h*2 + 0];
                    float v1 = acc[mi][nh][ni][h*2 + 1];
                    if (!isZ) {
                        float2 o;
                        o.x = v0 + bxv[cpk];
                        o.y = v1 + bxv[cpk + 1];
                        *(float2*)&g_x[(size_t)row * E_ + cpk] = o;
                    } else {
                        int c = cpk - E_;
                        float zc, sl;
                        float2 o;
                        zc = v0 + bzv[c];     sl = zc / (1.f + __expf(-zc)); o.x = 1.f / (1.f + __expf(-sl));
                        zc = v1 + bzv[c + 1]; sl = zc / (1.f + __expf(-zc)); o.y = 1.f / (1.f + __expf(-sl));
                        *(float2*)&g_gate[(size_t)row * E_ + c] = o;
                    }
                }
            }
        }
    }
}

// ---------------- K2a: depthwise conv — register weights, rolling window ----------------
__global__ __launch_bounds__(384) void conv_kernel(
        const float* __restrict__ cwf, const float* __restrict__ cbf,
        const float* __restrict__ cwb, const float* __restrict__ cbb) {
    __shared__ float swf[3][E_], swb[3][E_], sbf[E_], sbb[E_];
    int tid = threadIdx.x;

    for (int i = tid; i < 3*E_; i += 384) {
        int e = i / 3, t = i - e*3;
        swf[t][e] = cwf[i];
        swb[t][e] = cwb[i];
    }
    if (tid < E_) { sbf[tid] = cbf[tid]; sbb[tid] = cbb[tid]; }
    __syncthreads();

    int strip = tid / 96;
    int eg    = tid - strip * 96;
    int e     = eg * 4;
    int rowbase = blockIdx.x * 64 + strip * 16;
    int b  = rowbase >> 10;
    int j0 = rowbase & (J_ - 1);

    float wf[3][4], wb[3][4], bfv[4], bbv[4];
    #pragma unroll
    for (int t = 0; t < 3; t++) {
        *(float4*)wf[t] = *(const float4*)&swf[t][e];
        *(float4*)wb[t] = *(const float4*)&swb[t][e];
    }
    *(float4*)bfv = *(const float4*)&sbf[e];
    *(float4*)bbv = *(const float4*)&sbb[e];

    const float* xp = g_x + (size_t)rowbase * E_ + e;
    float x0[4], x1[4], x2[4];
    if (j0 > 0) *(float4*)x0 = *(const float4*)(xp - E_);
    else { x0[0] = x0[1] = x0[2] = x0[3] = 0.f; }
    *(float4*)x1 = *(const float4*)xp;

    #pragma unroll
    for (int r = 0; r < 16; r++) {
        int j = j0 + r;
        if (j < J_ - 1) *(float4*)x2 = *(const float4*)(xp + E_);
        else { x2[0] = x2[1] = x2[2] = x2[3] = 0.f; }

        __nv_bfloat16 fh[4], fl[4], bh[4], bl[4];
        #pragma unroll
        for (int q = 0; q < 4; q++) {
            float vf = wf[0][q]*x0[q] + wf[1][q]*x1[q] + wf[2][q]*x2[q] + bfv[q];
            float vb = wb[0][q]*x2[q] + wb[1][q]*x1[q] + wb[2][q]*x0[q] + bbv[q];
            fh[q] = __float2bfloat16(vf); fl[q] = __float2bfloat16(vf - __bfloat162float(fh[q]));
            bh[q] = __float2bfloat16(vb); bl[q] = __float2bfloat16(vb - __bfloat162float(bh[q]));
        }
        size_t of = (size_t)(b * J_ + j) * E_ + e;
        size_t ob = (size_t)(b * J_ + (J_ - 1 - j)) * E_ + e;
        *(uint2*)&g_xch[0][of] = *(uint2*)fh;
        *(uint2*)&g_xcl[0][of] = *(uint2*)fl;
        *(uint2*)&g_xch[1][ob] = *(uint2*)bh;
        *(uint2*)&g_xcl[1][ob] = *(uint2*)bl;

        #pragma unroll
        for (int q = 0; q < 4; q++) { x0[q] = x1[q]; x1[q] = x2[q]; }
        xp += E_;
    }
}

// ---------------- K2b: proj MMA + ZOH epilogue (cp.async double-buffer) ----------------
#define EPS 65
__global__ __launch_bounds__(256) void projmma_kernel(
        const float* __restrict__ bBf, const float* __restrict__ bCf,
        const float* __restrict__ bDf, const float* __restrict__ bBb,
        const float* __restrict__ bCb, const float* __restrict__ bDb,
        const float* __restrict__ A_log, const float* __restrict__ bi) {
    extern __shared__ char dynsm[];
    __nv_bfloat16* sAh = (__nv_bfloat16*)dynsm;
    __nv_bfloat16* sAl = sAh + 2*128*SW;
    __nv_bfloat16* sBh = sAl + 2*128*SW;
    __nv_bfloat16* sBl = sBh + 2*64*SW;
    float* ep = (float*)dynsm;                 // epilogue overlay (33280 B)
    __shared__ float sbias[4][N_];
    __shared__ float sAn[N_], sInv[N_];

    int tid  = threadIdx.x;
    int wid  = tid >> 5;
    int lane = tid & 31;
    int row0 = blockIdx.x * 128;
    int dir  = blockIdx.y;
    int b    = row0 >> 10;
    int s0   = row0 & (J_ - 1);
    int wm = (wid & 3) * 32;
    int wn = (wid >> 2) * 32;
    int grp  = lane >> 2;
    int qd   = lane & 3;
    uint32_t aAh = smem_u32(sAh), aAl = smem_u32(sAl);
    uint32_t aBh = smem_u32(sBh), aBl = smem_u32(sBl);

    if (tid < N_) {
        int n = tid;
        sbias[0][n] = dir ? bBb[n] : bBf[n];
        sbias[1][n] = dir ? bCb[n] : bCf[n];
        sbias[2][n] = dir ? bDb[n] : bDf[n];
        sbias[3][n] = bi[n];
        float al = A_log[n];
        float An = -log1pf(expf(al));
        sAn[n] = An;
        sInv[n] = 1.f / (An + 1e-6f);
    }

    const __nv_bfloat16* Ah = g_xch[dir];
    const __nv_bfloat16* Al = g_xcl[dir];
    const __nv_bfloat16* Bh = g_wph[dir];
    const __nv_bfloat16* Bl = g_wpl[dir];

    float acc[2][4][4];
    #pragma unroll
    for (int mi = 0; mi < 2; mi++)
        #pragma unroll
        for (int ni = 0; ni < 4; ni++)
            #pragma unroll
            for (int q = 0; q < 4; q++) acc[mi][ni][q] = 0.f;

    auto stage = [&](int p, int kt) {
        #pragma unroll
        for (int i = 0; i < 2; i++) {
            int q = tid + i * 256;
            int r = q >> 2, kc = (q & 3) * 8;
            const size_t go = (size_t)(row0 + r) * E_ + kt + kc;
            cp16(&sAh[p*128*SW + r*SW + kc], Ah + go);
            cp16(&sAl[p*128*SW + r*SW + kc], Al + go);
        }
        int r = tid >> 2, kc = (tid & 3) * 8;
        const size_t go = (size_t)r * E_ + kt + kc;
        cp16(&sBh[p*64*SW + r*SW + kc], Bh + go);
        cp16(&sBl[p*64*SW + r*SW + kc], Bl + go);
    };

    stage(0, 0); CP_COMMIT();
    for (int it = 0; it < 12; it++) {
        int p = it & 1;
        if (it < 11) { stage(p ^ 1, (it + 1) * 32); CP_COMMIT(); CP_WAIT1(); }
        else CP_WAIT0();
        __syncthreads();
        uint32_t bAhp = aAh + p*128*SW*2, bAlp = aAl + p*128*SW*2;
        uint32_t bBhp = aBh + p*64*SW*2,  bBlp = aBl + p*64*SW*2;
        #pragma unroll
        for (int ks = 0; ks < 2; ks++) {
            int k0 = ks * 16;
            uint32_t ah[2][4], al[2][4], bh[8], bl[8];
            #pragma unroll
            for (int mi = 0; mi < 2; mi++) {
                lda_frag(ah[mi], bAhp, wm + mi*16, k0, lane);
                lda_frag(al[mi], bAlp, wm + mi*16, k0, lane);
            }
            #pragma unroll
            for (int pp = 0; pp < 2; pp++) {
                ldb_frag(&bh[pp*4], bBhp, wn + pp*16, k0, lane);
                ldb_frag(&bl[pp*4], bBlp, wn + pp*16, k0, lane);
            }
            #pragma unroll
            for (int mi = 0; mi < 2; mi++)
                #pragma unroll
                for (int ni = 0; ni < 4; ni++) {
                    mma16816(acc[mi][ni], ah[mi], &bh[ni*2]);
                    mma16816(acc[mi][ni], ah[mi], &bl[ni*2]);
                    mma16816(acc[mi][ni], al[mi], &bh[ni*2]);
                }
        }
        __syncthreads();
    }

    #pragma unroll
    for (int mi = 0; mi < 2; mi++)
        #pragma unroll
        for (int ni = 0; ni < 4; ni++) {
            int c = wn + ni * 8 + qd * 2;
            int r0 = wm + mi * 16 + grp;
            #pragma unroll
            for (int h = 0; h < 2; h++) {
                ep[(r0 + h*8)*EPS + c    ] = acc[mi][ni][h*2 + 0];
                ep[(r0 + h*8)*EPS + c + 1] = acc[mi][ni][h*2 + 1];
            }
        }
    __syncthreads();

    #pragma unroll
    for (int it = 0; it < 8; it++) {
        int idx = tid + it * 256;
        int s = idx & 127;
        int n = idx >> 7;
        float bt  = ep[s*EPS + n     ] + sbias[0][n];
        float ct  = ep[s*EPS + n + 16] + sbias[1][n];
        float dtr = ep[s*EPS + n + 32] + sbias[2][n];
        float u   = ep[s*EPS + n + 48] + sbias[3][n];
        float An  = sAn[n];
        float dt  = (dtr > 20.f) ? dtr : log1pf(__expf(dtr));
        float abar = __expf(dt * An);
        float bu = (abar - 1.f) * sInv[n] * bt * u;
        size_t base = (size_t)(b*N_ + n) * J_ + s0 + s;
        g_Abar[dir][base] = abar;
        g_Bu[dir][base]   = bu;
        g_Ct[dir][base]   = ct;
    }
}

// ---------------- K3: blocked segmented scan (8 elems/lane) ----------------
__global__ __launch_bounds__(512) void scan_kernel() {
    int b   = blockIdx.x;
    int dir = blockIdx.y;
    int w    = threadIdx.x >> 5;
    int lane = threadIdx.x & 31;
    size_t base = (size_t)(b*N_ + w) * J_;
    const float* Aa = g_Abar[dir] + base;
    const float* Bu = g_Bu[dir]   + base;
    const float* Ct = g_Ct[dir]   + base;
    float carry = 0.f;
    #pragma unroll
    for (int seg = 0; seg < 4; seg++) {
        int s = seg*256 + lane*8;
        float a[8], bu[8];
        *(float4*)&a[0]  = *(const float4*)(Aa + s);
        *(float4*)&a[4]  = *(const float4*)(Aa + s + 4);
        *(float4*)&bu[0] = *(const float4*)(Bu + s);
        *(float4*)&bu[4] = *(const float4*)(Bu + s + 4);
        #pragma unroll
        for (int i = 1; i < 8; i++) { bu[i] = fmaf(a[i], bu[i-1], bu[i]); a[i] *= a[i-1]; }
        float As = a[7], Bs = bu[7];
        #pragma unroll
        for (int off = 1; off < 32; off <<= 1) {
            float ap = __shfl_up_sync(0xffffffffu, As, off);
            float bp = __shfl_up_sync(0xffffffffu, Bs, off);
            if (lane >= off) { Bs = fmaf(As, bp, Bs); As *= ap; }
        }
        float Ae = __shfl_up_sync(0xffffffffu, As, 1);
        float Be = __shfl_up_sync(0xffffffffu, Bs, 1);
        float Hprev = (lane == 0) ? carry : fmaf(Ae, carry, Be);
        float ct[8];
        *(float4*)&ct[0] = *(const float4*)(Ct + s);
        *(float4*)&ct[4] = *(const float4*)(Ct + s + 4);
        float hlast = 0.f;
        #pragma unroll
        for (int i = 0; i < 8; i++) {
            float h = fmaf(a[i], Hprev, bu[i]);
            if (i == 7) hlast = h;
            int sg = s + i;
            int jorig = dir ? (J_ - 1 - sg) : sg;
            g_g[dir][(size_t)(b*J_ + jorig) * N_ + w] = h * ct[i];
        }
        carry = __shfl_sync(0xffffffffu, hlast, 31);
    }
}

// ---------------- K4a: y = (gsum@Wr + 2br) * gate -> bf16 hi/lo ----------------
__global__ __launch_bounds__(256) void y_kernel(const float* __restrict__ Wr,
                                                const float* __restrict__ br) {
    __shared__ float sWr[N_*E_];
    __shared__ float sbr[E_];
    __shared__ float gsm[8*N_];
    int tid = threadIdx.x;
    int row0 = blockIdx.x * 8;

    #pragma unroll
    for (int i = 0; i < 24; i++) sWr[tid + i*256] = Wr[tid + i*256];
    if (tid < 128) {
        sbr[tid]       = 2.f * br[tid];
        sbr[tid + 128] = 2.f * br[tid + 128];
        if (tid < 64)  sbr[tid + 256] = 2.f * br[tid + 256];
        else           sbr[(tid - 64) + 320] = 2.f * br[(tid - 64) + 320];
    }
    if (tid < 128) {
        int r = tid >> 4, n = tid & 15;
        size_t row = (size_t)(row0 + r);
        gsm[tid] = g_g[0][row*N_ + n] + g_g[1][row*N_ + n];
    }
    __syncthreads();

    #pragma unroll
    for (int i = 0; i < 12; i++) {
        int q = tid + i * 256;
        int r = q / E_, e = q - r * E_;
        const float* gv = &gsm[r*N_];
        float acc = sbr[e];
        #pragma unroll
        for (int nn = 0; nn < N_; nn++) acc += gv[nn] * sWr[nn*E_ + e];
        size_t row = (size_t)(row0 + r);
        float y = acc * g_gate[row*E_ + e];
        __nv_bfloat16 h = __float2bfloat16(y);
        g_xch[0][row*E_ + e] = h;
        g_xcl[0][row*E_ + e] = __float2bfloat16(y - __bfloat162float(h));
    }
}

// ---------------- K4b: out = tokens + y @ Wo + bo — full 192-col tile per block ----------------
__global__ __launch_bounds__(256) void outmma_kernel(const float* __restrict__ tokens,
                                                     const float* __restrict__ bo,
                                                     float* __restrict__ out) {
    extern __shared__ char dynsm[];
    __nv_bfloat16* sAh = (__nv_bfloat16*)dynsm;          // [2][128*SW]
    __nv_bfloat16* sAl = sAh + 2*128*SW;
    __nv_bfloat16* sBh = sAl + 2*128*SW;                 // [2][192*SW]
    __nv_bfloat16* sBl = sBh + 2*192*SW;

    int tid  = threadIdx.x;
    int wid  = tid >> 5;
    int lane = tid & 31;
    int grp  = lane >> 2;
    int qd   = lane & 3;
    int row0 = blockIdx.x * 128;
    int wm = (wid & 1) * 64;      // 2 row halves, 64 rows each -> mi 0..3
    int wn = (wid >> 1) * 48;     // 4 col quarters, 48 cols each -> ni 0..5
    uint32_t aAh = smem_u32(sAh), aAl = smem_u32(sAl);
    uint32_t aBh = smem_u32(sBh), aBl = smem_u32(sBl);

    float acc[4][6][4];
    #pragma unroll
    for (int mi = 0; mi < 4; mi++)
        #pragma unroll
        for (int ni = 0; ni < 6; ni++)
            #pragma unroll
            for (int q = 0; q < 4; q++) acc[mi][ni][q] = 0.f;

    auto stage = [&](int p, int kt) {
        #pragma unroll
        for (int i = 0; i < 2; i++) {
            int q = tid + i * 256;
            int r = q >> 2, kc = (q & 3) * 8;
            const size_t go = (size_t)(row0 + r) * E_ + kt + kc;
            cp16(&sAh[p*128*SW + r*SW + kc], g_xch[0] + go);
            cp16(&sAl[p*128*SW + r*SW + kc], g_xcl[0] + go);
        }
        #pragma unroll
        for (int i = 0; i < 3; i++) {
            int q = tid + i * 256;
            int r = q >> 2, kc = (q & 3) * 8;
            const size_t go = (size_t)r * E_ + kt + kc;
            cp16(&sBh[p*192*SW + r*SW + kc], g_woh + go);
            cp16(&sBl[p*192*SW + r*SW + kc], g_wol + go);
        }
    };

    stage(0, 0); CP_COMMIT();
    for (int it = 0; it < 12; it++) {
        int p = it & 1;
        if (it < 11) { stage(p ^ 1, (it + 1) * 32); CP_COMMIT(); CP_WAIT1(); }
        else CP_WAIT0();
        __syncthreads();
        uint32_t bAhp = aAh + p*128*SW*2, bAlp = aAl + p*128*SW*2;
        uint32_t bBhp = aBh + p*192*SW*2, bBlp = aBl + p*192*SW*2;
        #pragma unroll
        for (int ks = 0; ks < 2; ks++) {
            int k0 = ks * 16;
            uint32_t ah[4][4], al[4][4];
            #pragma unroll
            for (int mi = 0; mi < 4; mi++) {
                lda_frag(ah[mi], bAhp, wm + mi*16, k0, lane);
                lda_frag(al[mi], bAlp, wm + mi*16, k0, lane);
            }
            #pragma unroll
            for (int pp = 0; pp < 3; pp++) {
                uint32_t bh[4], bl[4];
                ldb_frag(bh, bBhp, wn + pp*16, k0, lane);
                ldb_frag(bl, bBlp, wn + pp*16, k0, lane);
                #pragma unroll
                for (int mi = 0; mi < 4; mi++)
                    #pragma unroll
                    for (int nn = 0; nn < 2; nn++) {
                        int ni = pp*2 + nn;
                        mma16816(acc[mi][ni], ah[mi], &bh[nn*2]);
                        mma16816(acc[mi][ni], ah[mi], &bl[nn*2]);
                        mma16816(acc[mi][ni], al[mi], &bh[nn*2]);
                    }
            }
        }
        __syncthreads();
    }

    #pragma unroll
    for (int mi = 0; mi < 4; mi++) {
        #pragma unroll
        for (int ni = 0; ni < 6; ni++) {
            int c = wn + ni * 8 + qd * 2;
            int r0 = row0 + wm + mi * 16 + grp;
            float2 bov = *(const float2*)&bo[c];
            #pragma unroll
            for (int h = 0; h < 2; h++) {
                int row = r0 + h * 8;
                float2 tk = *(const float2*)&tokens[(size_t)row * D_ + c];
                float2 o;
                o.x = tk.x + acc[mi][ni][h*2 + 0] + bov.x;
                o.y = tk.y + acc[mi][ni][h*2 + 1] + bov.y;
                *(float2*)&out[(size_t)row * D_ + c] = o;
            }
        }
    }
}

// ---------------- launch ----------------
#define DYN_SMEM_G1  81920
#define DYN_SMEM     61440
#define DYN_SMEM_OUT 102400

extern "C" void kernel_launch(void* const* d_in, const int* in_sizes, int n_in,
                              void* d_out, int out_size) {
    const float* tokens = (const float*)d_in[0];
    const float* norm_g = (const float*)d_in[1];
    const float* norm_b = (const float*)d_in[2];
    const float* Wx  = (const float*)d_in[3];
    const float* bx  = (const float*)d_in[4];
    const float* Wz  = (const float*)d_in[5];
    const float* bz  = (const float*)d_in[6];
    const float* cwf = (const float*)d_in[7];
    const float* cbf = (const float*)d_in[8];
    const float* cwb = (const float*)d_in[9];
    const float* cbb = (const float*)d_in[10];
    const float* WBf = (const float*)d_in[11];
    const float* bBf = (const float*)d_in[12];
    const float* WCf = (const float*)d_in[13];
    const float* bCf = (const float*)d_in[14];
    const float* WDf = (const float*)d_in[15];
    const float* bDf = (const float*)d_in[16];
    const float* WBb = (const float*)d_in[17];
    const float* bBb = (const float*)d_in[18];
    const float* WCb = (const float*)d_in[19];
    const float* bCb = (const float*)d_in[20];
    const float* WDb = (const float*)d_in[21];
    const float* bDb = (const float*)d_in[22];
    const float* A_log = (const float*)d_in[23];
    const float* Wi  = (const float*)d_in[24];
    const float* bi  = (const float*)d_in[25];
    const float* Wr  = (const float*)d_in[26];
    const float* br  = (const float*)d_in[27];
    const float* Wo  = (const float*)d_in[28];
    const float* bo  = (const float*)d_in[29];
    float* out = (float*)d_out;

    cudaFuncSetAttribute(gemm1_mma,      cudaFuncAttributeMaxDynamicSharedMemorySize, DYN_SMEM_G1);
    cudaFuncSetAttribute(projmma_kernel, cudaFuncAttributeMaxDynamicSharedMemorySize, DYN_SMEM);
    cudaFuncSetAttribute(outmma_kernel,  cudaFuncAttributeMaxDynamicSharedMemorySize, DYN_SMEM_OUT);

    prep_kernel<<<BJ_/8 + 1056, 256>>>(tokens, norm_g, norm_b, Wx, Wz,
                                       WBf, WCf, WDf, WBb, WCb, WDb, Wi, Wo);
    gemm1_mma<<<dim3(BJ_/128, 6), 256, DYN_SMEM_G1>>>(bx, bz);
    conv_kernel<<<BJ_/64, 384>>>(cwf, cbf, cwb, cbb);
    projmma_kernel<<<dim3(BJ_/128, 2), 256, DYN_SMEM>>>(bBf, bCf, bDf, bBb, bCb, bDb, A_log, bi);
    scan_kernel<<<dim3(B_, 2), 512>>>();
    y_kernel<<<BJ_/8, 256>>>(Wr, br);
    outmma_kernel<<<BJ_/128, 256, DYN_SMEM_OUT>>>(tokens, bo, out);
}

// round 11
// speedup vs baseline: 2.8080x; 1.0058x over previous
#include <cuda_runtime.h>
#include <cuda_bf16.h>
#include <math.h>
#include <stdint.h>

#define B_ 32
#define J_ 1024
#define D_ 192
#define E_ 384
#define N_ 16
#define BJ_ (B_*J_)

// ---------------- device scratch (no allocs allowed) ----------------
__device__ __nv_bfloat16 g_th[BJ_*D_];     // LN output hi (bf16)
__device__ __nv_bfloat16 g_tl[BJ_*D_];     // LN output lo (bf16)
__device__ __nv_bfloat16 g_wht[768*D_];    // [Wx|Wz] transposed hi: [col][k]
__device__ __nv_bfloat16 g_wlt[768*D_];    // [Wx|Wz] transposed lo
__device__ float g_x[BJ_*E_];              // x = t@Wx + bx
__device__ float g_gate[BJ_*E_];           // sigmoid(silu(z))
__device__ __nv_bfloat16 g_xch[2][BJ_*E_]; // conv output hi ([0] reused as y hi)
__device__ __nv_bfloat16 g_xcl[2][BJ_*E_]; // conv output lo ([0] reused as y lo)
__device__ __nv_bfloat16 g_wph[2][64*E_];  // [dir][col][k] packed [WB|WC|WD|Wi] hi
__device__ __nv_bfloat16 g_wpl[2][64*E_];  // lo
__device__ __nv_bfloat16 g_woh[192*E_];    // Wo transposed hi: [d][k]
__device__ __nv_bfloat16 g_wol[192*E_];    // lo
__device__ float g_Abar[2][B_*N_*J_];      // [dir][b][n][s]
__device__ float g_Bu  [2][B_*N_*J_];
__device__ float g_Ct  [2][B_*N_*J_];
__device__ float g_g   [2][BJ_*N_];        // hs*Ct at ORIGINAL j

// ---------------- helpers ----------------
#define SW 40   // smem row stride in bf16 (80B: conflict-free for ldmatrix phases)

__device__ __forceinline__ uint32_t smem_u32(const void* p) {
    return (uint32_t)__cvta_generic_to_shared(p);
}
__device__ __forceinline__ void cp16(void* dst_smem, const void* src) {
    uint32_t d = smem_u32(dst_smem);
    asm volatile("cp.async.ca.shared.global [%0], [%1], 16;" :: "r"(d), "l"(src));
}
#define CP_COMMIT() asm volatile("cp.async.commit_group;" ::: "memory")
#define CP_WAIT1()  asm volatile("cp.async.wait_group 1;" ::: "memory")
#define CP_WAIT0()  asm volatile("cp.async.wait_group 0;" ::: "memory")

__device__ __forceinline__ void ldsm_x4(uint32_t* r, uint32_t addr) {
    asm volatile("ldmatrix.sync.aligned.m8n8.x4.shared.b16 {%0,%1,%2,%3}, [%4];"
        : "=r"(r[0]), "=r"(r[1]), "=r"(r[2]), "=r"(r[3]) : "r"(addr));
}
__device__ __forceinline__ void lda_frag(uint32_t* a, uint32_t sbase, int rb, int k0, int lane) {
    uint32_t addr = sbase + (uint32_t)((rb + (lane & 15)) * (SW*2) + k0*2 + ((lane >> 4) << 4));
    ldsm_x4(a, addr);
}
__device__ __forceinline__ void ldb_frag(uint32_t* b, uint32_t sbase, int nb_pair, int k0, int lane) {
    int sub = lane >> 3;
    int row = nb_pair + ((sub >> 1) << 3) + (lane & 7);
    uint32_t addr = sbase + (uint32_t)(row * (SW*2) + (k0 + ((sub & 1) << 3)) * 2);
    ldsm_x4(b, addr);
}
__device__ __forceinline__ void mma16816(float* c, const uint32_t* a, const uint32_t* b) {
    asm volatile(
        "mma.sync.aligned.m16n8k16.row.col.f32.bf16.bf16.f32 "
        "{%0,%1,%2,%3}, {%4,%5,%6,%7}, {%8,%9}, {%0,%1,%2,%3};"
        : "+f"(c[0]), "+f"(c[1]), "+f"(c[2]), "+f"(c[3])
        : "r"(a[0]), "r"(a[1]), "r"(a[2]), "r"(a[3]), "r"(b[0]), "r"(b[1]));
}

// ---------------- K0: merged LayerNorm + weight prep ----------------
__global__ void prep_kernel(const float* __restrict__ tok,
                            const float* __restrict__ gamma,
                            const float* __restrict__ beta,
                            const float* __restrict__ Wx, const float* __restrict__ Wz,
                            const float* __restrict__ WBf, const float* __restrict__ WCf,
                            const float* __restrict__ WDf, const float* __restrict__ WBb,
                            const float* __restrict__ WCb, const float* __restrict__ WDb,
                            const float* __restrict__ Wi,  const float* __restrict__ Wo) {
    if (blockIdx.x < BJ_/8) {
        // LayerNorm -> bf16 hi/lo
        int row  = blockIdx.x * 8 + (threadIdx.x >> 5);
        int lane = threadIdx.x & 31;
        const float* tr = tok + (size_t)row * D_;
        float v[6];
        float s = 0.f;
        #pragma unroll
        for (int i = 0; i < 6; i++) { v[i] = tr[lane + 32*i]; s += v[i]; }
        #pragma unroll
        for (int o = 16; o > 0; o >>= 1) s += __shfl_xor_sync(0xffffffffu, s, o);
        float mu = s * (1.f / D_);
        float vs = 0.f;
        #pragma unroll
        for (int i = 0; i < 6; i++) { float d = v[i] - mu; vs += d * d; }
        #pragma unroll
        for (int o = 16; o > 0; o >>= 1) vs += __shfl_xor_sync(0xffffffffu, vs, o);
        float inv = rsqrtf(vs * (1.f / D_) + 1e-5f);
        #pragma unroll
        for (int i = 0; i < 6; i++) {
            int c = lane + 32*i;
            float t = (v[i] - mu) * inv * gamma[c] + beta[c];
            __nv_bfloat16 h = __float2bfloat16(t);
            g_th[(size_t)row * D_ + c] = h;
            g_tl[(size_t)row * D_ + c] = __float2bfloat16(t - __bfloat162float(h));
        }
    } else {
        int i = (blockIdx.x - BJ_/8) * 256 + threadIdx.x;
        const int n1 = 768 * D_;
        const int n2 = n1 + 2 * 64 * E_;
        const int n3 = n2 + 192 * E_;
        if (i < n1) {
            int c = i / D_, k = i - c * D_;
            float w = (c < E_) ? Wx[(size_t)k * E_ + c] : Wz[(size_t)k * E_ + (c - E_)];
            __nv_bfloat16 h = __float2bfloat16(w);
            g_wht[i] = h;
            g_wlt[i] = __float2bfloat16(w - __bfloat162float(h));
        } else if (i < n2) {
            int q = i - n1;
            int dir = q / (64 * E_);
            int rem = q - dir * 64 * E_;
            int c = rem / E_, k = rem - c * E_;
            int m = c >> 4, n = c & 15;
            const float* W;
            if (m == 0) W = dir ? WBb : WBf;
            else if (m == 1) W = dir ? WCb : WCf;
            else if (m == 2) W = dir ? WDb : WDf;
            else W = Wi;
            float w = W[(size_t)k * N_ + n];
            __nv_bfloat16 h = __float2bfloat16(w);
            g_wph[dir][rem] = h;
            g_wpl[dir][rem] = __float2bfloat16(w - __bfloat162float(h));
        } else if (i < n3) {
            int q = i - n2;
            int d = q / E_, k = q - d * E_;
            float w = Wo[(size_t)k * D_ + d];
            __nv_bfloat16 h = __float2bfloat16(w);
            g_woh[q] = h;
            g_wol[q] = __float2bfloat16(w - __bfloat162float(h));
        }
    }
}

// ---------------- K1: HMMA dual GEMM, 128x128 tiles over packed 768 cols ----------------
__global__ __launch_bounds__(256) void gemm1_mma(const float* __restrict__ bxv,
                                                 const float* __restrict__ bzv) {
    extern __shared__ char dynsm[];
    __nv_bfloat16* sAh = (__nv_bfloat16*)dynsm;      // [2][128*SW]
    __nv_bfloat16* sAl = sAh + 2*128*SW;
    __nv_bfloat16* sBh = sAl + 2*128*SW;             // [2][128*SW]
    __nv_bfloat16* sBl = sBh + 2*128*SW;

    int tid  = threadIdx.x;
    int wid  = tid >> 5;
    int lane = tid & 31;
    int grp  = lane >> 2;
    int qd   = lane & 3;
    int row0 = blockIdx.x * 128;
    int c0   = blockIdx.y * 128;          // packed col base (0..767)
    int isZ  = (c0 >= E_);
    int wm = (wid & 3) * 32;
    int wn = (wid >> 2) * 32;
    uint32_t aAh = smem_u32(sAh), aAl = smem_u32(sAl);
    uint32_t aBh = smem_u32(sBh), aBl = smem_u32(sBl);

    float acc[2][2][4][4];
    #pragma unroll
    for (int mi = 0; mi < 2; mi++)
        #pragma unroll
        for (int nh = 0; nh < 2; nh++)
            #pragma unroll
            for (int ni = 0; ni < 4; ni++)
                #pragma unroll
                for (int q = 0; q < 4; q++) acc[mi][nh][ni][q] = 0.f;

    auto stage = [&](int p, int kt) {
        #pragma unroll
        for (int i = 0; i < 2; i++) {
            int q = tid + i * 256;
            int r = q >> 2, kc = (q & 3) * 8;
            const size_t ga = (size_t)(row0 + r) * D_ + kt + kc;
            cp16(&sAh[p*128*SW + r*SW + kc], g_th + ga);
            cp16(&sAl[p*128*SW + r*SW + kc], g_tl + ga);
            const size_t gb = (size_t)(c0 + r) * D_ + kt + kc;
            cp16(&sBh[p*128*SW + r*SW + kc], g_wht + gb);
            cp16(&sBl[p*128*SW + r*SW + kc], g_wlt + gb);
        }
    };

    stage(0, 0); CP_COMMIT();
    for (int it = 0; it < 6; it++) {
        int p = it & 1;
        if (it < 5) { stage(p ^ 1, (it + 1) * 32); CP_COMMIT(); CP_WAIT1(); }
        else CP_WAIT0();
        __syncthreads();
        uint32_t bAh = aAh + p*128*SW*2, bAl = aAl + p*128*SW*2;
        uint32_t bBh = aBh + p*128*SW*2, bBl = aBl + p*128*SW*2;
        #pragma unroll
        for (int ks = 0; ks < 2; ks++) {
            int k0 = ks * 16;
            uint32_t ah[2][4], al[2][4];
            #pragma unroll
            for (int mi = 0; mi < 2; mi++) {
                lda_frag(ah[mi], bAh, wm + mi*16, k0, lane);
                lda_frag(al[mi], bAl, wm + mi*16, k0, lane);
            }
            #pragma unroll
            for (int nh = 0; nh < 2; nh++) {
                uint32_t bh[8], bl[8];
                #pragma unroll
                for (int pp = 0; pp < 2; pp++) {
                    ldb_frag(&bh[pp*4], bBh, nh*64 + wn + pp*16, k0, lane);
                    ldb_frag(&bl[pp*4], bBl, nh*64 + wn + pp*16, k0, lane);
                }
                #pragma unroll
                for (int mi = 0; mi < 2; mi++)
                    #pragma unroll
                    for (int ni = 0; ni < 4; ni++) {
                        mma16816(acc[mi][nh][ni], ah[mi], &bh[ni*2]);
                        mma16816(acc[mi][nh][ni], ah[mi], &bl[ni*2]);
                        mma16816(acc[mi][nh][ni], al[mi], &bh[ni*2]);
                    }
            }
        }
        __syncthreads();
    }

    #pragma unroll
    for (int mi = 0; mi < 2; mi++) {
        #pragma unroll
        for (int nh = 0; nh < 2; nh++) {
            #pragma unroll
            for (int ni = 0; ni < 4; ni++) {
                int cpk = c0 + nh*64 + wn + ni * 8 + qd * 2;
                int r0 = row0 + wm + mi * 16 + grp;
                #pragma unroll
                for (int h = 0; h < 2; h++) {
                    int row = r0 + h * 8;
                    float v0 = acc[mi][nh][ni][h*2 + 0];
                    float v1 = acc[mi][nh][ni][h*2 + 1];
                    if (!isZ) {
                        float2 o;
                        o.x = v0 + bxv[cpk];
                        o.y = v1 + bxv[cpk + 1];
                        *(float2*)&g_x[(size_t)row * E_ + cpk] = o;
                    } else {
                        int c = cpk - E_;
                        float zc, sl;
                        float2 o;
                        zc = v0 + bzv[c];     sl = zc / (1.f + __expf(-zc)); o.x = 1.f / (1.f + __expf(-sl));
                        zc = v1 + bzv[c + 1]; sl = zc / (1.f + __expf(-zc)); o.y = 1.f / (1.f + __expf(-sl));
                        *(float2*)&g_gate[(size_t)row * E_ + c] = o;
                    }
                }
            }
        }
    }
}

// ---------------- K2a: depthwise conv — register weights, rolling window ----------------
__global__ __launch_bounds__(384) void conv_kernel(
        const float* __restrict__ cwf, const float* __restrict__ cbf,
        const float* __restrict__ cwb, const float* __restrict__ cbb) {
    __shared__ float swf[3][E_], swb[3][E_], sbf[E_], sbb[E_];
    int tid = threadIdx.x;

    for (int i = tid; i < 3*E_; i += 384) {
        int e = i / 3, t = i - e*3;
        swf[t][e] = cwf[i];
        swb[t][e] = cwb[i];
    }
    if (tid < E_) { sbf[tid] = cbf[tid]; sbb[tid] = cbb[tid]; }
    __syncthreads();

    int strip = tid / 96;
    int eg    = tid - strip * 96;
    int e     = eg * 4;
    int rowbase = blockIdx.x * 64 + strip * 16;
    int b  = rowbase >> 10;
    int j0 = rowbase & (J_ - 1);

    float wf[3][4], wb[3][4], bfv[4], bbv[4];
    #pragma unroll
    for (int t = 0; t < 3; t++) {
        *(float4*)wf[t] = *(const float4*)&swf[t][e];
        *(float4*)wb[t] = *(const float4*)&swb[t][e];
    }
    *(float4*)bfv = *(const float4*)&sbf[e];
    *(float4*)bbv = *(const float4*)&sbb[e];

    const float* xp = g_x + (size_t)rowbase * E_ + e;
    float x0[4], x1[4], x2[4];
    if (j0 > 0) *(float4*)x0 = *(const float4*)(xp - E_);
    else { x0[0] = x0[1] = x0[2] = x0[3] = 0.f; }
    *(float4*)x1 = *(const float4*)xp;

    #pragma unroll
    for (int r = 0; r < 16; r++) {
        int j = j0 + r;
        if (j < J_ - 1) *(float4*)x2 = *(const float4*)(xp + E_);
        else { x2[0] = x2[1] = x2[2] = x2[3] = 0.f; }

        __nv_bfloat16 fh[4], fl[4], bh[4], bl[4];
        #pragma unroll
        for (int q = 0; q < 4; q++) {
            float vf = wf[0][q]*x0[q] + wf[1][q]*x1[q] + wf[2][q]*x2[q] + bfv[q];
            float vb = wb[0][q]*x2[q] + wb[1][q]*x1[q] + wb[2][q]*x0[q] + bbv[q];
            fh[q] = __float2bfloat16(vf); fl[q] = __float2bfloat16(vf - __bfloat162float(fh[q]));
            bh[q] = __float2bfloat16(vb); bl[q] = __float2bfloat16(vb - __bfloat162float(bh[q]));
        }
        size_t of = (size_t)(b * J_ + j) * E_ + e;
        size_t ob = (size_t)(b * J_ + (J_ - 1 - j)) * E_ + e;
        *(uint2*)&g_xch[0][of] = *(uint2*)fh;
        *(uint2*)&g_xcl[0][of] = *(uint2*)fl;
        *(uint2*)&g_xch[1][ob] = *(uint2*)bh;
        *(uint2*)&g_xcl[1][ob] = *(uint2*)bl;

        #pragma unroll
        for (int q = 0; q < 4; q++) { x0[q] = x1[q]; x1[q] = x2[q]; }
        xp += E_;
    }
}

// ---------------- K2b: proj MMA + ZOH epilogue (cp.async double-buffer) ----------------
#define EPS 65
__global__ __launch_bounds__(256) void projmma_kernel(
        const float* __restrict__ bBf, const float* __restrict__ bCf,
        const float* __restrict__ bDf, const float* __restrict__ bBb,
        const float* __restrict__ bCb, const float* __restrict__ bDb,
        const float* __restrict__ A_log, const float* __restrict__ bi) {
    extern __shared__ char dynsm[];
    __nv_bfloat16* sAh = (__nv_bfloat16*)dynsm;
    __nv_bfloat16* sAl = sAh + 2*128*SW;
    __nv_bfloat16* sBh = sAl + 2*128*SW;
    __nv_bfloat16* sBl = sBh + 2*64*SW;
    float* ep = (float*)dynsm;                 // epilogue overlay (33280 B)
    __shared__ float sbias[4][N_];
    __shared__ float sAn[N_], sInv[N_];

    int tid  = threadIdx.x;
    int wid  = tid >> 5;
    int lane = tid & 31;
    int row0 = blockIdx.x * 128;
    int dir  = blockIdx.y;
    int b    = row0 >> 10;
    int s0   = row0 & (J_ - 1);
    int wm = (wid & 3) * 32;
    int wn = (wid >> 2) * 32;
    int grp  = lane >> 2;
    int qd   = lane & 3;
    uint32_t aAh = smem_u32(sAh), aAl = smem_u32(sAl);
    uint32_t aBh = smem_u32(sBh), aBl = smem_u32(sBl);

    if (tid < N_) {
        int n = tid;
        sbias[0][n] = dir ? bBb[n] : bBf[n];
        sbias[1][n] = dir ? bCb[n] : bCf[n];
        sbias[2][n] = dir ? bDb[n] : bDf[n];
        sbias[3][n] = bi[n];
        float al = A_log[n];
        float An = -log1pf(expf(al));
        sAn[n] = An;
        sInv[n] = 1.f / (An + 1e-6f);
    }

    const __nv_bfloat16* Ah = g_xch[dir];
    const __nv_bfloat16* Al = g_xcl[dir];
    const __nv_bfloat16* Bh = g_wph[dir];
    const __nv_bfloat16* Bl = g_wpl[dir];

    float acc[2][4][4];
    #pragma unroll
    for (int mi = 0; mi < 2; mi++)
        #pragma unroll
        for (int ni = 0; ni < 4; ni++)
            #pragma unroll
            for (int q = 0; q < 4; q++) acc[mi][ni][q] = 0.f;

    auto stage = [&](int p, int kt) {
        #pragma unroll
        for (int i = 0; i < 2; i++) {
            int q = tid + i * 256;
            int r = q >> 2, kc = (q & 3) * 8;
            const size_t go = (size_t)(row0 + r) * E_ + kt + kc;
            cp16(&sAh[p*128*SW + r*SW + kc], Ah + go);
            cp16(&sAl[p*128*SW + r*SW + kc], Al + go);
        }
        int r = tid >> 2, kc = (tid & 3) * 8;
        const size_t go = (size_t)r * E_ + kt + kc;
        cp16(&sBh[p*64*SW + r*SW + kc], Bh + go);
        cp16(&sBl[p*64*SW + r*SW + kc], Bl + go);
    };

    stage(0, 0); CP_COMMIT();
    for (int it = 0; it < 12; it++) {
        int p = it & 1;
        if (it < 11) { stage(p ^ 1, (it + 1) * 32); CP_COMMIT(); CP_WAIT1(); }
        else CP_WAIT0();
        __syncthreads();
        uint32_t bAhp = aAh + p*128*SW*2, bAlp = aAl + p*128*SW*2;
        uint32_t bBhp = aBh + p*64*SW*2,  bBlp = aBl + p*64*SW*2;
        #pragma unroll
        for (int ks = 0; ks < 2; ks++) {
            int k0 = ks * 16;
            uint32_t ah[2][4], al[2][4], bh[8], bl[8];
            #pragma unroll
            for (int mi = 0; mi < 2; mi++) {
                lda_frag(ah[mi], bAhp, wm + mi*16, k0, lane);
                lda_frag(al[mi], bAlp, wm + mi*16, k0, lane);
            }
            #pragma unroll
            for (int pp = 0; pp < 2; pp++) {
                ldb_frag(&bh[pp*4], bBhp, wn + pp*16, k0, lane);
                ldb_frag(&bl[pp*4], bBlp, wn + pp*16, k0, lane);
            }
            #pragma unroll
            for (int mi = 0; mi < 2; mi++)
                #pragma unroll
                for (int ni = 0; ni < 4; ni++) {
                    mma16816(acc[mi][ni], ah[mi], &bh[ni*2]);
                    mma16816(acc[mi][ni], ah[mi], &bl[ni*2]);
                    mma16816(acc[mi][ni], al[mi], &bh[ni*2]);
                }
        }
        __syncthreads();
    }

    #pragma unroll
    for (int mi = 0; mi < 2; mi++)
        #pragma unroll
        for (int ni = 0; ni < 4; ni++) {
            int c = wn + ni * 8 + qd * 2;
            int r0 = wm + mi * 16 + grp;
            #pragma unroll
            for (int h = 0; h < 2; h++) {
                ep[(r0 + h*8)*EPS + c    ] = acc[mi][ni][h*2 + 0];
                ep[(r0 + h*8)*EPS + c + 1] = acc[mi][ni][h*2 + 1];
            }
        }
    __syncthreads();

    #pragma unroll
    for (int it = 0; it < 8; it++) {
        int idx = tid + it * 256;
        int s = idx & 127;
        int n = idx >> 7;
        float bt  = ep[s*EPS + n     ] + sbias[0][n];
        float ct  = ep[s*EPS + n + 16] + sbias[1][n];
        float dtr = ep[s*EPS + n + 32] + sbias[2][n];
        float u   = ep[s*EPS + n + 48] + sbias[3][n];
        float An  = sAn[n];
        float dt  = (dtr > 20.f) ? dtr : log1pf(__expf(dtr));
        float abar = __expf(dt * An);
        float bu = (abar - 1.f) * sInv[n] * bt * u;
        size_t base = (size_t)(b*N_ + n) * J_ + s0 + s;
        g_Abar[dir][base] = abar;
        g_Bu[dir][base]   = bu;
        g_Ct[dir][base]   = ct;
    }
}

// ---------------- K3: blocked segmented scan (8 elems/lane) ----------------
__global__ __launch_bounds__(512) void scan_kernel() {
    int b   = blockIdx.x;
    int dir = blockIdx.y;
    int w    = threadIdx.x >> 5;
    int lane = threadIdx.x & 31;
    size_t base = (size_t)(b*N_ + w) * J_;
    const float* Aa = g_Abar[dir] + base;
    const float* Bu = g_Bu[dir]   + base;
    const float* Ct = g_Ct[dir]   + base;
    float carry = 0.f;
    #pragma unroll
    for (int seg = 0; seg < 4; seg++) {
        int s = seg*256 + lane*8;
        float a[8], bu[8];
        *(float4*)&a[0]  = *(const float4*)(Aa + s);
        *(float4*)&a[4]  = *(const float4*)(Aa + s + 4);
        *(float4*)&bu[0] = *(const float4*)(Bu + s);
        *(float4*)&bu[4] = *(const float4*)(Bu + s + 4);
        #pragma unroll
        for (int i = 1; i < 8; i++) { bu[i] = fmaf(a[i], bu[i-1], bu[i]); a[i] *= a[i-1]; }
        float As = a[7], Bs = bu[7];
        #pragma unroll
        for (int off = 1; off < 32; off <<= 1) {
            float ap = __shfl_up_sync(0xffffffffu, As, off);
            float bp = __shfl_up_sync(0xffffffffu, Bs, off);
            if (lane >= off) { Bs = fmaf(As, bp, Bs); As *= ap; }
        }
        float Ae = __shfl_up_sync(0xffffffffu, As, 1);
        float Be = __shfl_up_sync(0xffffffffu, Bs, 1);
        float Hprev = (lane == 0) ? carry : fmaf(Ae, carry, Be);
        float ct[8];
        *(float4*)&ct[0] = *(const float4*)(Ct + s);
        *(float4*)&ct[4] = *(const float4*)(Ct + s + 4);
        float hlast = 0.f;
        #pragma unroll
        for (int i = 0; i < 8; i++) {
            float h = fmaf(a[i], Hprev, bu[i]);
            if (i == 7) hlast = h;
            int sg = s + i;
            int jorig = dir ? (J_ - 1 - sg) : sg;
            g_g[dir][(size_t)(b*J_ + jorig) * N_ + w] = h * ct[i];
        }
        carry = __shfl_sync(0xffffffffu, hlast, 31);
    }
}

// ---------------- K4a: y = (gsum@Wr + 2br) * gate -> bf16 hi/lo ----------------
__global__ __launch_bounds__(256) void y_kernel(const float* __restrict__ Wr,
                                                const float* __restrict__ br) {
    __shared__ float sWr[N_*E_];
    __shared__ float sbr[E_];
    __shared__ float gsm[8*N_];
    int tid = threadIdx.x;
    int row0 = blockIdx.x * 8;

    #pragma unroll
    for (int i = 0; i < 24; i++) sWr[tid + i*256] = Wr[tid + i*256];
    if (tid < 128) {
        sbr[tid]       = 2.f * br[tid];
        sbr[tid + 128] = 2.f * br[tid + 128];
        if (tid < 64)  sbr[tid + 256] = 2.f * br[tid + 256];
        else           sbr[(tid - 64) + 320] = 2.f * br[(tid - 64) + 320];
    }
    if (tid < 128) {
        int r = tid >> 4, n = tid & 15;
        size_t row = (size_t)(row0 + r);
        gsm[tid] = g_g[0][row*N_ + n] + g_g[1][row*N_ + n];
    }
    __syncthreads();

    #pragma unroll
    for (int i = 0; i < 12; i++) {
        int q = tid + i * 256;
        int r = q / E_, e = q - r * E_;
        const float* gv = &gsm[r*N_];
        float acc = sbr[e];
        #pragma unroll
        for (int nn = 0; nn < N_; nn++) acc += gv[nn] * sWr[nn*E_ + e];
        size_t row = (size_t)(row0 + r);
        float y = acc * g_gate[row*E_ + e];
        __nv_bfloat16 h = __float2bfloat16(y);
        g_xch[0][row*E_ + e] = h;
        g_xcl[0][row*E_ + e] = __float2bfloat16(y - __bfloat162float(h));
    }
}

// ---------------- K4b: out = tokens + y @ Wo + bo — full 192-col tile per block ----------------
__global__ __launch_bounds__(256) void outmma_kernel(const float* __restrict__ tokens,
                                                     const float* __restrict__ bo,
                                                     float* __restrict__ out) {
    extern __shared__ char dynsm[];
    __nv_bfloat16* sAh = (__nv_bfloat16*)dynsm;          // [2][128*SW]
    __nv_bfloat16* sAl = sAh + 2*128*SW;
    __nv_bfloat16* sBh = sAl + 2*128*SW;                 // [2][192*SW]
    __nv_bfloat16* sBl = sBh + 2*192*SW;

    int tid  = threadIdx.x;
    int wid  = tid >> 5;
    int lane = tid & 31;
    int grp  = lane >> 2;
    int qd   = lane & 3;
    int row0 = blockIdx.x * 128;
    int wm = (wid & 1) * 64;      // 2 row halves, 64 rows each -> mi 0..3
    int wn = (wid >> 1) * 48;     // 4 col quarters, 48 cols each -> ni 0..5
    uint32_t aAh = smem_u32(sAh), aAl = smem_u32(sAl);
    uint32_t aBh = smem_u32(sBh), aBl = smem_u32(sBl);

    float acc[4][6][4];
    #pragma unroll
    for (int mi = 0; mi < 4; mi++)
        #pragma unroll
        for (int ni = 0; ni < 6; ni++)
            #pragma unroll
            for (int q = 0; q < 4; q++) acc[mi][ni][q] = 0.f;

    auto stage = [&](int p, int kt) {
        #pragma unroll
        for (int i = 0; i < 2; i++) {
            int q = tid + i * 256;
            int r = q >> 2, kc = (q & 3) * 8;
            const size_t go = (size_t)(row0 + r) * E_ + kt + kc;
            cp16(&sAh[p*128*SW + r*SW + kc], g_xch[0] + go);
            cp16(&sAl[p*128*SW + r*SW + kc], g_xcl[0] + go);
        }
        #pragma unroll
        for (int i = 0; i < 3; i++) {
            int q = tid + i * 256;
            int r = q >> 2, kc = (q & 3) * 8;
            const size_t go = (size_t)r * E_ + kt + kc;
            cp16(&sBh[p*192*SW + r*SW + kc], g_woh + go);
            cp16(&sBl[p*192*SW + r*SW + kc], g_wol + go);
        }
    };

    stage(0, 0); CP_COMMIT();
    for (int it = 0; it < 12; it++) {
        int p = it & 1;
        if (it < 11) { stage(p ^ 1, (it + 1) * 32); CP_COMMIT(); CP_WAIT1(); }
        else CP_WAIT0();
        __syncthreads();
        uint32_t bAhp = aAh + p*128*SW*2, bAlp = aAl + p*128*SW*2;
        uint32_t bBhp = aBh + p*192*SW*2, bBlp = aBl + p*192*SW*2;
        #pragma unroll
        for (int ks = 0; ks < 2; ks++) {
            int k0 = ks * 16;
            uint32_t ah[4][4], al[4][4];
            #pragma unroll
            for (int mi = 0; mi < 4; mi++) {
                lda_frag(ah[mi], bAhp, wm + mi*16, k0, lane);
                lda_frag(al[mi], bAlp, wm + mi*16, k0, lane);
            }
            #pragma unroll
            for (int pp = 0; pp < 3; pp++) {
                uint32_t bh[4], bl[4];
                ldb_frag(bh, bBhp, wn + pp*16, k0, lane);
                ldb_frag(bl, bBlp, wn + pp*16, k0, lane);
                #pragma unroll
                for (int mi = 0; mi < 4; mi++)
                    #pragma unroll
                    for (int nn = 0; nn < 2; nn++) {
                        int ni = pp*2 + nn;
                        mma16816(acc[mi][ni], ah[mi], &bh[nn*2]);
                        mma16816(acc[mi][ni], ah[mi], &bl[nn*2]);
                        mma16816(acc[mi][ni], al[mi], &bh[nn*2]);
                    }
            }
        }
        __syncthreads();
    }

    #pragma unroll
    for (int mi = 0; mi < 4; mi++) {
        #pragma unroll
        for (int ni = 0; ni < 6; ni++) {
            int c = wn + ni * 8 + qd * 2;
            int r0 = row0 + wm + mi * 16 + grp;
            float2 bov = *(const float2*)&bo[c];
            #pragma unroll
            for (int h = 0; h < 2; h++) {
                int row = r0 + h * 8;
                float2 tk = *(const float2*)&tokens[(size_t)row * D_ + c];
                float2 o;
                o.x = tk.x + acc[mi][ni][h*2 + 0] + bov.x;
                o.y = tk.y + acc[mi][ni][h*2 + 1] + bov.y;
                *(float2*)&out[(size_t)row * D_ + c] = o;
            }
        }
    }
}

// ---------------- launch ----------------
#define DYN_SMEM_G1  81920
#define DYN_SMEM     61440
#define DYN_SMEM_OUT 102400

extern "C" void kernel_launch(void* const* d_in, const int* in_sizes, int n_in,
                              void* d_out, int out_size) {
    const float* tokens = (const float*)d_in[0];
    const float* norm_g = (const float*)d_in[1];
    const float* norm_b = (const float*)d_in[2];
    const float* Wx  = (const float*)d_in[3];
    const float* bx  = (const float*)d_in[4];
    const float* Wz  = (const float*)d_in[5];
    const float* bz  = (const float*)d_in[6];
    const float* cwf = (const float*)d_in[7];
    const float* cbf = (const float*)d_in[8];
    const float* cwb = (const float*)d_in[9];
    const float* cbb = (const float*)d_in[10];
    const float* WBf = (const float*)d_in[11];
    const float* bBf = (const float*)d_in[12];
    const float* WCf = (const float*)d_in[13];
    const float* bCf = (const float*)d_in[14];
    const float* WDf = (const float*)d_in[15];
    const float* bDf = (const float*)d_in[16];
    const float* WBb = (const float*)d_in[17];
    const float* bBb = (const float*)d_in[18];
    const float* WCb = (const float*)d_in[19];
    const float* bCb = (const float*)d_in[20];
    const float* WDb = (const float*)d_in[21];
    const float* bDb = (const float*)d_in[22];
    const float* A_log = (const float*)d_in[23];
    const float* Wi  = (const float*)d_in[24];
    const float* bi  = (const float*)d_in[25];
    const float* Wr  = (const float*)d_in[26];
    const float* br  = (const float*)d_in[27];
    const float* Wo  = (const float*)d_in[28];
    const float* bo  = (const float*)d_in[29];
    float* out = (float*)d_out;

    cudaFuncSetAttribute(gemm1_mma,      cudaFuncAttributeMaxDynamicSharedMemorySize, DYN_SMEM_G1);
    cudaFuncSetAttribute(projmma_kernel, cudaFuncAttributeMaxDynamicSharedMemorySize, DYN_SMEM);
    cudaFuncSetAttribute(outmma_kernel,  cudaFuncAttributeMaxDynamicSharedMemorySize, DYN_SMEM_OUT);

    prep_kernel<<<BJ_/8 + 1056, 256>>>(tokens, norm_g, norm_b, Wx, Wz,
                                       WBf, WCf, WDf, WBb, WCb, WDb, Wi, Wo);
    gemm1_mma<<<dim3(BJ_/128, 6), 256, DYN_SMEM_G1>>>(bx, bz);
    conv_kernel<<<BJ_/64, 384>>>(cwf, cbf, cwb, cbb);
    projmma_kernel<<<dim3(BJ_/128, 2), 256, DYN_SMEM>>>(bBf, bCf, bDf, bBb, bCb, bDb, A_log, bi);
    scan_kernel<<<dim3(B_, 2), 512>>>();
    y_kernel<<<BJ_/8, 256>>>(Wr, br);
    outmma_kernel<<<BJ_/128, 256, DYN_SMEM_OUT>>>(tokens, bo, out);
}